// round 3
// baseline (speedup 1.0000x reference)
#include <cuda_runtime.h>
#include <math.h>

#define DIM 128
#define NL 50000
#define NP 100000
#define N_E_LL 500000
#define N_E_PP 400000
#define N_E_LP 500000
#define N_E_PL 500000

// ------------------------- device scratch (no allocs allowed) -------------------------
__device__ float g_lego_x[(size_t)NL * DIM];
__device__ float g_point_x[(size_t)NP * DIM];
__device__ float g_lego_a[(size_t)NL * DIM];
__device__ float g_point_a[(size_t)NP * DIM];
__device__ float g_q[(size_t)NL * DIM];
__device__ float g_k[(size_t)NL * DIM];
__device__ float g_v[(size_t)NL * DIM];
__device__ float g_hs[(size_t)NP * DIM];
__device__ float g_as[NP];
__device__ float g_ad[NP];
__device__ float g_score[N_E_LL];
__device__ float g_segm[NP];
__device__ float g_segd[NP];
__device__ float g_C[(size_t)NP * 512];
__device__ float g_B[(size_t)NP * 512];
__device__ float g_eagg[(size_t)NP * DIM];
__device__ float g_w1d[128 * 512];
__device__ float g_wa[256];

// ------------------------- small helpers -------------------------
__device__ __forceinline__ void atomicMaxF(float* addr, float val) {
    // sign-split trick: int-max for >=0, uint-min for <0.  Works with -inf init.
    if (val >= 0.0f) atomicMax((int*)addr, __float_as_int(val));
    else             atomicMin((unsigned int*)addr, (unsigned int)__float_as_int(val));
}

__global__ void fill_kernel(float* __restrict__ p, float v, int n) {
    int i = blockIdx.x * blockDim.x + threadIdx.x;
    if (i < n) p[i] = v;
}

// W1diff = W1[0:128,:] - W1[128:256,:]   (128x512)
__global__ void w1diff_kernel(const float* __restrict__ W1, float* __restrict__ out) {
    int i = blockIdx.x * blockDim.x + threadIdx.x;
    if (i < 128 * 512) out[i] = W1[i] - W1[i + 128 * 512];
}

// wa[0:128] = W @ a_s ; wa[128:256] = W @ a_d     (launch <<<1,256>>>)
__global__ void wa_kernel(const float* __restrict__ W, const float* __restrict__ a_s,
                          const float* __restrict__ a_d, float* __restrict__ wa) {
    int r = threadIdx.x;
    const float* av = (r < 128) ? a_s : a_d;
    int rr = r & 127;
    float s = 0.0f;
    for (int c = 0; c < 128; c++) s = fmaf(W[rr * 128 + c], av[c], s);
    wa[r] = s;
}

// out[i] = dot(X[i,:], w)   (warp per node)
__global__ void gemv_dot_kernel(const float* __restrict__ X, const float* __restrict__ w,
                                float* __restrict__ out, int N) {
    int i = (blockIdx.x * blockDim.x + threadIdx.x) >> 5;
    if (i >= N) return;
    int lane = threadIdx.x & 31;
    float4 xa = ((const float4*)(X + (size_t)i * DIM))[lane];
    float4 wv = ((const float4*)w)[lane];
    float p = xa.x * wv.x + xa.y * wv.y + xa.z * wv.z + xa.w * wv.w;
    #pragma unroll
    for (int o = 16; o; o >>= 1) p += __shfl_down_sync(0xffffffffu, p, o);
    if (lane == 0) out[i] = p;
}

// ------------------------- GEMM: C[MxN] = X[MxK] @ W[KxN](ldw) + b1 + b2 -------------------------
// BM=BN=128, BK=16, 256 threads, 8x8 per-thread register tile.
__global__ __launch_bounds__(256)
void gemm_bias_kernel(const float* __restrict__ X, const float* __restrict__ W,
                      const float* __restrict__ b1, const float* __restrict__ b2,
                      float* __restrict__ C, int M, int N, int K, int ldw) {
    __shared__ float As[16][132];
    __shared__ float Bs[16][128];
    const int t = threadIdx.x;
    const int tx = t & 15, ty = t >> 4;
    const int bm = blockIdx.y * 128, bn = blockIdx.x * 128;

    float acc[8][8];
    #pragma unroll
    for (int i = 0; i < 8; i++)
        #pragma unroll
        for (int j = 0; j < 8; j++) acc[i][j] = 0.0f;

    for (int k0 = 0; k0 < K; k0 += 16) {
        #pragma unroll
        for (int l = 0; l < 2; l++) {
            int f = t + l * 256;                 // 512 float4 of A (128 rows x 16 k)
            int row = f >> 2, kq = (f & 3) * 4;
            int gr = bm + row;
            float4 a = (gr < M) ? *(const float4*)(X + (size_t)gr * K + k0 + kq)
                                : make_float4(0.f, 0.f, 0.f, 0.f);
            As[kq + 0][row] = a.x; As[kq + 1][row] = a.y;
            As[kq + 2][row] = a.z; As[kq + 3][row] = a.w;
            int r2 = f >> 5, cq = (f & 31) * 4;  // 512 float4 of B (16 rows x 128 cols)
            *(float4*)&Bs[r2][cq] = *(const float4*)(W + (size_t)(k0 + r2) * ldw + bn + cq);
        }
        __syncthreads();
        #pragma unroll
        for (int k = 0; k < 16; k++) {
            float ar[8], br[8];
            #pragma unroll
            for (int i = 0; i < 8; i++) ar[i] = As[k][ty + 16 * i];
            #pragma unroll
            for (int j = 0; j < 8; j++) br[j] = Bs[k][tx + 16 * j];
            #pragma unroll
            for (int i = 0; i < 8; i++)
                #pragma unroll
                for (int j = 0; j < 8; j++) acc[i][j] = fmaf(ar[i], br[j], acc[i][j]);
        }
        __syncthreads();
    }
    #pragma unroll
    for (int i = 0; i < 8; i++) {
        int gr = bm + ty + 16 * i;
        if (gr >= M) continue;
        #pragma unroll
        for (int j = 0; j < 8; j++) {
            int gc = bn + tx + 16 * j;
            float vv = acc[i][j];
            if (b1) vv += b1[gc];
            if (b2) vv += b2[gc];
            C[(size_t)gr * N + gc] = vv;
        }
    }
}

// ------------------------- Transformer conv edge kernels -------------------------
__global__ void trans_score_kernel(const float* __restrict__ q, const float* __restrict__ k,
                                   const int* __restrict__ src, const int* __restrict__ dst,
                                   int E, float* __restrict__ score, float* __restrict__ segm) {
    int e = (blockIdx.x * blockDim.x + threadIdx.x) >> 5;
    if (e >= E) return;
    int lane = threadIdx.x & 31;
    int s = src[e], d = dst[e];
    float4 qa = ((const float4*)(q + (size_t)d * DIM))[lane];
    float4 ka = ((const float4*)(k + (size_t)s * DIM))[lane];
    float p = qa.x * ka.x + qa.y * ka.y + qa.z * ka.z + qa.w * ka.w;
    #pragma unroll
    for (int o = 16; o; o >>= 1) p += __shfl_down_sync(0xffffffffu, p, o);
    if (lane == 0) {
        p *= 0.08838834764831845f;   // 1/sqrt(128)
        score[e] = p;
        atomicMaxF(&segm[d], p);
    }
}

__global__ void gat_score_kernel(const float* __restrict__ as_, const float* __restrict__ ad_,
                                 const int* __restrict__ src, const int* __restrict__ dst,
                                 int E, float* __restrict__ score, float* __restrict__ segm) {
    int e = blockIdx.x * blockDim.x + threadIdx.x;
    if (e >= E) return;
    float s = as_[src[e]] + ad_[dst[e]];
    s = (s > 0.0f) ? s : 0.2f * s;          // leaky_relu 0.2
    score[e] = s;
    atomicMaxF(&segm[dst[e]], s);
}

__global__ void seg_exp_kernel(float* __restrict__ score, const int* __restrict__ dst,
                               const float* __restrict__ segm, float* __restrict__ segd, int E) {
    int e = blockIdx.x * blockDim.x + threadIdx.x;
    if (e >= E) return;
    int d = dst[e];
    float w = expf(score[e] - segm[d]);
    score[e] = w;
    atomicAdd(&segd[d], w);
}

// out[dst] += (score[e]/(segd[dst]+eps)) * v[src]     (warp per edge)
__global__ void seg_agg_kernel(const float* __restrict__ score, const float* __restrict__ segd,
                               const float* __restrict__ v, const int* __restrict__ src,
                               const int* __restrict__ dst, int E, float* __restrict__ out) {
    int e = (blockIdx.x * blockDim.x + threadIdx.x) >> 5;
    if (e >= E) return;
    int lane = threadIdx.x & 31;
    int s = src[e], d = dst[e];
    float a = score[e] / (segd[d] + 1e-16f);
    float4 val = ((const float4*)(v + (size_t)s * DIM))[lane];
    float* op = out + (size_t)d * DIM + lane * 4;
    atomicAdd(op + 0, a * val.x);
    atomicAdd(op + 1, a * val.y);
    atomicAdd(op + 2, a * val.z);
    atomicAdd(op + 3, a * val.w);
}

// ------------------------- EdgeConv per-edge MLP (2nd GEMM) + segment max -------------------------
// m[e,:] = relu(Cn[dst]+Bn[src]) @ W2 + b2 ; agg[dst] = max(agg[dst], m)
// 64 edges per block, 256 threads, acc[4 edges][8 cols] per thread.
__global__ __launch_bounds__(256)
void edge_mlp_max_kernel(const float* __restrict__ Cn, const float* __restrict__ Bn,
                         const int* __restrict__ src, const int* __restrict__ dst, int E,
                         const float* __restrict__ W2, const float* __restrict__ b2,
                         float* __restrict__ agg) {
    __shared__ float W2s[32][128];
    __shared__ float Hs[64][36];
    __shared__ int sS[64], sD[64];
    const int t = threadIdx.x;
    const int e0 = blockIdx.x * 64;
    if (t < 64) {
        int e = e0 + t;
        sS[t] = (e < E) ? src[e] : 0;
        sD[t] = (e < E) ? dst[e] : 0;
    }
    __syncthreads();
    const int cg = t & 15, eg = t >> 4;
    float acc[4][8];
    #pragma unroll
    for (int i = 0; i < 4; i++)
        #pragma unroll
        for (int j = 0; j < 8; j++) acc[i][j] = 0.0f;

    for (int kc = 0; kc < 512; kc += 32) {
        #pragma unroll
        for (int l = 0; l < 4; l++) {            // W2 chunk: 32x128 = 1024 float4
            int f = t + l * 256;
            ((float4*)W2s)[f] = ((const float4*)(W2 + (size_t)kc * 128))[f];
        }
        #pragma unroll
        for (int l = 0; l < 2; l++) {            // H chunk: 64 edges x 32 k = 512 float4
            int f = t + l * 256;
            int el = f >> 3, kq = (f & 7) * 4;
            int dd = sD[el], ss = sS[el];
            float4 cv = *(const float4*)(Cn + (size_t)dd * 512 + kc + kq);
            float4 bv = *(const float4*)(Bn + (size_t)ss * 512 + kc + kq);
            float4 h;
            h.x = fmaxf(cv.x + bv.x, 0.0f);
            h.y = fmaxf(cv.y + bv.y, 0.0f);
            h.z = fmaxf(cv.z + bv.z, 0.0f);
            h.w = fmaxf(cv.w + bv.w, 0.0f);
            *(float4*)&Hs[el][kq] = h;
        }
        __syncthreads();
        #pragma unroll
        for (int k = 0; k < 32; k++) {
            float w[8];
            #pragma unroll
            for (int j = 0; j < 8; j++) w[j] = W2s[k][cg + 16 * j];
            #pragma unroll
            for (int i = 0; i < 4; i++) {
                float h = Hs[eg * 4 + i][k];
                #pragma unroll
                for (int j = 0; j < 8; j++) acc[i][j] = fmaf(h, w[j], acc[i][j]);
            }
        }
        __syncthreads();
    }
    #pragma unroll
    for (int i = 0; i < 4; i++) {
        int e = e0 + eg * 4 + i;
        if (e >= E) continue;
        int d = sD[eg * 4 + i];
        #pragma unroll
        for (int j = 0; j < 8; j++) {
            int c = cg + 16 * j;
            atomicMaxF(&agg[(size_t)d * DIM + c], acc[i][j] + b2[c]);
        }
    }
}

// out = (isfinite(agg) ? agg : 0) [+ gbias[col]]
__global__ void finalize_max_kernel(const float* __restrict__ agg, const float* __restrict__ gbias,
                                    float* __restrict__ out, int n) {
    int i = blockIdx.x * blockDim.x + threadIdx.x;
    if (i >= n) return;
    float v = agg[i];
    if (!isfinite(v)) v = 0.0f;
    if (gbias) v += gbias[i & (DIM - 1)];
    out[i] = v;
}

// ------------------------- host orchestration -------------------------
static inline int ceil_div(int a, int b) { return (a + b - 1) / b; }

extern "C" void kernel_launch(void* const* d_in, const int* in_sizes, int n_in,
                              void* d_out, int out_size) {
    const float* in_xl = (const float*)d_in[0];
    const float* in_xp = (const float*)d_in[1];
    const float* tWq = (const float*)d_in[2];
    const float* tbq = (const float*)d_in[3];
    const float* tWk = (const float*)d_in[4];
    const float* tbk = (const float*)d_in[5];
    const float* tWv = (const float*)d_in[6];
    const float* tbv = (const float*)d_in[7];
    const float* tWs = (const float*)d_in[8];
    const float* tbs = (const float*)d_in[9];
    const float* eW1 = (const float*)d_in[10];
    const float* eb1 = (const float*)d_in[11];
    const float* eW2 = (const float*)d_in[12];
    const float* eb2 = (const float*)d_in[13];
    const float* gW  = (const float*)d_in[14];
    const float* gAs = (const float*)d_in[15];
    const float* gAd = (const float*)d_in[16];
    const float* gb  = (const float*)d_in[17];
    const int* ll_src = (const int*)d_in[18];
    const int* ll_dst = (const int*)d_in[19];
    const int* pp_src = (const int*)d_in[20];
    const int* pp_dst = (const int*)d_in[21];
    const int* lp_src = (const int*)d_in[22];
    const int* lp_dst = (const int*)d_in[23];
    const int* pl_src = (const int*)d_in[24];
    const int* pl_dst = (const int*)d_in[25];

    float *lx, *px, *la, *pa, *q, *k, *v, *hs, *asb, *adb, *sc, *sm, *sd, *Cb, *Bb, *ea, *w1d, *wa;
    cudaGetSymbolAddress((void**)&lx, g_lego_x);
    cudaGetSymbolAddress((void**)&px, g_point_x);
    cudaGetSymbolAddress((void**)&la, g_lego_a);
    cudaGetSymbolAddress((void**)&pa, g_point_a);
    cudaGetSymbolAddress((void**)&q, g_q);
    cudaGetSymbolAddress((void**)&k, g_k);
    cudaGetSymbolAddress((void**)&v, g_v);
    cudaGetSymbolAddress((void**)&hs, g_hs);
    cudaGetSymbolAddress((void**)&asb, g_as);
    cudaGetSymbolAddress((void**)&adb, g_ad);
    cudaGetSymbolAddress((void**)&sc, g_score);
    cudaGetSymbolAddress((void**)&sm, g_segm);
    cudaGetSymbolAddress((void**)&sd, g_segd);
    cudaGetSymbolAddress((void**)&Cb, g_C);
    cudaGetSymbolAddress((void**)&Bb, g_B);
    cudaGetSymbolAddress((void**)&ea, g_eagg);
    cudaGetSymbolAddress((void**)&w1d, g_w1d);
    cudaGetSymbolAddress((void**)&wa, g_wa);

    auto gemm = [&](const float* X, const float* W, const float* b1, const float* b2,
                    float* Cc, int M, int N, int K, int ldw) {
        dim3 gr(N / 128, ceil_div(M, 128));
        gemm_bias_kernel<<<gr, 256>>>(X, W, b1, b2, Cc, M, N, K, ldw);
    };
    auto fill = [&](float* p, float val, int n) {
        fill_kernel<<<ceil_div(n, 256), 256>>>(p, val, n);
    };

    cudaMemcpyAsync(lx, in_xl, sizeof(float) * (size_t)NL * DIM, cudaMemcpyDeviceToDevice, 0);
    cudaMemcpyAsync(px, in_xp, sizeof(float) * (size_t)NP * DIM, cudaMemcpyDeviceToDevice, 0);

    for (int layer = 0; layer < 2; layer++) {
        const int iA = 2 * layer, iB = 2 * layer + 1;
        const int i_lp = 2 * layer, i_pl = 2 * layer + 1;

        // ======== conv A ========
        // --- TransConv (lego->lego over ll), weights iA; GAT-pl bias folded into skip ---
        gemm(lx, tWq + (size_t)iA * 16384, tbq + iA * 128, nullptr, q, NL, 128, 128, 128);
        gemm(lx, tWk + (size_t)iA * 16384, tbk + iA * 128, nullptr, k, NL, 128, 128, 128);
        gemm(lx, tWv + (size_t)iA * 16384, tbv + iA * 128, nullptr, v, NL, 128, 128, 128);
        gemm(lx, tWs + (size_t)iA * 16384, tbs + iA * 128, gb + i_pl * 128, la, NL, 128, 128, 128);
        fill(sm, -INFINITY, NL);
        trans_score_kernel<<<ceil_div(N_E_LL, 8), 256>>>(q, k, ll_src, ll_dst, N_E_LL, sc, sm);
        fill(sd, 0.0f, NL);
        seg_exp_kernel<<<ceil_div(N_E_LL, 256), 256>>>(sc, ll_dst, sm, sd, N_E_LL);
        seg_agg_kernel<<<ceil_div(N_E_LL, 8), 256>>>(sc, sd, v, ll_src, ll_dst, N_E_LL, la);

        // --- GAT (point -> lego over pl), weights i_pl ---
        gemm(px, gW + (size_t)i_pl * 16384, nullptr, nullptr, hs, NP, 128, 128, 128);
        wa_kernel<<<1, 256>>>(gW + (size_t)i_pl * 16384, gAs + i_pl * 128, gAd + i_pl * 128, wa);
        gemv_dot_kernel<<<ceil_div(NP, 8), 256>>>(px, wa, asb, NP);
        gemv_dot_kernel<<<ceil_div(NL, 8), 256>>>(lx, wa + 128, adb, NL);
        fill(sm, -INFINITY, NL);
        gat_score_kernel<<<ceil_div(N_E_PL, 256), 256>>>(asb, adb, pl_src, pl_dst, N_E_PL, sc, sm);
        fill(sd, 0.0f, NL);
        seg_exp_kernel<<<ceil_div(N_E_PL, 256), 256>>>(sc, pl_dst, sm, sd, N_E_PL);
        seg_agg_kernel<<<ceil_div(N_E_PL, 8), 256>>>(sc, sd, hs, pl_src, pl_dst, N_E_PL, la);

        // --- EdgeConv (point->point over pp), weights iA; GAT-lp bias folded in finalize ---
        w1diff_kernel<<<ceil_div(65536, 256), 256>>>(eW1 + (size_t)iA * 131072, w1d);
        gemm(px, w1d, eb1 + iA * 512, nullptr, Cb, NP, 512, 128, 512);
        gemm(px, eW1 + (size_t)iA * 131072 + 65536, nullptr, nullptr, Bb, NP, 512, 128, 512);
        fill(ea, -INFINITY, NP * DIM);
        edge_mlp_max_kernel<<<ceil_div(N_E_PP, 64), 256>>>(Cb, Bb, pp_src, pp_dst, N_E_PP,
                                                           eW2 + (size_t)iA * 65536, eb2 + iA * 128, ea);
        finalize_max_kernel<<<ceil_div(NP * DIM, 256), 256>>>(ea, gb + i_lp * 128, pa, NP * DIM);

        // --- GAT (lego -> point over lp), weights i_lp ---
        gemm(lx, gW + (size_t)i_lp * 16384, nullptr, nullptr, hs, NL, 128, 128, 128);
        wa_kernel<<<1, 256>>>(gW + (size_t)i_lp * 16384, gAs + i_lp * 128, gAd + i_lp * 128, wa);
        gemv_dot_kernel<<<ceil_div(NL, 8), 256>>>(lx, wa, asb, NL);
        gemv_dot_kernel<<<ceil_div(NP, 8), 256>>>(px, wa + 128, adb, NP);
        fill(sm, -INFINITY, NP);
        gat_score_kernel<<<ceil_div(N_E_LP, 256), 256>>>(asb, adb, lp_src, lp_dst, N_E_LP, sc, sm);
        fill(sd, 0.0f, NP);
        seg_exp_kernel<<<ceil_div(N_E_LP, 256), 256>>>(sc, lp_dst, sm, sd, N_E_LP);
        seg_agg_kernel<<<ceil_div(N_E_LP, 8), 256>>>(sc, sd, hs, lp_src, lp_dst, N_E_LP, pa);

        // ======== conv B ========
        // --- TransConv (lego_a -> x_lego), weights iB ---
        gemm(la, tWq + (size_t)iB * 16384, tbq + iB * 128, nullptr, q, NL, 128, 128, 128);
        gemm(la, tWk + (size_t)iB * 16384, tbk + iB * 128, nullptr, k, NL, 128, 128, 128);
        gemm(la, tWv + (size_t)iB * 16384, tbv + iB * 128, nullptr, v, NL, 128, 128, 128);
        gemm(la, tWs + (size_t)iB * 16384, tbs + iB * 128, nullptr, lx, NL, 128, 128, 128);
        fill(sm, -INFINITY, NL);
        trans_score_kernel<<<ceil_div(N_E_LL, 8), 256>>>(q, k, ll_src, ll_dst, N_E_LL, sc, sm);
        fill(sd, 0.0f, NL);
        seg_exp_kernel<<<ceil_div(N_E_LL, 256), 256>>>(sc, ll_dst, sm, sd, N_E_LL);
        seg_agg_kernel<<<ceil_div(N_E_LL, 8), 256>>>(sc, sd, v, ll_src, ll_dst, N_E_LL, lx);

        // --- EdgeConv (point_a -> x_point), weights iB ---
        w1diff_kernel<<<ceil_div(65536, 256), 256>>>(eW1 + (size_t)iB * 131072, w1d);
        gemm(pa, w1d, eb1 + iB * 512, nullptr, Cb, NP, 512, 128, 512);
        gemm(pa, eW1 + (size_t)iB * 131072 + 65536, nullptr, nullptr, Bb, NP, 512, 128, 512);
        fill(ea, -INFINITY, NP * DIM);
        edge_mlp_max_kernel<<<ceil_div(N_E_PP, 64), 256>>>(Cb, Bb, pp_src, pp_dst, N_E_PP,
                                                           eW2 + (size_t)iB * 65536, eb2 + iB * 128, ea);
        finalize_max_kernel<<<ceil_div(NP * DIM, 256), 256>>>(ea, nullptr, px, NP * DIM);
    }

    float* out = (float*)d_out;
    cudaMemcpyAsync(out, lx, sizeof(float) * (size_t)NL * DIM, cudaMemcpyDeviceToDevice, 0);
    cudaMemcpyAsync(out + (size_t)NL * DIM, px, sizeof(float) * (size_t)NP * DIM,
                    cudaMemcpyDeviceToDevice, 0);
}

// round 10
// speedup vs baseline: 1.4389x; 1.4389x over previous
#include <cuda_runtime.h>
#include <cuda_bf16.h>
#include <math.h>
#include <stdint.h>

#define DIM 128
#define NL 50000
#define NP 100000
#define N_E_LL 500000
#define N_E_PP 400000
#define N_E_LP 500000
#define N_E_PL 500000

// ------------------------- device scratch (no allocs allowed) -------------------------
__device__ float g_lego_x[(size_t)NL * DIM];
__device__ float g_point_x[(size_t)NP * DIM];
__device__ float g_lego_a[(size_t)NL * DIM];
__device__ float g_point_a[(size_t)NP * DIM];
__device__ float g_q[(size_t)NL * DIM];
__device__ float g_k[(size_t)NL * DIM];
__device__ float g_v[(size_t)NL * DIM];
__device__ float g_hs[(size_t)NP * DIM];
__device__ float g_as[NP];
__device__ float g_ad[NP];
__device__ float g_score[N_E_LL];
__device__ float g_segm[NP];
__device__ float g_segd[NP];
__device__ float g_C[(size_t)NP * 512];
__device__ float g_B[(size_t)NP * 512];
__device__ float g_eagg[(size_t)NP * DIM];
__device__ float g_w1d[128 * 512];
__device__ float g_wa[256];

// ------------------------- PTX helpers (arch-neutral: ldmatrix + mma.sync) -------------------------
__device__ __forceinline__ uint32_t smem_u32(const void* p) {
    uint32_t a;
    asm("{ .reg .u64 t; cvta.to.shared.u64 t, %1; cvt.u32.u64 %0, t; }" : "=r"(a) : "l"(p));
    return a;
}
__device__ __forceinline__ void ldsm_x4(uint32_t* r, uint32_t addr) {
    asm volatile("ldmatrix.sync.aligned.m8n8.x4.shared.b16 {%0,%1,%2,%3}, [%4];"
                 : "=r"(r[0]), "=r"(r[1]), "=r"(r[2]), "=r"(r[3]) : "r"(addr));
}
__device__ __forceinline__ void mma_bf16(float* c, const uint32_t* a, const uint32_t* b) {
    asm volatile(
        "mma.sync.aligned.m16n8k16.row.col.f32.bf16.bf16.f32 "
        "{%0,%1,%2,%3}, {%4,%5,%6,%7}, {%8,%9}, {%0,%1,%2,%3};"
        : "+f"(c[0]), "+f"(c[1]), "+f"(c[2]), "+f"(c[3])
        : "r"(a[0]), "r"(a[1]), "r"(a[2]), "r"(a[3]), "r"(b[0]), "r"(b[1]));
}

// split 8 fp32 into hi/lo bf16 16B groups (Markstein split)
__device__ __forceinline__ void split8(const float* f, uint4* hi, uint4* lo) {
    uint32_t hw[4], lw[4];
#pragma unroll
    for (int i = 0; i < 4; i++) {
        float x0 = f[2 * i], x1 = f[2 * i + 1];
        __nv_bfloat16 h0 = __float2bfloat16(x0), h1 = __float2bfloat16(x1);
        __nv_bfloat162 hp = __halves2bfloat162(h0, h1);
        hw[i] = *reinterpret_cast<uint32_t*>(&hp);
        __nv_bfloat16 l0 = __float2bfloat16(x0 - __bfloat162float(h0));
        __nv_bfloat16 l1 = __float2bfloat16(x1 - __bfloat162float(h1));
        __nv_bfloat162 lp = __halves2bfloat162(l0, l1);
        lw[i] = *reinterpret_cast<uint32_t*>(&lp);
    }
    *hi = make_uint4(hw[0], hw[1], hw[2], hw[3]);
    *lo = make_uint4(lw[0], lw[1], lw[2], lw[3]);
}

// ------------------------- small helpers -------------------------
__device__ __forceinline__ void atomicMaxF(float* addr, float val) {
    if (val >= 0.0f) atomicMax((int*)addr, __float_as_int(val));
    else             atomicMin((unsigned int*)addr, (unsigned int)__float_as_int(val));
}

__global__ void fill_kernel(float* __restrict__ p, float v, int n) {
    int i = blockIdx.x * blockDim.x + threadIdx.x;
    if (i < n) p[i] = v;
}

__global__ void w1diff_kernel(const float* __restrict__ W1, float* __restrict__ out) {
    int i = blockIdx.x * blockDim.x + threadIdx.x;
    if (i < 128 * 512) out[i] = W1[i] - W1[i + 128 * 512];
}

__global__ void wa_kernel(const float* __restrict__ W, const float* __restrict__ a_s,
                          const float* __restrict__ a_d, float* __restrict__ wa) {
    int r = threadIdx.x;
    const float* av = (r < 128) ? a_s : a_d;
    int rr = r & 127;
    float s = 0.0f;
    for (int c = 0; c < 128; c++) s = fmaf(W[rr * 128 + c], av[c], s);
    wa[r] = s;
}

__global__ void gemv_dot_kernel(const float* __restrict__ X, const float* __restrict__ w,
                                float* __restrict__ out, int N) {
    int i = (blockIdx.x * blockDim.x + threadIdx.x) >> 5;
    if (i >= N) return;
    int lane = threadIdx.x & 31;
    float4 xa = ((const float4*)(X + (size_t)i * DIM))[lane];
    float4 wv = ((const float4*)w)[lane];
    float p = xa.x * wv.x + xa.y * wv.y + xa.z * wv.z + xa.w * wv.w;
#pragma unroll
    for (int o = 16; o; o >>= 1) p += __shfl_down_sync(0xffffffffu, p, o);
    if (lane == 0) out[i] = p;
}

// ------------------------- mma.sync node GEMM: C[MxN] = X[Mx128] @ W[128xN] + b1 + b2 -------------------------
// CTA 128x128, K=128 resident, 256 threads / 8 warps, warp tile 32x64.
// SMEM tiles bf16 hi/lo, stride 136 bf16 (=272B = 17x16B -> ldmatrix conflict-free).
#define SA_G 272
#define OAH 0
#define OAL 34816
#define OBH 69632
#define OBL 104448
#define GEMM_SMEM 139264

__global__ __launch_bounds__(256, 1)
void gemm_tc(const float* __restrict__ X, const float* __restrict__ W,
             const float* __restrict__ b1, const float* __restrict__ b2,
             float* __restrict__ Cout, int M, int N, int ldw) {
    extern __shared__ __align__(16) char smem[];
    const uint32_t sbase = smem_u32(smem);
    const int tid = threadIdx.x, lane = tid & 31, wid = tid >> 5;
    const int bm = blockIdx.y * 128, bn = blockIdx.x * 128;

    // ---- A tile: X rows [bm, bm+128) x K=128, hi/lo split ----
#pragma unroll
    for (int it = 0; it < 8; it++) {
        int task = tid + it * 256;           // 2048 tasks: 128 m x 16 k8
        int m = task >> 4, k8 = task & 15;
        int gm = bm + m;
        float f[8];
        if (gm < M) {
            const float4* p = (const float4*)(X + (size_t)gm * 128 + k8 * 8);
            float4 a = p[0], b = p[1];
            f[0] = a.x; f[1] = a.y; f[2] = a.z; f[3] = a.w;
            f[4] = b.x; f[5] = b.y; f[6] = b.z; f[7] = b.w;
        } else {
#pragma unroll
            for (int i = 0; i < 8; i++) f[i] = 0.0f;
        }
        uint4 hi, lo; split8(f, &hi, &lo);
        uint32_t off = (uint32_t)m * SA_G + (uint32_t)k8 * 16;
        *(uint4*)(smem + OAH + off) = hi;
        *(uint4*)(smem + OAL + off) = lo;
    }
    // ---- B tile: W[0:128, bn:bn+128] -> Bs[n][k] (k-contiguous), hi/lo split ----
#pragma unroll
    for (int it = 0; it < 8; it++) {
        int task = tid + it * 256;           // 2048 tasks: 16 k8 x 128 n
        int k8 = task >> 7, n = task & 127;
        const float* p = W + (size_t)(k8 * 8) * ldw + bn + n;
        float f[8];
#pragma unroll
        for (int i = 0; i < 8; i++) f[i] = p[(size_t)i * ldw];
        uint4 hi, lo; split8(f, &hi, &lo);
        uint32_t off = (uint32_t)n * SA_G + (uint32_t)k8 * 16;
        *(uint4*)(smem + OBH + off) = hi;
        *(uint4*)(smem + OBL + off) = lo;
    }
    __syncthreads();

    const int wm = (wid & 3) * 32, wn = (wid >> 2) * 64;
    const int g = lane >> 3, lr = lane & 7;
    const uint32_t aoff = (uint32_t)((g & 1) * 8 + lr) * SA_G + (uint32_t)(g >> 1) * 16;
    const uint32_t boff = (uint32_t)((g >> 1) * 8 + lr) * SA_G + (uint32_t)(g & 1) * 16;

    float acc[2][8][4];
#pragma unroll
    for (int i = 0; i < 2; i++)
#pragma unroll
        for (int j = 0; j < 8; j++)
#pragma unroll
            for (int r = 0; r < 4; r++) acc[i][j][r] = 0.0f;

#pragma unroll
    for (int pass = 0; pass < 3; pass++) {
        uint32_t Ab = sbase + (pass == 2 ? OAL : OAH) + (uint32_t)wm * SA_G + aoff;
        uint32_t Bb = sbase + (pass == 1 ? OBL : OBH) + (uint32_t)wn * SA_G + boff;
#pragma unroll
        for (int s = 0; s < 8; s++) {
            uint32_t a[2][4], b[4][4];
#pragma unroll
            for (int i = 0; i < 2; i++) ldsm_x4(a[i], Ab + i * (16 * SA_G) + s * 32);
#pragma unroll
            for (int j = 0; j < 4; j++) ldsm_x4(b[j], Bb + j * (16 * SA_G) + s * 32);
#pragma unroll
            for (int i = 0; i < 2; i++)
#pragma unroll
                for (int j = 0; j < 8; j++)
                    mma_bf16(acc[i][j], a[i], &b[j >> 1][(j & 1) * 2]);
        }
    }

    // ---- epilogue: direct float2 stores with fused bias ----
    const int q = lane >> 2, idx = lane & 3;
#pragma unroll
    for (int i = 0; i < 2; i++) {
        int gr0 = bm + wm + i * 16 + q;
#pragma unroll
        for (int j = 0; j < 8; j++) {
            int gc = bn + wn + j * 8 + idx * 2;
            float bb0 = 0.0f, bb1 = 0.0f;
            if (b1) { bb0 += b1[gc]; bb1 += b1[gc + 1]; }
            if (b2) { bb0 += b2[gc]; bb1 += b2[gc + 1]; }
            if (gr0 < M)
                *(float2*)(Cout + (size_t)gr0 * N + gc) =
                    make_float2(acc[i][j][0] + bb0, acc[i][j][1] + bb1);
            int gr1 = gr0 + 8;
            if (gr1 < M)
                *(float2*)(Cout + (size_t)gr1 * N + gc) =
                    make_float2(acc[i][j][2] + bb0, acc[i][j][3] + bb1);
        }
    }
}

// ------------------------- mma.sync EdgeConv per-edge MLP + segment max -------------------------
// 128 edges/CTA; H[e,:] = relu(Cn[dst]+Bn[src]) (K=512 in 64-chunks); D = H @ W2 (128 cols);
// fp32 accumulators persist across chunks; epilogue atomicMax into agg[dst].
#define SE_G 144
#define OSS 0
#define OSD 512
#define OHH 1024
#define OHL 19456
#define OWH 37888
#define OWL 56320
#define EDGE_SMEM 74752

__global__ __launch_bounds__(256, 1)
void edge_tc(const float* __restrict__ Cn, const float* __restrict__ Bn,
             const int* __restrict__ src, const int* __restrict__ dst, int E,
             const float* __restrict__ W2, const float* __restrict__ b2,
             float* __restrict__ agg) {
    extern __shared__ __align__(16) char smem[];
    const uint32_t sbase = smem_u32(smem);
    const int tid = threadIdx.x, lane = tid & 31, wid = tid >> 5;
    const int e0 = blockIdx.x * 128;
    int* sS = (int*)(smem + OSS);
    int* sD = (int*)(smem + OSD);

    if (tid < 128) {
        int e = e0 + tid;
        sS[tid] = (e < E) ? src[e] : 0;
        sD[tid] = (e < E) ? dst[e] : 0;
    }
    __syncthreads();

    const int wm = (wid & 3) * 32, wn = (wid >> 2) * 64;
    const int g = lane >> 3, lr = lane & 7;
    const uint32_t aoff = (uint32_t)((g & 1) * 8 + lr) * SE_G + (uint32_t)(g >> 1) * 16;
    const uint32_t boff = (uint32_t)((g >> 1) * 8 + lr) * SE_G + (uint32_t)(g & 1) * 16;

    float acc[2][8][4];
#pragma unroll
    for (int i = 0; i < 2; i++)
#pragma unroll
        for (int j = 0; j < 8; j++)
#pragma unroll
            for (int r = 0; r < 4; r++) acc[i][j][r] = 0.0f;

    for (int kc = 0; kc < 8; kc++) {
        // W2 chunk: [kc*64 .. +64) x 128 cols -> Ws[n][k], hi/lo
#pragma unroll
        for (int it = 0; it < 4; it++) {
            int task = tid + it * 256;       // 1024 tasks: 8 k8 x 128 n
            int k8 = task >> 7, n = task & 127;
            const float* p = W2 + (size_t)(kc * 64 + k8 * 8) * 128 + n;
            float f[8];
#pragma unroll
            for (int i = 0; i < 8; i++) f[i] = p[(size_t)i * 128];
            uint4 hi, lo; split8(f, &hi, &lo);
            uint32_t off = (uint32_t)n * SE_G + (uint32_t)k8 * 16;
            *(uint4*)(smem + OWH + off) = hi;
            *(uint4*)(smem + OWL + off) = lo;
        }
        // H chunk: 128 edges x 64 k  (gather + relu + split)
#pragma unroll
        for (int it = 0; it < 4; it++) {
            int task = tid + it * 256;       // 1024 tasks: 128 e x 8 k8
            int e = task >> 3, k8 = task & 7;
            const float4* pc = (const float4*)(Cn + (size_t)sD[e] * 512 + kc * 64 + k8 * 8);
            const float4* pb = (const float4*)(Bn + (size_t)sS[e] * 512 + kc * 64 + k8 * 8);
            float4 c0v = pc[0], c1v = pc[1], b0v = pb[0], b1v = pb[1];
            float f[8];
            f[0] = fmaxf(c0v.x + b0v.x, 0.f); f[1] = fmaxf(c0v.y + b0v.y, 0.f);
            f[2] = fmaxf(c0v.z + b0v.z, 0.f); f[3] = fmaxf(c0v.w + b0v.w, 0.f);
            f[4] = fmaxf(c1v.x + b1v.x, 0.f); f[5] = fmaxf(c1v.y + b1v.y, 0.f);
            f[6] = fmaxf(c1v.z + b1v.z, 0.f); f[7] = fmaxf(c1v.w + b1v.w, 0.f);
            uint4 hi, lo; split8(f, &hi, &lo);
            uint32_t off = (uint32_t)e * SE_G + (uint32_t)k8 * 16;
            *(uint4*)(smem + OHH + off) = hi;
            *(uint4*)(smem + OHL + off) = lo;
        }
        __syncthreads();

#pragma unroll
        for (int pass = 0; pass < 3; pass++) {
            uint32_t Ab = sbase + (pass == 2 ? OHL : OHH) + (uint32_t)wm * SE_G + aoff;
            uint32_t Bb = sbase + (pass == 1 ? OWL : OWH) + (uint32_t)wn * SE_G + boff;
#pragma unroll
            for (int s = 0; s < 4; s++) {
                uint32_t a[2][4], b[4][4];
#pragma unroll
                for (int i = 0; i < 2; i++) ldsm_x4(a[i], Ab + i * (16 * SE_G) + s * 32);
#pragma unroll
                for (int j = 0; j < 4; j++) ldsm_x4(b[j], Bb + j * (16 * SE_G) + s * 32);
#pragma unroll
                for (int i = 0; i < 2; i++)
#pragma unroll
                    for (int j = 0; j < 8; j++)
                        mma_bf16(acc[i][j], a[i], &b[j >> 1][(j & 1) * 2]);
            }
        }
        __syncthreads();
    }

    // ---- epilogue: segment-max atomics ----
    const int q = lane >> 2, idx = lane & 3;
#pragma unroll
    for (int i = 0; i < 2; i++) {
#pragma unroll
        for (int half = 0; half < 2; half++) {
            int el = wm + i * 16 + half * 8 + q;
            if (e0 + el >= E) continue;
            float* ag = agg + (size_t)sD[el] * 128;
#pragma unroll
            for (int j = 0; j < 8; j++) {
                int c = wn + j * 8 + idx * 2;
                atomicMaxF(&ag[c],     acc[i][j][half * 2 + 0] + b2[c]);
                atomicMaxF(&ag[c + 1], acc[i][j][half * 2 + 1] + b2[c + 1]);
            }
        }
    }
}

// ------------------------- Transformer conv edge kernels -------------------------
__global__ void trans_score_kernel(const float* __restrict__ q, const float* __restrict__ k,
                                   const int* __restrict__ src, const int* __restrict__ dst,
                                   int E, float* __restrict__ score, float* __restrict__ segm) {
    int e = (blockIdx.x * blockDim.x + threadIdx.x) >> 5;
    if (e >= E) return;
    int lane = threadIdx.x & 31;
    int s = src[e], d = dst[e];
    float4 qa = ((const float4*)(q + (size_t)d * DIM))[lane];
    float4 ka = ((const float4*)(k + (size_t)s * DIM))[lane];
    float p = qa.x * ka.x + qa.y * ka.y + qa.z * ka.z + qa.w * ka.w;
#pragma unroll
    for (int o = 16; o; o >>= 1) p += __shfl_down_sync(0xffffffffu, p, o);
    if (lane == 0) {
        p *= 0.08838834764831845f;
        score[e] = p;
        atomicMaxF(&segm[d], p);
    }
}

__global__ void gat_score_kernel(const float* __restrict__ as_, const float* __restrict__ ad_,
                                 const int* __restrict__ src, const int* __restrict__ dst,
                                 int E, float* __restrict__ score, float* __restrict__ segm) {
    int e = blockIdx.x * blockDim.x + threadIdx.x;
    if (e >= E) return;
    float s = as_[src[e]] + ad_[dst[e]];
    s = (s > 0.0f) ? s : 0.2f * s;
    score[e] = s;
    atomicMaxF(&segm[dst[e]], s);
}

__global__ void seg_exp_kernel(float* __restrict__ score, const int* __restrict__ dst,
                               const float* __restrict__ segm, float* __restrict__ segd, int E) {
    int e = blockIdx.x * blockDim.x + threadIdx.x;
    if (e >= E) return;
    int d = dst[e];
    float w = expf(score[e] - segm[d]);
    score[e] = w;
    atomicAdd(&segd[d], w);
}

__global__ void seg_agg_kernel(const float* __restrict__ score, const float* __restrict__ segd,
                               const float* __restrict__ v, const int* __restrict__ src,
                               const int* __restrict__ dst, int E, float* __restrict__ out) {
    int e = (blockIdx.x * blockDim.x + threadIdx.x) >> 5;
    if (e >= E) return;
    int lane = threadIdx.x & 31;
    int s = src[e], d = dst[e];
    float a = score[e] / (segd[d] + 1e-16f);
    float4 val = ((const float4*)(v + (size_t)s * DIM))[lane];
    float* op = out + (size_t)d * DIM + lane * 4;
    atomicAdd(op + 0, a * val.x);
    atomicAdd(op + 1, a * val.y);
    atomicAdd(op + 2, a * val.z);
    atomicAdd(op + 3, a * val.w);
}

__global__ void finalize_max_kernel(const float* __restrict__ agg, const float* __restrict__ gbias,
                                    float* __restrict__ out, int n) {
    int i = blockIdx.x * blockDim.x + threadIdx.x;
    if (i >= n) return;
    float v = agg[i];
    if (!isfinite(v)) v = 0.0f;
    if (gbias) v += gbias[i & (DIM - 1)];
    out[i] = v;
}

// ------------------------- host orchestration -------------------------
static inline int ceil_div(int a, int b) { return (a + b - 1) / b; }

extern "C" void kernel_launch(void* const* d_in, const int* in_sizes, int n_in,
                              void* d_out, int out_size) {
    const float* in_xl = (const float*)d_in[0];
    const float* in_xp = (const float*)d_in[1];
    const float* tWq = (const float*)d_in[2];
    const float* tbq = (const float*)d_in[3];
    const float* tWk = (const float*)d_in[4];
    const float* tbk = (const float*)d_in[5];
    const float* tWv = (const float*)d_in[6];
    const float* tbv = (const float*)d_in[7];
    const float* tWs = (const float*)d_in[8];
    const float* tbs = (const float*)d_in[9];
    const float* eW1 = (const float*)d_in[10];
    const float* eb1 = (const float*)d_in[11];
    const float* eW2 = (const float*)d_in[12];
    const float* eb2 = (const float*)d_in[13];
    const float* gW  = (const float*)d_in[14];
    const float* gAs = (const float*)d_in[15];
    const float* gAd = (const float*)d_in[16];
    const float* gb  = (const float*)d_in[17];
    const int* ll_src = (const int*)d_in[18];
    const int* ll_dst = (const int*)d_in[19];
    const int* pp_src = (const int*)d_in[20];
    const int* pp_dst = (const int*)d_in[21];
    const int* lp_src = (const int*)d_in[22];
    const int* lp_dst = (const int*)d_in[23];
    const int* pl_src = (const int*)d_in[24];
    const int* pl_dst = (const int*)d_in[25];

    cudaFuncSetAttribute(gemm_tc, cudaFuncAttributeMaxDynamicSharedMemorySize, GEMM_SMEM);
    cudaFuncSetAttribute(edge_tc, cudaFuncAttributeMaxDynamicSharedMemorySize, EDGE_SMEM);

    float *lx, *px, *la, *pa, *q, *k, *v, *hs, *asb, *adb, *sc, *sm, *sd, *Cb, *Bb, *ea, *w1d, *wa;
    cudaGetSymbolAddress((void**)&lx, g_lego_x);
    cudaGetSymbolAddress((void**)&px, g_point_x);
    cudaGetSymbolAddress((void**)&la, g_lego_a);
    cudaGetSymbolAddress((void**)&pa, g_point_a);
    cudaGetSymbolAddress((void**)&q, g_q);
    cudaGetSymbolAddress((void**)&k, g_k);
    cudaGetSymbolAddress((void**)&v, g_v);
    cudaGetSymbolAddress((void**)&hs, g_hs);
    cudaGetSymbolAddress((void**)&asb, g_as);
    cudaGetSymbolAddress((void**)&adb, g_ad);
    cudaGetSymbolAddress((void**)&sc, g_score);
    cudaGetSymbolAddress((void**)&sm, g_segm);
    cudaGetSymbolAddress((void**)&sd, g_segd);
    cudaGetSymbolAddress((void**)&Cb, g_C);
    cudaGetSymbolAddress((void**)&Bb, g_B);
    cudaGetSymbolAddress((void**)&ea, g_eagg);
    cudaGetSymbolAddress((void**)&w1d, g_w1d);
    cudaGetSymbolAddress((void**)&wa, g_wa);

    auto gemm = [&](const float* X, const float* W, const float* b1, const float* b2,
                    float* Cc, int M, int N, int ldw) {
        dim3 gr(N / 128, ceil_div(M, 128));
        gemm_tc<<<gr, 256, GEMM_SMEM>>>(X, W, b1, b2, Cc, M, N, ldw);
    };
    auto fill = [&](float* p, float val, int n) {
        fill_kernel<<<ceil_div(n, 256), 256>>>(p, val, n);
    };

    cudaMemcpyAsync(lx, in_xl, sizeof(float) * (size_t)NL * DIM, cudaMemcpyDeviceToDevice, 0);
    cudaMemcpyAsync(px, in_xp, sizeof(float) * (size_t)NP * DIM, cudaMemcpyDeviceToDevice, 0);

    for (int layer = 0; layer < 2; layer++) {
        const int iA = 2 * layer, iB = 2 * layer + 1;
        const int i_lp = 2 * layer, i_pl = 2 * layer + 1;

        // ======== conv A ========
        // --- TransConv (lego->lego over ll), weights iA; GAT-pl bias folded into skip ---
        gemm(lx, tWq + (size_t)iA * 16384, tbq + iA * 128, nullptr, q, NL, 128, 128);
        gemm(lx, tWk + (size_t)iA * 16384, tbk + iA * 128, nullptr, k, NL, 128, 128);
        gemm(lx, tWv + (size_t)iA * 16384, tbv + iA * 128, nullptr, v, NL, 128, 128);
        gemm(lx, tWs + (size_t)iA * 16384, tbs + iA * 128, gb + i_pl * 128, la, NL, 128, 128);
        fill(sm, -INFINITY, NL);
        trans_score_kernel<<<ceil_div(N_E_LL, 8), 256>>>(q, k, ll_src, ll_dst, N_E_LL, sc, sm);
        fill(sd, 0.0f, NL);
        seg_exp_kernel<<<ceil_div(N_E_LL, 256), 256>>>(sc, ll_dst, sm, sd, N_E_LL);
        seg_agg_kernel<<<ceil_div(N_E_LL, 8), 256>>>(sc, sd, v, ll_src, ll_dst, N_E_LL, la);

        // --- GAT (point -> lego over pl), weights i_pl ---
        gemm(px, gW + (size_t)i_pl * 16384, nullptr, nullptr, hs, NP, 128, 128);
        wa_kernel<<<1, 256>>>(gW + (size_t)i_pl * 16384, gAs + i_pl * 128, gAd + i_pl * 128, wa);
        gemv_dot_kernel<<<ceil_div(NP, 8), 256>>>(px, wa, asb, NP);
        gemv_dot_kernel<<<ceil_div(NL, 8), 256>>>(lx, wa + 128, adb, NL);
        fill(sm, -INFINITY, NL);
        gat_score_kernel<<<ceil_div(N_E_PL, 256), 256>>>(asb, adb, pl_src, pl_dst, N_E_PL, sc, sm);
        fill(sd, 0.0f, NL);
        seg_exp_kernel<<<ceil_div(N_E_PL, 256), 256>>>(sc, pl_dst, sm, sd, N_E_PL);
        seg_agg_kernel<<<ceil_div(N_E_PL, 8), 256>>>(sc, sd, hs, pl_src, pl_dst, N_E_PL, la);

        // --- EdgeConv (point->point over pp), weights iA; GAT-lp bias folded in finalize ---
        w1diff_kernel<<<ceil_div(65536, 256), 256>>>(eW1 + (size_t)iA * 131072, w1d);
        gemm(px, w1d, eb1 + iA * 512, nullptr, Cb, NP, 512, 512);
        gemm(px, eW1 + (size_t)iA * 131072 + 65536, nullptr, nullptr, Bb, NP, 512, 512);
        fill(ea, -INFINITY, NP * DIM);
        edge_tc<<<ceil_div(N_E_PP, 128), 256, EDGE_SMEM>>>(Cb, Bb, pp_src, pp_dst, N_E_PP,
                                                           eW2 + (size_t)iA * 65536, eb2 + iA * 128, ea);
        finalize_max_kernel<<<ceil_div(NP * DIM, 256), 256>>>(ea, gb + i_lp * 128, pa, NP * DIM);

        // --- GAT (lego -> point over lp), weights i_lp ---
        gemm(lx, gW + (size_t)i_lp * 16384, nullptr, nullptr, hs, NL, 128, 128);
        wa_kernel<<<1, 256>>>(gW + (size_t)i_lp * 16384, gAs + i_lp * 128, gAd + i_lp * 128, wa);
        gemv_dot_kernel<<<ceil_div(NL, 8), 256>>>(lx, wa, asb, NL);
        gemv_dot_kernel<<<ceil_div(NP, 8), 256>>>(px, wa + 128, adb, NP);
        fill(sm, -INFINITY, NP);
        gat_score_kernel<<<ceil_div(N_E_LP, 256), 256>>>(asb, adb, lp_src, lp_dst, N_E_LP, sc, sm);
        fill(sd, 0.0f, NP);
        seg_exp_kernel<<<ceil_div(N_E_LP, 256), 256>>>(sc, lp_dst, sm, sd, N_E_LP);
        seg_agg_kernel<<<ceil_div(N_E_LP, 8), 256>>>(sc, sd, hs, lp_src, lp_dst, N_E_LP, pa);

        // ======== conv B ========
        // --- TransConv (lego_a -> x_lego), weights iB ---
        gemm(la, tWq + (size_t)iB * 16384, tbq + iB * 128, nullptr, q, NL, 128, 128);
        gemm(la, tWk + (size_t)iB * 16384, tbk + iB * 128, nullptr, k, NL, 128, 128);
        gemm(la, tWv + (size_t)iB * 16384, tbv + iB * 128, nullptr, v, NL, 128, 128);
        gemm(la, tWs + (size_t)iB * 16384, tbs + iB * 128, nullptr, lx, NL, 128, 128);
        fill(sm, -INFINITY, NL);
        trans_score_kernel<<<ceil_div(N_E_LL, 8), 256>>>(q, k, ll_src, ll_dst, N_E_LL, sc, sm);
        fill(sd, 0.0f, NL);
        seg_exp_kernel<<<ceil_div(N_E_LL, 256), 256>>>(sc, ll_dst, sm, sd, N_E_LL);
        seg_agg_kernel<<<ceil_div(N_E_LL, 8), 256>>>(sc, sd, v, ll_src, ll_dst, N_E_LL, lx);

        // --- EdgeConv (point_a -> x_point), weights iB ---
        w1diff_kernel<<<ceil_div(65536, 256), 256>>>(eW1 + (size_t)iB * 131072, w1d);
        gemm(pa, w1d, eb1 + iB * 512, nullptr, Cb, NP, 512, 512);
        gemm(pa, eW1 + (size_t)iB * 131072 + 65536, nullptr, nullptr, Bb, NP, 512, 512);
        fill(ea, -INFINITY, NP * DIM);
        edge_tc<<<ceil_div(N_E_PP, 128), 256, EDGE_SMEM>>>(Cb, Bb, pp_src, pp_dst, N_E_PP,
                                                           eW2 + (size_t)iB * 65536, eb2 + iB * 128, ea);
        finalize_max_kernel<<<ceil_div(NP * DIM, 256), 256>>>(ea, nullptr, px, NP * DIM);
    }

    float* out = (float*)d_out;
    cudaMemcpyAsync(out, lx, sizeof(float) * (size_t)NL * DIM, cudaMemcpyDeviceToDevice, 0);
    cudaMemcpyAsync(out + (size_t)NL * DIM, px, sizeof(float) * (size_t)NP * DIM,
                    cudaMemcpyDeviceToDevice, 0);
}

// round 13
// speedup vs baseline: 1.6541x; 1.1496x over previous
#include <cuda_runtime.h>
#include <cuda_bf16.h>
#include <math.h>
#include <stdint.h>

#define DIM 128
#define NL 50000
#define NP 100000
#define N_E_LL 500000
#define N_E_PP 400000
#define N_E_LP 500000
#define N_E_PL 500000

// ------------------------- device scratch (no allocs allowed) -------------------------
__device__ float g_lego_x[(size_t)NL * DIM];
__device__ float g_point_x[(size_t)NP * DIM];
__device__ float g_lego_a[(size_t)NL * DIM];
__device__ float g_point_a[(size_t)NP * DIM];
__device__ float g_q[(size_t)NL * DIM];
__device__ float g_k[(size_t)NL * DIM];
__device__ float g_v[(size_t)NL * DIM];
__device__ float g_hs[(size_t)NP * DIM];
__device__ float g_as[NP];
__device__ float g_ad[NP];
__device__ float g_score[N_E_LL];
__device__ float g_C[(size_t)NP * 512];
__device__ float g_B[(size_t)NP * 512];
__device__ float g_eagg[(size_t)NP * DIM];
__device__ float g_wa[256];

// sorted-edge infrastructure
__device__ int g_rp_ll[NL + 1];
__device__ int g_rp_pl[NL + 1];
__device__ int g_rp_pp[NP + 1];
__device__ int g_rp_lp[NP + 1];
__device__ int g_cur[NP + 1];
__device__ int g_part[256];
__device__ int g_ss_ll[N_E_LL], g_sd_ll[N_E_LL];
__device__ int g_ss_pp[N_E_PP], g_sd_pp[N_E_PP];
__device__ int g_ss_lp[N_E_LP], g_sd_lp[N_E_LP];
__device__ int g_ss_pl[N_E_PL], g_sd_pl[N_E_PL];

// pre-split transposed weights (bf16 hi/lo), layout [n][k] k-contiguous
#define OW_Q 0
#define OW_K 16384
#define OW_V 32768
#define OW_S 49152
#define OW_G 65536
#define OW_1D 81920
#define OW_1B 147456
#define OW_2 212992
#define W_INST 278528
__device__ __nv_bfloat16 g_wh[(size_t)4 * W_INST];
__device__ __nv_bfloat16 g_wl[(size_t)4 * W_INST];

// ------------------------- PTX helpers (arch-neutral: ldmatrix + mma.sync) -------------------------
__device__ __forceinline__ uint32_t smem_u32(const void* p) {
    uint32_t a;
    asm("{ .reg .u64 t; cvta.to.shared.u64 t, %1; cvt.u32.u64 %0, t; }" : "=r"(a) : "l"(p));
    return a;
}
__device__ __forceinline__ void ldsm_x4(uint32_t* r, uint32_t addr) {
    asm volatile("ldmatrix.sync.aligned.m8n8.x4.shared.b16 {%0,%1,%2,%3}, [%4];"
                 : "=r"(r[0]), "=r"(r[1]), "=r"(r[2]), "=r"(r[3]) : "r"(addr));
}
__device__ __forceinline__ void mma_bf16(float* c, const uint32_t* a, const uint32_t* b) {
    asm volatile(
        "mma.sync.aligned.m16n8k16.row.col.f32.bf16.bf16.f32 "
        "{%0,%1,%2,%3}, {%4,%5,%6,%7}, {%8,%9}, {%0,%1,%2,%3};"
        : "+f"(c[0]), "+f"(c[1]), "+f"(c[2]), "+f"(c[3])
        : "r"(a[0]), "r"(a[1]), "r"(a[2]), "r"(a[3]), "r"(b[0]), "r"(b[1]));
}

// split 8 fp32 into hi/lo bf16 16B groups (Markstein split)
__device__ __forceinline__ void split8(const float* f, uint4* hi, uint4* lo) {
    uint32_t hw[4], lw[4];
#pragma unroll
    for (int i = 0; i < 4; i++) {
        float x0 = f[2 * i], x1 = f[2 * i + 1];
        __nv_bfloat16 h0 = __float2bfloat16(x0), h1 = __float2bfloat16(x1);
        __nv_bfloat162 hp = __halves2bfloat162(h0, h1);
        hw[i] = *reinterpret_cast<uint32_t*>(&hp);
        __nv_bfloat16 l0 = __float2bfloat16(x0 - __bfloat162float(h0));
        __nv_bfloat16 l1 = __float2bfloat16(x1 - __bfloat162float(h1));
        __nv_bfloat162 lp = __halves2bfloat162(l0, l1);
        lw[i] = *reinterpret_cast<uint32_t*>(&lp);
    }
    *hi = make_uint4(hw[0], hw[1], hw[2], hw[3]);
    *lo = make_uint4(lw[0], lw[1], lw[2], lw[3]);
}

// ------------------------- small helpers -------------------------
__device__ __forceinline__ void atomicMaxF(float* addr, float val) {
    if (val >= 0.0f) atomicMax((int*)addr, __float_as_int(val));
    else             atomicMin((unsigned int*)addr, (unsigned int)__float_as_int(val));
}

__global__ void fill_kernel(float* __restrict__ p, float v, int n) {
    int i = blockIdx.x * blockDim.x + threadIdx.x;
    if (i < n) p[i] = v;
}
__global__ void fill_int_kernel(int* __restrict__ p, int v, int n) {
    int i = blockIdx.x * blockDim.x + threadIdx.x;
    if (i < n) p[i] = v;
}
__global__ void copy_int_kernel(int* __restrict__ d, const int* __restrict__ s, int n) {
    int i = blockIdx.x * blockDim.x + threadIdx.x;
    if (i < n) d[i] = s[i];
}

// ------------------------- counting sort by dst -------------------------
__global__ void hist_kernel(const int* __restrict__ dst, int E, int* __restrict__ cnt) {
    int e = blockIdx.x * blockDim.x + threadIdx.x;
    if (e < E) atomicAdd(&cnt[dst[e]], 1);
}
__global__ void scan_block_kernel(int* __restrict__ data, int* __restrict__ part, int n) {
    __shared__ int sh[1024];
    int i = blockIdx.x * 1024 + threadIdx.x;
    int x = (i < n) ? data[i] : 0;
    sh[threadIdx.x] = x;
    __syncthreads();
    for (int o = 1; o < 1024; o <<= 1) {
        int t = (threadIdx.x >= o) ? sh[threadIdx.x - o] : 0;
        __syncthreads();
        sh[threadIdx.x] += t;
        __syncthreads();
    }
    if (i < n) data[i] = sh[threadIdx.x] - x;      // exclusive
    if (threadIdx.x == 1023) part[blockIdx.x] = sh[1023];
}
__global__ void scan_part_kernel(int* __restrict__ part, int nb) {
    __shared__ int sh[1024];
    int x = (threadIdx.x < nb) ? part[threadIdx.x] : 0;
    sh[threadIdx.x] = x;
    __syncthreads();
    for (int o = 1; o < 1024; o <<= 1) {
        int t = (threadIdx.x >= o) ? sh[threadIdx.x - o] : 0;
        __syncthreads();
        sh[threadIdx.x] += t;
        __syncthreads();
    }
    if (threadIdx.x < nb) part[threadIdx.x] = sh[threadIdx.x] - x;   // exclusive
}
__global__ void scan_add_kernel(int* __restrict__ data, const int* __restrict__ part, int n) {
    int i = blockIdx.x * 1024 + threadIdx.x;
    if (i < n) data[i] += part[blockIdx.x];
}
__global__ void scatter_kernel(const int* __restrict__ src, const int* __restrict__ dst, int E,
                               int* __restrict__ cur, int* __restrict__ ssrc, int* __restrict__ sdst) {
    int e = blockIdx.x * blockDim.x + threadIdx.x;
    if (e >= E) return;
    int d = dst[e];
    int pos = atomicAdd(&cur[d], 1);
    ssrc[pos] = src[e];
    sdst[pos] = d;
}

// ------------------------- weight pre-split (transposed, bf16 hi/lo) -------------------------
__global__ void split_wT_kernel(const float* __restrict__ W, int K, int N,
                                __nv_bfloat16* __restrict__ hiT, __nv_bfloat16* __restrict__ loT) {
    int idx = blockIdx.x * 256 + threadIdx.x;
    if (idx >= K * N) return;
    int k = idx / N, n = idx - k * N;
    float x = W[idx];
    __nv_bfloat16 h = __float2bfloat16(x);
    __nv_bfloat16 l = __float2bfloat16(x - __bfloat162float(h));
    hiT[(size_t)n * K + k] = h;
    loT[(size_t)n * K + k] = l;
}
// W1diff = W1[0:128,:] - W1[128:256,:]  (K=128, N=512), split+transpose
__global__ void split_w1d_kernel(const float* __restrict__ W1,
                                 __nv_bfloat16* __restrict__ hiT, __nv_bfloat16* __restrict__ loT) {
    int idx = blockIdx.x * 256 + threadIdx.x;
    if (idx >= 128 * 512) return;
    int k = idx >> 9, n = idx & 511;
    float x = W1[idx] - W1[idx + 128 * 512];
    __nv_bfloat16 h = __float2bfloat16(x);
    __nv_bfloat16 l = __float2bfloat16(x - __bfloat162float(h));
    hiT[(size_t)n * 128 + k] = h;
    loT[(size_t)n * 128 + k] = l;
}

__global__ void wa_kernel(const float* __restrict__ W, const float* __restrict__ a_s,
                          const float* __restrict__ a_d, float* __restrict__ wa) {
    int r = threadIdx.x;
    const float* av = (r < 128) ? a_s : a_d;
    int rr = r & 127;
    float s = 0.0f;
    for (int c = 0; c < 128; c++) s = fmaf(W[rr * 128 + c], av[c], s);
    wa[r] = s;
}

__global__ void gemv_dot_kernel(const float* __restrict__ X, const float* __restrict__ w,
                                float* __restrict__ out, int N) {
    int i = (blockIdx.x * blockDim.x + threadIdx.x) >> 5;
    if (i >= N) return;
    int lane = threadIdx.x & 31;
    float4 xa = ((const float4*)(X + (size_t)i * DIM))[lane];
    float4 wv = ((const float4*)w)[lane];
    float p = xa.x * wv.x + xa.y * wv.y + xa.z * wv.z + xa.w * wv.w;
#pragma unroll
    for (int o = 16; o; o >>= 1) p += __shfl_down_sync(0xffffffffu, p, o);
    if (lane == 0) out[i] = p;
}

// ------------------------- mma.sync node GEMM (pre-split weights) -------------------------
// C[MxN] = X[Mx128] @ W[128xN] + b1 + b2 ; WhiT/WloT layout [N][128] k-contiguous bf16.
#define SA_G 272
#define OAH 0
#define OAL 34816
#define OBH 69632
#define OBL 104448
#define GEMM_SMEM 139264

__global__ __launch_bounds__(256, 1)
void gemm_tc(const float* __restrict__ X,
             const __nv_bfloat16* __restrict__ WhiT, const __nv_bfloat16* __restrict__ WloT,
             const float* __restrict__ b1, const float* __restrict__ b2,
             float* __restrict__ Cout, int M, int N) {
    extern __shared__ __align__(16) char smem[];
    const uint32_t sbase = smem_u32(smem);
    const int tid = threadIdx.x, lane = tid & 31, wid = tid >> 5;
    const int bm = blockIdx.y * 128, bn = blockIdx.x * 128;

    // ---- A tile: X rows [bm, bm+128) x K=128, hi/lo split on the fly ----
#pragma unroll
    for (int it = 0; it < 8; it++) {
        int task = tid + it * 256;           // 2048 tasks: 128 m x 16 k8
        int m = task >> 4, k8 = task & 15;
        int gm = bm + m;
        float f[8];
        if (gm < M) {
            const float4* p = (const float4*)(X + (size_t)gm * 128 + k8 * 8);
            float4 a = p[0], b = p[1];
            f[0] = a.x; f[1] = a.y; f[2] = a.z; f[3] = a.w;
            f[4] = b.x; f[5] = b.y; f[6] = b.z; f[7] = b.w;
        } else {
#pragma unroll
            for (int i = 0; i < 8; i++) f[i] = 0.0f;
        }
        uint4 hi, lo; split8(f, &hi, &lo);
        uint32_t off = (uint32_t)m * SA_G + (uint32_t)k8 * 16;
        *(uint4*)(smem + OAH + off) = hi;
        *(uint4*)(smem + OAL + off) = lo;
    }
    // ---- B tile: straight copies from pre-split transposed weights ----
#pragma unroll
    for (int it = 0; it < 8; it++) {
        int task = tid + it * 256;           // 2048 tasks: 128 n x 16 chunks
        int n = task >> 4, c = task & 15;
        uint32_t off = (uint32_t)n * SA_G + (uint32_t)c * 16;
        *(uint4*)(smem + OBH + off) = *(const uint4*)(WhiT + (size_t)(bn + n) * 128 + c * 8);
        *(uint4*)(smem + OBL + off) = *(const uint4*)(WloT + (size_t)(bn + n) * 128 + c * 8);
    }
    __syncthreads();

    const int wm = (wid & 3) * 32, wn = (wid >> 2) * 64;
    const int g = lane >> 3, lr = lane & 7;
    const uint32_t aoff = (uint32_t)((g & 1) * 8 + lr) * SA_G + (uint32_t)(g >> 1) * 16;
    const uint32_t boff = (uint32_t)((g >> 1) * 8 + lr) * SA_G + (uint32_t)(g & 1) * 16;

    float acc[2][8][4];
#pragma unroll
    for (int i = 0; i < 2; i++)
#pragma unroll
        for (int j = 0; j < 8; j++)
#pragma unroll
            for (int r = 0; r < 4; r++) acc[i][j][r] = 0.0f;

#pragma unroll
    for (int pass = 0; pass < 3; pass++) {
        uint32_t Ab = sbase + (pass == 2 ? OAL : OAH) + (uint32_t)wm * SA_G + aoff;
        uint32_t Bb = sbase + (pass == 1 ? OBL : OBH) + (uint32_t)wn * SA_G + boff;
#pragma unroll
        for (int s = 0; s < 8; s++) {
            uint32_t a[2][4], b[4][4];
#pragma unroll
            for (int i = 0; i < 2; i++) ldsm_x4(a[i], Ab + i * (16 * SA_G) + s * 32);
#pragma unroll
            for (int j = 0; j < 4; j++) ldsm_x4(b[j], Bb + j * (16 * SA_G) + s * 32);
#pragma unroll
            for (int i = 0; i < 2; i++)
#pragma unroll
                for (int j = 0; j < 8; j++)
                    mma_bf16(acc[i][j], a[i], &b[j >> 1][(j & 1) * 2]);
        }
    }

    // ---- epilogue ----
    const int q = lane >> 2, idx = lane & 3;
#pragma unroll
    for (int i = 0; i < 2; i++) {
        int gr0 = bm + wm + i * 16 + q;
#pragma unroll
        for (int j = 0; j < 8; j++) {
            int gc = bn + wn + j * 8 + idx * 2;
            float bb0 = 0.0f, bb1 = 0.0f;
            if (b1) { bb0 += b1[gc]; bb1 += b1[gc + 1]; }
            if (b2) { bb0 += b2[gc]; bb1 += b2[gc + 1]; }
            if (gr0 < M)
                *(float2*)(Cout + (size_t)gr0 * N + gc) =
                    make_float2(acc[i][j][0] + bb0, acc[i][j][1] + bb1);
            int gr1 = gr0 + 8;
            if (gr1 < M)
                *(float2*)(Cout + (size_t)gr1 * N + gc) =
                    make_float2(acc[i][j][2] + bb0, acc[i][j][3] + bb1);
        }
    }
}

// ------------------------- mma.sync EdgeConv per-edge MLP + segment max -------------------------
// dst-sorted edges: Cn[dst] gather is L2-local; W2 pre-split.
#define SE_G 144
#define OSS 0
#define OSD 512
#define OHH 1024
#define OHL 19456
#define OWH 37888
#define OWL 56320
#define EDGE_SMEM 74752

__global__ __launch_bounds__(256, 1)
void edge_tc(const float* __restrict__ Cn, const float* __restrict__ Bn,
             const int* __restrict__ src, const int* __restrict__ dst, int E,
             const __nv_bfloat16* __restrict__ W2hiT, const __nv_bfloat16* __restrict__ W2loT,
             const float* __restrict__ b2, float* __restrict__ agg) {
    extern __shared__ __align__(16) char smem[];
    const uint32_t sbase = smem_u32(smem);
    const int tid = threadIdx.x, lane = tid & 31, wid = tid >> 5;
    const int e0 = blockIdx.x * 128;
    int* sS = (int*)(smem + OSS);
    int* sD = (int*)(smem + OSD);

    if (tid < 128) {
        int e = e0 + tid;
        sS[tid] = (e < E) ? src[e] : 0;
        sD[tid] = (e < E) ? dst[e] : 0;
    }
    __syncthreads();

    const int wm = (wid & 3) * 32, wn = (wid >> 2) * 64;
    const int g = lane >> 3, lr = lane & 7;
    const uint32_t aoff = (uint32_t)((g & 1) * 8 + lr) * SE_G + (uint32_t)(g >> 1) * 16;
    const uint32_t boff = (uint32_t)((g >> 1) * 8 + lr) * SE_G + (uint32_t)(g & 1) * 16;

    float acc[2][8][4];
#pragma unroll
    for (int i = 0; i < 2; i++)
#pragma unroll
        for (int j = 0; j < 8; j++)
#pragma unroll
            for (int r = 0; r < 4; r++) acc[i][j][r] = 0.0f;

    for (int kc = 0; kc < 8; kc++) {
        // W2 chunk: straight copies from pre-split [n][k] bf16
#pragma unroll
        for (int it = 0; it < 4; it++) {
            int task = tid + it * 256;       // 1024 tasks: 128 n x 8 chunks
            int n = task >> 3, c = task & 7;
            uint32_t off = (uint32_t)n * SE_G + (uint32_t)c * 16;
            *(uint4*)(smem + OWH + off) = *(const uint4*)(W2hiT + (size_t)n * 512 + kc * 64 + c * 8);
            *(uint4*)(smem + OWL + off) = *(const uint4*)(W2loT + (size_t)n * 512 + kc * 64 + c * 8);
        }
        // H chunk: 128 edges x 64 k  (gather + relu + split)
#pragma unroll
        for (int it = 0; it < 4; it++) {
            int task = tid + it * 256;       // 1024 tasks: 128 e x 8 k8
            int e = task >> 3, k8 = task & 7;
            const float4* pc = (const float4*)(Cn + (size_t)sD[e] * 512 + kc * 64 + k8 * 8);
            const float4* pb = (const float4*)(Bn + (size_t)sS[e] * 512 + kc * 64 + k8 * 8);
            float4 c0v = pc[0], c1v = pc[1], b0v = pb[0], b1v = pb[1];
            float f[8];
            f[0] = fmaxf(c0v.x + b0v.x, 0.f); f[1] = fmaxf(c0v.y + b0v.y, 0.f);
            f[2] = fmaxf(c0v.z + b0v.z, 0.f); f[3] = fmaxf(c0v.w + b0v.w, 0.f);
            f[4] = fmaxf(c1v.x + b1v.x, 0.f); f[5] = fmaxf(c1v.y + b1v.y, 0.f);
            f[6] = fmaxf(c1v.z + b1v.z, 0.f); f[7] = fmaxf(c1v.w + b1v.w, 0.f);
            uint4 hi, lo; split8(f, &hi, &lo);
            uint32_t off = (uint32_t)e * SE_G + (uint32_t)k8 * 16;
            *(uint4*)(smem + OHH + off) = hi;
            *(uint4*)(smem + OHL + off) = lo;
        }
        __syncthreads();

#pragma unroll
        for (int pass = 0; pass < 3; pass++) {
            uint32_t Ab = sbase + (pass == 2 ? OHL : OHH) + (uint32_t)wm * SE_G + aoff;
            uint32_t Bb = sbase + (pass == 1 ? OWL : OWH) + (uint32_t)wn * SE_G + boff;
#pragma unroll
            for (int s = 0; s < 4; s++) {
                uint32_t a[2][4], b[4][4];
#pragma unroll
                for (int i = 0; i < 2; i++) ldsm_x4(a[i], Ab + i * (16 * SE_G) + s * 32);
#pragma unroll
                for (int j = 0; j < 4; j++) ldsm_x4(b[j], Bb + j * (16 * SE_G) + s * 32);
#pragma unroll
                for (int i = 0; i < 2; i++)
#pragma unroll
                    for (int j = 0; j < 8; j++)
                        mma_bf16(acc[i][j], a[i], &b[j >> 1][(j & 1) * 2]);
            }
        }
        __syncthreads();
    }

    // ---- epilogue: segment-max atomics (dst-sorted -> L2-local) ----
    const int q = lane >> 2, idx = lane & 3;
#pragma unroll
    for (int i = 0; i < 2; i++) {
#pragma unroll
        for (int half = 0; half < 2; half++) {
            int el = wm + i * 16 + half * 8 + q;
            if (e0 + el >= E) continue;
            float* ag = agg + (size_t)sD[el] * 128;
#pragma unroll
            for (int j = 0; j < 8; j++) {
                int c = wn + j * 8 + idx * 2;
                atomicMaxF(&ag[c],     acc[i][j][half * 2 + 0] + b2[c]);
                atomicMaxF(&ag[c + 1], acc[i][j][half * 2 + 1] + b2[c + 1]);
            }
        }
    }
}

// ------------------------- score kernels (sorted edges, no atomics) -------------------------
__global__ void trans_score_kernel(const float* __restrict__ q, const float* __restrict__ k,
                                   const int* __restrict__ ssrc, const int* __restrict__ sdst,
                                   int E, float* __restrict__ score) {
    int e = (blockIdx.x * blockDim.x + threadIdx.x) >> 5;
    if (e >= E) return;
    int lane = threadIdx.x & 31;
    int s = ssrc[e], d = sdst[e];
    float4 qa = ((const float4*)(q + (size_t)d * DIM))[lane];
    float4 ka = ((const float4*)(k + (size_t)s * DIM))[lane];
    float p = qa.x * ka.x + qa.y * ka.y + qa.z * ka.z + qa.w * ka.w;
#pragma unroll
    for (int o = 16; o; o >>= 1) p += __shfl_down_sync(0xffffffffu, p, o);
    if (lane == 0) score[e] = p * 0.08838834764831845f;
}

__global__ void gat_score_kernel(const float* __restrict__ as_, const float* __restrict__ ad_,
                                 const int* __restrict__ ssrc, const int* __restrict__ sdst,
                                 int E, float* __restrict__ score) {
    int e = blockIdx.x * blockDim.x + threadIdx.x;
    if (e >= E) return;
    float s = as_[ssrc[e]] + ad_[sdst[e]];
    score[e] = (s > 0.0f) ? s : 0.2f * s;
}

// ------------------------- CSR softmax-aggregation: warp per dst node -------------------------
// out[node,:] += softmax_over_segment(score) @ v[src]
__global__ void attn_agg_kernel(const int* __restrict__ rp, const int* __restrict__ ssrc,
                                const float* __restrict__ score, const float* __restrict__ v,
                                float* __restrict__ out, int N) {
    int node = (blockIdx.x * blockDim.x + threadIdx.x) >> 5;
    if (node >= N) return;
    int lane = threadIdx.x & 31;
    int beg = rp[node], end = rp[node + 1];
    if (beg == end) return;
    float m = -INFINITY;
    for (int i = beg + lane; i < end; i += 32) m = fmaxf(m, score[i]);
#pragma unroll
    for (int o = 16; o; o >>= 1) m = fmaxf(m, __shfl_xor_sync(0xffffffffu, m, o));
    float ax = 0.f, ay = 0.f, az = 0.f, aw = 0.f, asum = 0.f;
    for (int e = beg; e < end; e++) {
        float a = expf(score[e] - m);
        asum += a;
        float4 val = ((const float4*)(v + (size_t)ssrc[e] * DIM))[lane];
        ax = fmaf(a, val.x, ax); ay = fmaf(a, val.y, ay);
        az = fmaf(a, val.z, az); aw = fmaf(a, val.w, aw);
    }
    float inv = 1.0f / (asum + 1e-16f);
    float4* op = (float4*)(out + (size_t)node * DIM) + lane;
    float4 cur = *op;
    cur.x += ax * inv; cur.y += ay * inv; cur.z += az * inv; cur.w += aw * inv;
    *op = cur;
}

__global__ void finalize_max_kernel(const float* __restrict__ agg, const float* __restrict__ gbias,
                                    float* __restrict__ out, int n) {
    int i = blockIdx.x * blockDim.x + threadIdx.x;
    if (i >= n) return;
    float v = agg[i];
    if (!isfinite(v)) v = 0.0f;
    if (gbias) v += gbias[i & (DIM - 1)];
    out[i] = v;
}

// ------------------------- host orchestration -------------------------
static inline int ceil_div(int a, int b) { return (a + b - 1) / b; }

extern "C" void kernel_launch(void* const* d_in, const int* in_sizes, int n_in,
                              void* d_out, int out_size) {
    const float* in_xl = (const float*)d_in[0];
    const float* in_xp = (const float*)d_in[1];
    const float* tWq = (const float*)d_in[2];
    const float* tbq = (const float*)d_in[3];
    const float* tWk = (const float*)d_in[4];
    const float* tbk = (const float*)d_in[5];
    const float* tWv = (const float*)d_in[6];
    const float* tbv = (const float*)d_in[7];
    const float* tWs = (const float*)d_in[8];
    const float* tbs = (const float*)d_in[9];
    const float* eW1 = (const float*)d_in[10];
    const float* eb1 = (const float*)d_in[11];
    const float* eW2 = (const float*)d_in[12];
    const float* eb2 = (const float*)d_in[13];
    const float* gW  = (const float*)d_in[14];
    const float* gAs = (const float*)d_in[15];
    const float* gAd = (const float*)d_in[16];
    const float* gb  = (const float*)d_in[17];
    const int* ll_src = (const int*)d_in[18];
    const int* ll_dst = (const int*)d_in[19];
    const int* pp_src = (const int*)d_in[20];
    const int* pp_dst = (const int*)d_in[21];
    const int* lp_src = (const int*)d_in[22];
    const int* lp_dst = (const int*)d_in[23];
    const int* pl_src = (const int*)d_in[24];
    const int* pl_dst = (const int*)d_in[25];

    cudaFuncSetAttribute(gemm_tc, cudaFuncAttributeMaxDynamicSharedMemorySize, GEMM_SMEM);
    cudaFuncSetAttribute(edge_tc, cudaFuncAttributeMaxDynamicSharedMemorySize, EDGE_SMEM);

    float *lx, *px, *la, *pa, *q, *k, *v, *hs, *asb, *adb, *sc, *Cb, *Bb, *ea, *wa;
    cudaGetSymbolAddress((void**)&lx, g_lego_x);
    cudaGetSymbolAddress((void**)&px, g_point_x);
    cudaGetSymbolAddress((void**)&la, g_lego_a);
    cudaGetSymbolAddress((void**)&pa, g_point_a);
    cudaGetSymbolAddress((void**)&q, g_q);
    cudaGetSymbolAddress((void**)&k, g_k);
    cudaGetSymbolAddress((void**)&v, g_v);
    cudaGetSymbolAddress((void**)&hs, g_hs);
    cudaGetSymbolAddress((void**)&asb, g_as);
    cudaGetSymbolAddress((void**)&adb, g_ad);
    cudaGetSymbolAddress((void**)&sc, g_score);
    cudaGetSymbolAddress((void**)&Cb, g_C);
    cudaGetSymbolAddress((void**)&Bb, g_B);
    cudaGetSymbolAddress((void**)&ea, g_eagg);
    cudaGetSymbolAddress((void**)&wa, g_wa);

    int *rp_ll, *rp_pl, *rp_pp, *rp_lp, *cur, *part;
    int *ss_ll, *sd_ll, *ss_pp, *sd_pp, *ss_lp, *sd_lp, *ss_pl, *sd_pl;
    cudaGetSymbolAddress((void**)&rp_ll, g_rp_ll);
    cudaGetSymbolAddress((void**)&rp_pl, g_rp_pl);
    cudaGetSymbolAddress((void**)&rp_pp, g_rp_pp);
    cudaGetSymbolAddress((void**)&rp_lp, g_rp_lp);
    cudaGetSymbolAddress((void**)&cur, g_cur);
    cudaGetSymbolAddress((void**)&part, g_part);
    cudaGetSymbolAddress((void**)&ss_ll, g_ss_ll);
    cudaGetSymbolAddress((void**)&sd_ll, g_sd_ll);
    cudaGetSymbolAddress((void**)&ss_pp, g_ss_pp);
    cudaGetSymbolAddress((void**)&sd_pp, g_sd_pp);
    cudaGetSymbolAddress((void**)&ss_lp, g_ss_lp);
    cudaGetSymbolAddress((void**)&sd_lp, g_sd_lp);
    cudaGetSymbolAddress((void**)&ss_pl, g_ss_pl);
    cudaGetSymbolAddress((void**)&sd_pl, g_sd_pl);

    __nv_bfloat16 *wh, *wl;
    cudaGetSymbolAddress((void**)&wh, g_wh);
    cudaGetSymbolAddress((void**)&wl, g_wl);

    // ---- counting sort of each relation by dst ----
    auto sort_rel = [&](const int* src, const int* dst, int E, int Nn,
                        int* rp, int* ssrc, int* sdst) {
        int n1 = Nn + 1;
        fill_int_kernel<<<ceil_div(n1, 256), 256>>>(rp, 0, n1);
        hist_kernel<<<ceil_div(E, 256), 256>>>(dst, E, rp);
        int nb = ceil_div(n1, 1024);
        scan_block_kernel<<<nb, 1024>>>(rp, part, n1);
        scan_part_kernel<<<1, 1024>>>(part, nb);
        scan_add_kernel<<<nb, 1024>>>(rp, part, n1);
        copy_int_kernel<<<ceil_div(n1, 256), 256>>>(cur, rp, n1);
        scatter_kernel<<<ceil_div(E, 256), 256>>>(src, dst, E, cur, ssrc, sdst);
    };
    sort_rel(ll_src, ll_dst, N_E_LL, NL, rp_ll, ss_ll, sd_ll);
    sort_rel(pp_src, pp_dst, N_E_PP, NP, rp_pp, ss_pp, sd_pp);
    sort_rel(lp_src, lp_dst, N_E_LP, NP, rp_lp, ss_lp, sd_lp);
    sort_rel(pl_src, pl_dst, N_E_PL, NL, rp_pl, ss_pl, sd_pl);

    // ---- pre-split all weights ----
    for (int i = 0; i < 4; i++) {
        size_t o = (size_t)i * W_INST;
        split_wT_kernel<<<64, 256>>>(tWq + (size_t)i * 16384, 128, 128, wh + o + OW_Q, wl + o + OW_Q);
        split_wT_kernel<<<64, 256>>>(tWk + (size_t)i * 16384, 128, 128, wh + o + OW_K, wl + o + OW_K);
        split_wT_kernel<<<64, 256>>>(tWv + (size_t)i * 16384, 128, 128, wh + o + OW_V, wl + o + OW_V);
        split_wT_kernel<<<64, 256>>>(tWs + (size_t)i * 16384, 128, 128, wh + o + OW_S, wl + o + OW_S);
        split_wT_kernel<<<64, 256>>>(gW  + (size_t)i * 16384, 128, 128, wh + o + OW_G, wl + o + OW_G);
        split_w1d_kernel<<<256, 256>>>(eW1 + (size_t)i * 131072, wh + o + OW_1D, wl + o + OW_1D);
        split_wT_kernel<<<256, 256>>>(eW1 + (size_t)i * 131072 + 65536, 128, 512,
                                      wh + o + OW_1B, wl + o + OW_1B);
        split_wT_kernel<<<256, 256>>>(eW2 + (size_t)i * 65536, 512, 128,
                                      wh + o + OW_2, wl + o + OW_2);
    }

    auto gemm = [&](const float* X, size_t woff, const float* b1, const float* b2,
                    float* Cc, int M, int N) {
        dim3 gr(N / 128, ceil_div(M, 128));
        gemm_tc<<<gr, 256, GEMM_SMEM>>>(X, wh + woff, wl + woff, b1, b2, Cc, M, N);
    };

    cudaMemcpyAsync(lx, in_xl, sizeof(float) * (size_t)NL * DIM, cudaMemcpyDeviceToDevice, 0);
    cudaMemcpyAsync(px, in_xp, sizeof(float) * (size_t)NP * DIM, cudaMemcpyDeviceToDevice, 0);

    for (int layer = 0; layer < 2; layer++) {
        const int iA = 2 * layer, iB = 2 * layer + 1;
        const int i_lp = 2 * layer, i_pl = 2 * layer + 1;
        const size_t oA = (size_t)iA * W_INST, oB = (size_t)iB * W_INST;
        const size_t oLP = (size_t)i_lp * W_INST, oPL = (size_t)i_pl * W_INST;

        // ======== conv A ========
        // --- TransConv (lego->lego over ll), weights iA; GAT-pl bias folded into skip ---
        gemm(lx, oA + OW_Q, tbq + iA * 128, nullptr, q, NL, 128);
        gemm(lx, oA + OW_K, tbk + iA * 128, nullptr, k, NL, 128);
        gemm(lx, oA + OW_V, tbv + iA * 128, nullptr, v, NL, 128);
        gemm(lx, oA + OW_S, tbs + iA * 128, gb + i_pl * 128, la, NL, 128);
        trans_score_kernel<<<ceil_div(N_E_LL, 8), 256>>>(q, k, ss_ll, sd_ll, N_E_LL, sc);
        attn_agg_kernel<<<ceil_div(NL, 8), 256>>>(rp_ll, ss_ll, sc, v, la, NL);

        // --- GAT (point -> lego over pl), weights i_pl ---
        gemm(px, oPL + OW_G, nullptr, nullptr, hs, NP, 128);
        wa_kernel<<<1, 256>>>(gW + (size_t)i_pl * 16384, gAs + i_pl * 128, gAd + i_pl * 128, wa);
        gemv_dot_kernel<<<ceil_div(NP, 8), 256>>>(px, wa, asb, NP);
        gemv_dot_kernel<<<ceil_div(NL, 8), 256>>>(lx, wa + 128, adb, NL);
        gat_score_kernel<<<ceil_div(N_E_PL, 256), 256>>>(asb, adb, ss_pl, sd_pl, N_E_PL, sc);
        attn_agg_kernel<<<ceil_div(NL, 8), 256>>>(rp_pl, ss_pl, sc, hs, la, NL);

        // --- EdgeConv (point->point over pp), weights iA; GAT-lp bias folded in finalize ---
        gemm(px, oA + OW_1D, eb1 + iA * 512, nullptr, Cb, NP, 512);
        gemm(px, oA + OW_1B, nullptr, nullptr, Bb, NP, 512);
        fill_kernel<<<ceil_div(NP * DIM, 256), 256>>>(ea, -INFINITY, NP * DIM);
        edge_tc<<<ceil_div(N_E_PP, 128), 256, EDGE_SMEM>>>(Cb, Bb, ss_pp, sd_pp, N_E_PP,
                                                           wh + oA + OW_2, wl + oA + OW_2,
                                                           eb2 + iA * 128, ea);
        finalize_max_kernel<<<ceil_div(NP * DIM, 256), 256>>>(ea, gb + i_lp * 128, pa, NP * DIM);

        // --- GAT (lego -> point over lp), weights i_lp ---
        gemm(lx, oLP + OW_G, nullptr, nullptr, hs, NL, 128);
        wa_kernel<<<1, 256>>>(gW + (size_t)i_lp * 16384, gAs + i_lp * 128, gAd + i_lp * 128, wa);
        gemv_dot_kernel<<<ceil_div(NL, 8), 256>>>(lx, wa, asb, NL);
        gemv_dot_kernel<<<ceil_div(NP, 8), 256>>>(px, wa + 128, adb, NP);
        gat_score_kernel<<<ceil_div(N_E_LP, 256), 256>>>(asb, adb, ss_lp, sd_lp, N_E_LP, sc);
        attn_agg_kernel<<<ceil_div(NP, 8), 256>>>(rp_lp, ss_lp, sc, hs, pa, NP);

        // ======== conv B ========
        // --- TransConv (lego_a -> x_lego), weights iB ---
        gemm(la, oB + OW_Q, tbq + iB * 128, nullptr, q, NL, 128);
        gemm(la, oB + OW_K, tbk + iB * 128, nullptr, k, NL, 128);
        gemm(la, oB + OW_V, tbv + iB * 128, nullptr, v, NL, 128);
        gemm(la, oB + OW_S, tbs + iB * 128, nullptr, lx, NL, 128);
        trans_score_kernel<<<ceil_div(N_E_LL, 8), 256>>>(q, k, ss_ll, sd_ll, N_E_LL, sc);
        attn_agg_kernel<<<ceil_div(NL, 8), 256>>>(rp_ll, ss_ll, sc, v, lx, NL);

        // --- EdgeConv (point_a -> x_point), weights iB ---
        gemm(pa, oB + OW_1D, eb1 + iB * 512, nullptr, Cb, NP, 512);
        gemm(pa, oB + OW_1B, nullptr, nullptr, Bb, NP, 512);
        fill_kernel<<<ceil_div(NP * DIM, 256), 256>>>(ea, -INFINITY, NP * DIM);
        edge_tc<<<ceil_div(N_E_PP, 128), 256, EDGE_SMEM>>>(Cb, Bb, ss_pp, sd_pp, N_E_PP,
                                                           wh + oB + OW_2, wl + oB + OW_2,
                                                           eb2 + iB * 128, ea);
        finalize_max_kernel<<<ceil_div(NP * DIM, 256), 256>>>(ea, nullptr, px, NP * DIM);
    }

    float* out = (float*)d_out;
    cudaMemcpyAsync(out, lx, sizeof(float) * (size_t)NL * DIM, cudaMemcpyDeviceToDevice, 0);
    cudaMemcpyAsync(out + (size_t)NL * DIM, px, sizeof(float) * (size_t)NP * DIM,
                    cudaMemcpyDeviceToDevice, 0);
}

// round 14
// speedup vs baseline: 1.8533x; 1.1204x over previous
#include <cuda_runtime.h>
#include <cuda_bf16.h>
#include <math.h>
#include <stdint.h>

#define DIM 128
#define NL 50000
#define NP 100000
#define N_E_LL 500000
#define N_E_PP 400000
#define N_E_LP 500000
#define N_E_PL 500000

// ------------------------- device scratch (no allocs allowed) -------------------------
__device__ float g_lego_x[(size_t)NL * DIM];
__device__ float g_point_x[(size_t)NP * DIM];
__device__ float g_lego_a[(size_t)NL * DIM];
__device__ float g_point_a[(size_t)NP * DIM];
__device__ float g_q[(size_t)NL * DIM];
__device__ float g_k[(size_t)NL * DIM];
__device__ float g_v[(size_t)NL * DIM];
__device__ float g_hs[(size_t)NP * DIM];
__device__ float g_as[NP];
__device__ float g_ad[NP];
__device__ float g_score[N_E_LL];
__device__ float g_C[(size_t)NP * 512];
__device__ float g_B[(size_t)NP * 512];
__device__ float g_eagg[(size_t)NP * DIM];
__device__ float g_wa[256];

// sorted-edge infrastructure
__device__ int g_rp_ll[NL + 1];
__device__ int g_rp_pl[NL + 1];
__device__ int g_rp_pp[NP + 1];
__device__ int g_rp_lp[NP + 1];
__device__ int g_cur[NP + 1];
__device__ int g_part[256];
__device__ int g_ss_ll[N_E_LL], g_sd_ll[N_E_LL];
__device__ int g_ss_pp[N_E_PP], g_sd_pp[N_E_PP];
__device__ int g_ss_lp[N_E_LP], g_sd_lp[N_E_LP];
__device__ int g_ss_pl[N_E_PL], g_sd_pl[N_E_PL];

// pre-split transposed weights (bf16 hi/lo), layout [n][k] k-contiguous
#define OW_Q 0
#define OW_K 16384
#define OW_V 32768
#define OW_S 49152
#define OW_G 65536
#define OW_1D 81920
#define OW_1B 147456
#define W_INST 212992
__device__ __nv_bfloat16 g_wh[(size_t)4 * W_INST];
__device__ __nv_bfloat16 g_wl[(size_t)4 * W_INST];
// W2 transposed tf32, layout [n][512]
__device__ float g_w2t[(size_t)4 * 65536];

// ------------------------- multi-output GEMM spec -------------------------
struct OutSpec {
    float* base[8];
    const float* bias1[8];
    const float* bias2[8];
    int stride[8];
};

// ------------------------- PTX helpers -------------------------
__device__ __forceinline__ uint32_t smem_u32(const void* p) {
    uint32_t a;
    asm("{ .reg .u64 t; cvta.to.shared.u64 t, %1; cvt.u32.u64 %0, t; }" : "=r"(a) : "l"(p));
    return a;
}
__device__ __forceinline__ void ldsm_x4(uint32_t* r, uint32_t addr) {
    asm volatile("ldmatrix.sync.aligned.m8n8.x4.shared.b16 {%0,%1,%2,%3}, [%4];"
                 : "=r"(r[0]), "=r"(r[1]), "=r"(r[2]), "=r"(r[3]) : "r"(addr));
}
__device__ __forceinline__ void mma_bf16(float* c, const uint32_t* a, const uint32_t* b) {
    asm volatile(
        "mma.sync.aligned.m16n8k16.row.col.f32.bf16.bf16.f32 "
        "{%0,%1,%2,%3}, {%4,%5,%6,%7}, {%8,%9}, {%0,%1,%2,%3};"
        : "+f"(c[0]), "+f"(c[1]), "+f"(c[2]), "+f"(c[3])
        : "r"(a[0]), "r"(a[1]), "r"(a[2]), "r"(a[3]), "r"(b[0]), "r"(b[1]));
}
__device__ __forceinline__ void mma_tf32(float* c, const uint32_t* a, const uint32_t* b) {
    asm volatile(
        "mma.sync.aligned.m16n8k8.row.col.f32.tf32.tf32.f32 "
        "{%0,%1,%2,%3}, {%4,%5,%6,%7}, {%8,%9}, {%0,%1,%2,%3};"
        : "+f"(c[0]), "+f"(c[1]), "+f"(c[2]), "+f"(c[3])
        : "r"(a[0]), "r"(a[1]), "r"(a[2]), "r"(a[3]), "r"(b[0]), "r"(b[1]));
}
__device__ __forceinline__ uint32_t f2tf(float x) {
    uint32_t u;
    asm("cvt.rna.tf32.f32 %0, %1;" : "=r"(u) : "f"(x));
    return u;
}

// split 8 fp32 into hi/lo bf16 16B groups (Markstein split)
__device__ __forceinline__ void split8(const float* f, uint4* hi, uint4* lo) {
    uint32_t hw[4], lw[4];
#pragma unroll
    for (int i = 0; i < 4; i++) {
        float x0 = f[2 * i], x1 = f[2 * i + 1];
        __nv_bfloat16 h0 = __float2bfloat16(x0), h1 = __float2bfloat16(x1);
        __nv_bfloat162 hp = __halves2bfloat162(h0, h1);
        hw[i] = *reinterpret_cast<uint32_t*>(&hp);
        __nv_bfloat16 l0 = __float2bfloat16(x0 - __bfloat162float(h0));
        __nv_bfloat16 l1 = __float2bfloat16(x1 - __bfloat162float(h1));
        __nv_bfloat162 lp = __halves2bfloat162(l0, l1);
        lw[i] = *reinterpret_cast<uint32_t*>(&lp);
    }
    *hi = make_uint4(hw[0], hw[1], hw[2], hw[3]);
    *lo = make_uint4(lw[0], lw[1], lw[2], lw[3]);
}

// ------------------------- small helpers -------------------------
__device__ __forceinline__ void atomicMaxF(float* addr, float val) {
    if (val >= 0.0f) atomicMax((int*)addr, __float_as_int(val));
    else             atomicMin((unsigned int*)addr, (unsigned int)__float_as_int(val));
}

__global__ void fill_kernel(float* __restrict__ p, float v, int n) {
    int i = blockIdx.x * blockDim.x + threadIdx.x;
    if (i < n) p[i] = v;
}
__global__ void fill_int_kernel(int* __restrict__ p, int v, int n) {
    int i = blockIdx.x * blockDim.x + threadIdx.x;
    if (i < n) p[i] = v;
}
__global__ void copy_int_kernel(int* __restrict__ d, const int* __restrict__ s, int n) {
    int i = blockIdx.x * blockDim.x + threadIdx.x;
    if (i < n) d[i] = s[i];
}

// ------------------------- counting sort by dst -------------------------
__global__ void hist_kernel(const int* __restrict__ dst, int E, int* __restrict__ cnt) {
    int e = blockIdx.x * blockDim.x + threadIdx.x;
    if (e < E) atomicAdd(&cnt[dst[e]], 1);
}
__global__ void scan_block_kernel(int* __restrict__ data, int* __restrict__ part, int n) {
    __shared__ int sh[1024];
    int i = blockIdx.x * 1024 + threadIdx.x;
    int x = (i < n) ? data[i] : 0;
    sh[threadIdx.x] = x;
    __syncthreads();
    for (int o = 1; o < 1024; o <<= 1) {
        int t = (threadIdx.x >= o) ? sh[threadIdx.x - o] : 0;
        __syncthreads();
        sh[threadIdx.x] += t;
        __syncthreads();
    }
    if (i < n) data[i] = sh[threadIdx.x] - x;      // exclusive
    if (threadIdx.x == 1023) part[blockIdx.x] = sh[1023];
}
__global__ void scan_part_kernel(int* __restrict__ part, int nb) {
    __shared__ int sh[1024];
    int x = (threadIdx.x < nb) ? part[threadIdx.x] : 0;
    sh[threadIdx.x] = x;
    __syncthreads();
    for (int o = 1; o < 1024; o <<= 1) {
        int t = (threadIdx.x >= o) ? sh[threadIdx.x - o] : 0;
        __syncthreads();
        sh[threadIdx.x] += t;
        __syncthreads();
    }
    if (threadIdx.x < nb) part[threadIdx.x] = sh[threadIdx.x] - x;   // exclusive
}
__global__ void scan_add_kernel(int* __restrict__ data, const int* __restrict__ part, int n) {
    int i = blockIdx.x * 1024 + threadIdx.x;
    if (i < n) data[i] += part[blockIdx.x];
}
__global__ void scatter_kernel(const int* __restrict__ src, const int* __restrict__ dst, int E,
                               int* __restrict__ cur, int* __restrict__ ssrc, int* __restrict__ sdst) {
    int e = blockIdx.x * blockDim.x + threadIdx.x;
    if (e >= E) return;
    int d = dst[e];
    int pos = atomicAdd(&cur[d], 1);
    ssrc[pos] = src[e];
    sdst[pos] = d;
}

// ------------------------- weight prep -------------------------
__global__ void split_wT_kernel(const float* __restrict__ W, int K, int N,
                                __nv_bfloat16* __restrict__ hiT, __nv_bfloat16* __restrict__ loT) {
    int idx = blockIdx.x * 256 + threadIdx.x;
    if (idx >= K * N) return;
    int k = idx / N, n = idx - k * N;
    float x = W[idx];
    __nv_bfloat16 h = __float2bfloat16(x);
    __nv_bfloat16 l = __float2bfloat16(x - __bfloat162float(h));
    hiT[(size_t)n * K + k] = h;
    loT[(size_t)n * K + k] = l;
}
// W1diff = W1[0:128,:] - W1[128:256,:]  (K=128, N=512), split+transpose
__global__ void split_w1d_kernel(const float* __restrict__ W1,
                                 __nv_bfloat16* __restrict__ hiT, __nv_bfloat16* __restrict__ loT) {
    int idx = blockIdx.x * 256 + threadIdx.x;
    if (idx >= 128 * 512) return;
    int k = idx >> 9, n = idx & 511;
    float x = W1[idx] - W1[idx + 128 * 512];
    __nv_bfloat16 h = __float2bfloat16(x);
    __nv_bfloat16 l = __float2bfloat16(x - __bfloat162float(h));
    hiT[(size_t)n * 128 + k] = h;
    loT[(size_t)n * 128 + k] = l;
}
// W2 [512][128] -> transposed tf32 [128][512]
__global__ void split_w2_tf32_kernel(const float* __restrict__ W2, float* __restrict__ outT) {
    int idx = blockIdx.x * 256 + threadIdx.x;
    if (idx >= 512 * 128) return;
    int k = idx >> 7, n = idx & 127;
    ((uint32_t*)outT)[(size_t)n * 512 + k] = f2tf(W2[idx]);
}

__global__ void wa_kernel(const float* __restrict__ W, const float* __restrict__ a_s,
                          const float* __restrict__ a_d, float* __restrict__ wa) {
    int r = threadIdx.x;
    const float* av = (r < 128) ? a_s : a_d;
    int rr = r & 127;
    float s = 0.0f;
    for (int c = 0; c < 128; c++) s = fmaf(W[rr * 128 + c], av[c], s);
    wa[r] = s;
}

__global__ void gemv_dot_kernel(const float* __restrict__ X, const float* __restrict__ w,
                                float* __restrict__ out, int N) {
    int i = (blockIdx.x * blockDim.x + threadIdx.x) >> 5;
    if (i >= N) return;
    int lane = threadIdx.x & 31;
    float4 xa = ((const float4*)(X + (size_t)i * DIM))[lane];
    float4 wv = ((const float4*)w)[lane];
    float p = xa.x * wv.x + xa.y * wv.y + xa.z * wv.z + xa.w * wv.w;
#pragma unroll
    for (int o = 16; o; o >>= 1) p += __shfl_down_sync(0xffffffffu, p, o);
    if (lane == 0) out[i] = p;
}

// ------------------------- mma.sync node GEMM (bf16 3-pass, multi-output) -------------------------
#define SA_G 272
#define OAH 0
#define OAL 34816
#define OBH 69632
#define OBL 104448
#define GEMM_SMEM 139264

__global__ __launch_bounds__(256, 1)
void gemm_tc(const float* __restrict__ X,
             const __nv_bfloat16* __restrict__ WhiT, const __nv_bfloat16* __restrict__ WloT,
             OutSpec spec, int M) {
    extern __shared__ __align__(16) char smem[];
    const uint32_t sbase = smem_u32(smem);
    const int tid = threadIdx.x, lane = tid & 31, wid = tid >> 5;
    const int bm = blockIdx.y * 128, bn = blockIdx.x * 128;

    // ---- A tile: X rows [bm, bm+128) x K=128, hi/lo split on the fly ----
#pragma unroll
    for (int it = 0; it < 8; it++) {
        int task = tid + it * 256;           // 2048 tasks: 128 m x 16 k8
        int m = task >> 4, k8 = task & 15;
        int gm = bm + m;
        float f[8];
        if (gm < M) {
            const float4* p = (const float4*)(X + (size_t)gm * 128 + k8 * 8);
            float4 a = p[0], b = p[1];
            f[0] = a.x; f[1] = a.y; f[2] = a.z; f[3] = a.w;
            f[4] = b.x; f[5] = b.y; f[6] = b.z; f[7] = b.w;
        } else {
#pragma unroll
            for (int i = 0; i < 8; i++) f[i] = 0.0f;
        }
        uint4 hi, lo; split8(f, &hi, &lo);
        uint32_t off = (uint32_t)m * SA_G + (uint32_t)k8 * 16;
        *(uint4*)(smem + OAH + off) = hi;
        *(uint4*)(smem + OAL + off) = lo;
    }
    // ---- B tile: straight copies from pre-split transposed weights ----
#pragma unroll
    for (int it = 0; it < 8; it++) {
        int task = tid + it * 256;           // 2048 tasks: 128 n x 16 chunks
        int n = task >> 4, c = task & 15;
        uint32_t off = (uint32_t)n * SA_G + (uint32_t)c * 16;
        *(uint4*)(smem + OBH + off) = *(const uint4*)(WhiT + (size_t)(bn + n) * 128 + c * 8);
        *(uint4*)(smem + OBL + off) = *(const uint4*)(WloT + (size_t)(bn + n) * 128 + c * 8);
    }
    __syncthreads();

    const int wm = (wid & 3) * 32, wn = (wid >> 2) * 64;
    const int g = lane >> 3, lr = lane & 7;
    const uint32_t aoff = (uint32_t)((g & 1) * 8 + lr) * SA_G + (uint32_t)(g >> 1) * 16;
    const uint32_t boff = (uint32_t)((g >> 1) * 8 + lr) * SA_G + (uint32_t)(g & 1) * 16;

    float acc[2][8][4];
#pragma unroll
    for (int i = 0; i < 2; i++)
#pragma unroll
        for (int j = 0; j < 8; j++)
#pragma unroll
            for (int r = 0; r < 4; r++) acc[i][j][r] = 0.0f;

#pragma unroll
    for (int pass = 0; pass < 3; pass++) {
        uint32_t Ab = sbase + (pass == 2 ? OAL : OAH) + (uint32_t)wm * SA_G + aoff;
        uint32_t Bb = sbase + (pass == 1 ? OBL : OBH) + (uint32_t)wn * SA_G + boff;
#pragma unroll
        for (int s = 0; s < 8; s++) {
            uint32_t a[2][4], b[4][4];
#pragma unroll
            for (int i = 0; i < 2; i++) ldsm_x4(a[i], Ab + i * (16 * SA_G) + s * 32);
#pragma unroll
            for (int j = 0; j < 4; j++) ldsm_x4(b[j], Bb + j * (16 * SA_G) + s * 32);
#pragma unroll
            for (int i = 0; i < 2; i++)
#pragma unroll
                for (int j = 0; j < 8; j++)
                    mma_bf16(acc[i][j], a[i], &b[j >> 1][(j & 1) * 2]);
        }
    }

    // ---- epilogue via OutSpec ----
    float* base = spec.base[blockIdx.x];
    const float* bb1 = spec.bias1[blockIdx.x];
    const float* bb2 = spec.bias2[blockIdx.x];
    const int stride = spec.stride[blockIdx.x];
    const int qq = lane >> 2, idx = lane & 3;
#pragma unroll
    for (int i = 0; i < 2; i++) {
        int gr0 = bm + wm + i * 16 + qq;
#pragma unroll
        for (int j = 0; j < 8; j++) {
            int gcl = wn + j * 8 + idx * 2;
            float bb0 = 0.0f, bv1 = 0.0f;
            if (bb1) { bb0 += bb1[gcl]; bv1 += bb1[gcl + 1]; }
            if (bb2) { bb0 += bb2[gcl]; bv1 += bb2[gcl + 1]; }
            if (gr0 < M)
                *(float2*)(base + (size_t)gr0 * stride + gcl) =
                    make_float2(acc[i][j][0] + bb0, acc[i][j][1] + bv1);
            int gr1 = gr0 + 8;
            if (gr1 < M)
                *(float2*)(base + (size_t)gr1 * stride + gcl) =
                    make_float2(acc[i][j][2] + bb0, acc[i][j][3] + bv1);
        }
    }
}

// ------------------------- tf32 single-pass EdgeConv MLP + segment max -------------------------
// 128 edges/CTA; H = relu(Cn[dst]+Bn[src]) (K=512 in 64-chunks, double-buffered);
// D = H @ W2 via m16n8k8 tf32; epilogue atomicMax into agg[dst].
#define ET_G 272
#define EOH0 1024
#define EOH1 35840
#define EOW0 70656
#define EOW1 105472
#define EDGE_SMEM 140288

__global__ __launch_bounds__(256, 1)
void edge_tc(const float* __restrict__ Cn, const float* __restrict__ Bn,
             const int* __restrict__ src, const int* __restrict__ dst, int E,
             const float* __restrict__ W2T, const float* __restrict__ b2,
             float* __restrict__ agg) {
    extern __shared__ __align__(16) char smem[];
    const uint32_t sbase = smem_u32(smem);
    const int tid = threadIdx.x, lane = tid & 31, wid = tid >> 5;
    const int e0 = blockIdx.x * 128;
    int* sS = (int*)(smem);
    int* sD = (int*)(smem + 512);

    if (tid < 128) {
        int e = e0 + tid;
        sS[tid] = (e < E) ? src[e] : 0;
        sD[tid] = (e < E) ? dst[e] : 0;
    }
    __syncthreads();

    const int wm = (wid & 3) * 32, wn = (wid >> 2) * 64;
    const int midx = lane >> 3, r = lane & 7;
    // A frag (m16k8): matrices = (rows0-7,klo),(rows8-15,klo),(rows0-7,khi),(rows8-15,khi)
    const uint32_t a_off = (uint32_t)(wm + (midx & 1) * 8 + r) * ET_G + (uint32_t)(midx >> 1) * 16;
    // B frags (k8n8) pair j: (nblk lo, klo),(nblk lo, khi),(nblk hi, klo),(nblk hi, khi)
    uint32_t b_off[4];
#pragma unroll
    for (int j = 0; j < 4; j++)
        b_off[j] = (uint32_t)(wn + 16 * j + (midx >> 1) * 8 + r) * ET_G + (uint32_t)(midx & 1) * 16;

    float acc[2][8][4];
#pragma unroll
    for (int i = 0; i < 2; i++)
#pragma unroll
        for (int j = 0; j < 8; j++)
#pragma unroll
            for (int rr = 0; rr < 4; rr++) acc[i][j][rr] = 0.0f;

    const int HB[2] = {EOH0, EOH1};
    const int WB[2] = {EOW0, EOW1};

    auto load_chunk = [&](int kc, int pb) {
        char* wdst = smem + WB[pb];
        const float* wsrc = W2T + kc * 64;
#pragma unroll
        for (int it = 0; it < 8; it++) {
            int task = tid + it * 256;       // 2048: 128 n x 16 chunks
            int n = task >> 4, c = task & 15;
            *(uint4*)(wdst + n * ET_G + c * 16) = *(const uint4*)(wsrc + (size_t)n * 512 + c * 4);
        }
        char* hdst = smem + HB[pb];
#pragma unroll
        for (int it = 0; it < 4; it++) {
            int task = tid + it * 256;       // 1024: 128 e x 8 k8
            int e = task >> 3, k8 = task & 7;
            const float4* pc = (const float4*)(Cn + (size_t)sD[e] * 512 + kc * 64 + k8 * 8);
            const float4* pb4 = (const float4*)(Bn + (size_t)sS[e] * 512 + kc * 64 + k8 * 8);
            float4 c0v = pc[0], c1v = pc[1], b0v = pb4[0], b1v = pb4[1];
            uint4 u0, u1;
            u0.x = f2tf(fmaxf(c0v.x + b0v.x, 0.f));
            u0.y = f2tf(fmaxf(c0v.y + b0v.y, 0.f));
            u0.z = f2tf(fmaxf(c0v.z + b0v.z, 0.f));
            u0.w = f2tf(fmaxf(c0v.w + b0v.w, 0.f));
            u1.x = f2tf(fmaxf(c1v.x + b1v.x, 0.f));
            u1.y = f2tf(fmaxf(c1v.y + b1v.y, 0.f));
            u1.z = f2tf(fmaxf(c1v.z + b1v.z, 0.f));
            u1.w = f2tf(fmaxf(c1v.w + b1v.w, 0.f));
            *(uint4*)(hdst + e * ET_G + k8 * 32) = u0;
            *(uint4*)(hdst + e * ET_G + k8 * 32 + 16) = u1;
        }
    };

    load_chunk(0, 0);
    __syncthreads();

    for (int kc = 0; kc < 8; kc++) {
        int pb = kc & 1;
        if (kc < 7) load_chunk(kc + 1, pb ^ 1);
        uint32_t Hbase = sbase + HB[pb];
        uint32_t Wbase = sbase + WB[pb];
#pragma unroll
        for (int s = 0; s < 8; s++) {
            uint32_t a[2][4];
            ldsm_x4(a[0], Hbase + a_off + s * 32);
            ldsm_x4(a[1], Hbase + a_off + 16 * ET_G + s * 32);
            uint32_t b[4][4];
#pragma unroll
            for (int j = 0; j < 4; j++) ldsm_x4(b[j], Wbase + b_off[j] + s * 32);
#pragma unroll
            for (int i = 0; i < 2; i++)
#pragma unroll
                for (int j = 0; j < 4; j++) {
                    mma_tf32(acc[i][2 * j],     a[i], &b[j][0]);
                    mma_tf32(acc[i][2 * j + 1], a[i], &b[j][2]);
                }
        }
        __syncthreads();
    }

    // ---- epilogue: segment-max atomics (dst-sorted -> L2-local) ----
    const int qq = lane >> 2, idx = lane & 3;
#pragma unroll
    for (int i = 0; i < 2; i++) {
#pragma unroll
        for (int half = 0; half < 2; half++) {
            int el = wm + i * 16 + half * 8 + qq;
            if (e0 + el >= E) continue;
            float* ag = agg + (size_t)sD[el] * 128;
#pragma unroll
            for (int j = 0; j < 8; j++) {
                int c = wn + j * 8 + idx * 2;
                atomicMaxF(&ag[c],     acc[i][j][half * 2 + 0] + b2[c]);
                atomicMaxF(&ag[c + 1], acc[i][j][half * 2 + 1] + b2[c + 1]);
            }
        }
    }
}

// ------------------------- score kernels (sorted edges, no atomics) -------------------------
__global__ void trans_score_kernel(const float* __restrict__ q, const float* __restrict__ k,
                                   const int* __restrict__ ssrc, const int* __restrict__ sdst,
                                   int E, float* __restrict__ score) {
    int e = (blockIdx.x * blockDim.x + threadIdx.x) >> 5;
    if (e >= E) return;
    int lane = threadIdx.x & 31;
    int s = ssrc[e], d = sdst[e];
    float4 qa = ((const float4*)(q + (size_t)d * DIM))[lane];
    float4 ka = ((const float4*)(k + (size_t)s * DIM))[lane];
    float p = qa.x * ka.x + qa.y * ka.y + qa.z * ka.z + qa.w * ka.w;
#pragma unroll
    for (int o = 16; o; o >>= 1) p += __shfl_down_sync(0xffffffffu, p, o);
    if (lane == 0) score[e] = p * 0.08838834764831845f;
}

__global__ void gat_score_kernel(const float* __restrict__ as_, const float* __restrict__ ad_,
                                 const int* __restrict__ ssrc, const int* __restrict__ sdst,
                                 int E, float* __restrict__ score) {
    int e = blockIdx.x * blockDim.x + threadIdx.x;
    if (e >= E) return;
    float s = as_[ssrc[e]] + ad_[sdst[e]];
    score[e] = (s > 0.0f) ? s : 0.2f * s;
}

// ------------------------- CSR softmax-aggregation: warp per dst node -------------------------
__global__ void attn_agg_kernel(const int* __restrict__ rp, const int* __restrict__ ssrc,
                                const float* __restrict__ score, const float* __restrict__ v,
                                float* __restrict__ out, int N) {
    int node = (blockIdx.x * blockDim.x + threadIdx.x) >> 5;
    if (node >= N) return;
    int lane = threadIdx.x & 31;
    int beg = rp[node], end = rp[node + 1];
    if (beg == end) return;
    float m = -INFINITY;
    for (int i = beg + lane; i < end; i += 32) m = fmaxf(m, score[i]);
#pragma unroll
    for (int o = 16; o; o >>= 1) m = fmaxf(m, __shfl_xor_sync(0xffffffffu, m, o));
    float ax = 0.f, ay = 0.f, az = 0.f, aw = 0.f, asum = 0.f;
    for (int e = beg; e < end; e++) {
        float a = expf(score[e] - m);
        asum += a;
        float4 val = ((const float4*)(v + (size_t)ssrc[e] * DIM))[lane];
        ax = fmaf(a, val.x, ax); ay = fmaf(a, val.y, ay);
        az = fmaf(a, val.z, az); aw = fmaf(a, val.w, aw);
    }
    float inv = 1.0f / (asum + 1e-16f);
    float4* op = (float4*)(out + (size_t)node * DIM) + lane;
    float4 cur = *op;
    cur.x += ax * inv; cur.y += ay * inv; cur.z += az * inv; cur.w += aw * inv;
    *op = cur;
}

__global__ void finalize_max_kernel(const float* __restrict__ agg, const float* __restrict__ gbias,
                                    float* __restrict__ out, int n) {
    int i = blockIdx.x * blockDim.x + threadIdx.x;
    if (i >= n) return;
    float v = agg[i];
    if (!isfinite(v)) v = 0.0f;
    if (gbias) v += gbias[i & (DIM - 1)];
    out[i] = v;
}

// ------------------------- host orchestration -------------------------
static inline int ceil_div(int a, int b) { return (a + b - 1) / b; }

extern "C" void kernel_launch(void* const* d_in, const int* in_sizes, int n_in,
                              void* d_out, int out_size) {
    const float* in_xl = (const float*)d_in[0];
    const float* in_xp = (const float*)d_in[1];
    const float* tWq = (const float*)d_in[2];
    const float* tbq = (const float*)d_in[3];
    const float* tWk = (const float*)d_in[4];
    const float* tbk = (const float*)d_in[5];
    const float* tWv = (const float*)d_in[6];
    const float* tbv = (const float*)d_in[7];
    const float* tWs = (const float*)d_in[8];
    const float* tbs = (const float*)d_in[9];
    const float* eW1 = (const float*)d_in[10];
    const float* eb1 = (const float*)d_in[11];
    const float* eW2 = (const float*)d_in[12];
    const float* eb2 = (const float*)d_in[13];
    const float* gW  = (const float*)d_in[14];
    const float* gAs = (const float*)d_in[15];
    const float* gAd = (const float*)d_in[16];
    const float* gb  = (const float*)d_in[17];
    const int* ll_src = (const int*)d_in[18];
    const int* ll_dst = (const int*)d_in[19];
    const int* pp_src = (const int*)d_in[20];
    const int* pp_dst = (const int*)d_in[21];
    const int* lp_src = (const int*)d_in[22];
    const int* lp_dst = (const int*)d_in[23];
    const int* pl_src = (const int*)d_in[24];
    const int* pl_dst = (const int*)d_in[25];

    cudaFuncSetAttribute(gemm_tc, cudaFuncAttributeMaxDynamicSharedMemorySize, GEMM_SMEM);
    cudaFuncSetAttribute(edge_tc, cudaFuncAttributeMaxDynamicSharedMemorySize, EDGE_SMEM);

    float *lx, *px, *la, *pa, *q, *k, *v, *hs, *asb, *adb, *sc, *Cb, *Bb, *ea, *wa, *w2t;
    cudaGetSymbolAddress((void**)&lx, g_lego_x);
    cudaGetSymbolAddress((void**)&px, g_point_x);
    cudaGetSymbolAddress((void**)&la, g_lego_a);
    cudaGetSymbolAddress((void**)&pa, g_point_a);
    cudaGetSymbolAddress((void**)&q, g_q);
    cudaGetSymbolAddress((void**)&k, g_k);
    cudaGetSymbolAddress((void**)&v, g_v);
    cudaGetSymbolAddress((void**)&hs, g_hs);
    cudaGetSymbolAddress((void**)&asb, g_as);
    cudaGetSymbolAddress((void**)&adb, g_ad);
    cudaGetSymbolAddress((void**)&sc, g_score);
    cudaGetSymbolAddress((void**)&Cb, g_C);
    cudaGetSymbolAddress((void**)&Bb, g_B);
    cudaGetSymbolAddress((void**)&ea, g_eagg);
    cudaGetSymbolAddress((void**)&wa, g_wa);
    cudaGetSymbolAddress((void**)&w2t, g_w2t);

    int *rp_ll, *rp_pl, *rp_pp, *rp_lp, *cur, *part;
    int *ss_ll, *sd_ll, *ss_pp, *sd_pp, *ss_lp, *sd_lp, *ss_pl, *sd_pl;
    cudaGetSymbolAddress((void**)&rp_ll, g_rp_ll);
    cudaGetSymbolAddress((void**)&rp_pl, g_rp_pl);
    cudaGetSymbolAddress((void**)&rp_pp, g_rp_pp);
    cudaGetSymbolAddress((void**)&rp_lp, g_rp_lp);
    cudaGetSymbolAddress((void**)&cur, g_cur);
    cudaGetSymbolAddress((void**)&part, g_part);
    cudaGetSymbolAddress((void**)&ss_ll, g_ss_ll);
    cudaGetSymbolAddress((void**)&sd_ll, g_sd_ll);
    cudaGetSymbolAddress((void**)&ss_pp, g_ss_pp);
    cudaGetSymbolAddress((void**)&sd_pp, g_sd_pp);
    cudaGetSymbolAddress((void**)&ss_lp, g_ss_lp);
    cudaGetSymbolAddress((void**)&sd_lp, g_sd_lp);
    cudaGetSymbolAddress((void**)&ss_pl, g_ss_pl);
    cudaGetSymbolAddress((void**)&sd_pl, g_sd_pl);

    __nv_bfloat16 *wh, *wl;
    cudaGetSymbolAddress((void**)&wh, g_wh);
    cudaGetSymbolAddress((void**)&wl, g_wl);

    // ---- counting sort of each relation by dst ----
    auto sort_rel = [&](const int* src, const int* dst, int E, int Nn,
                        int* rp, int* ssrc, int* sdst) {
        int n1 = Nn + 1;
        fill_int_kernel<<<ceil_div(n1, 256), 256>>>(rp, 0, n1);
        hist_kernel<<<ceil_div(E, 256), 256>>>(dst, E, rp);
        int nb = ceil_div(n1, 1024);
        scan_block_kernel<<<nb, 1024>>>(rp, part, n1);
        scan_part_kernel<<<1, 1024>>>(part, nb);
        scan_add_kernel<<<nb, 1024>>>(rp, part, n1);
        copy_int_kernel<<<ceil_div(n1, 256), 256>>>(cur, rp, n1);
        scatter_kernel<<<ceil_div(E, 256), 256>>>(src, dst, E, cur, ssrc, sdst);
    };
    sort_rel(ll_src, ll_dst, N_E_LL, NL, rp_ll, ss_ll, sd_ll);
    sort_rel(pp_src, pp_dst, N_E_PP, NP, rp_pp, ss_pp, sd_pp);
    sort_rel(lp_src, lp_dst, N_E_LP, NP, rp_lp, ss_lp, sd_lp);
    sort_rel(pl_src, pl_dst, N_E_PL, NL, rp_pl, ss_pl, sd_pl);

    // ---- pre-split / pre-convert all weights ----
    for (int i = 0; i < 4; i++) {
        size_t o = (size_t)i * W_INST;
        split_wT_kernel<<<64, 256>>>(tWq + (size_t)i * 16384, 128, 128, wh + o + OW_Q, wl + o + OW_Q);
        split_wT_kernel<<<64, 256>>>(tWk + (size_t)i * 16384, 128, 128, wh + o + OW_K, wl + o + OW_K);
        split_wT_kernel<<<64, 256>>>(tWv + (size_t)i * 16384, 128, 128, wh + o + OW_V, wl + o + OW_V);
        split_wT_kernel<<<64, 256>>>(tWs + (size_t)i * 16384, 128, 128, wh + o + OW_S, wl + o + OW_S);
        split_wT_kernel<<<64, 256>>>(gW  + (size_t)i * 16384, 128, 128, wh + o + OW_G, wl + o + OW_G);
        split_w1d_kernel<<<256, 256>>>(eW1 + (size_t)i * 131072, wh + o + OW_1D, wl + o + OW_1D);
        split_wT_kernel<<<256, 256>>>(eW1 + (size_t)i * 131072 + 65536, 128, 512,
                                      wh + o + OW_1B, wl + o + OW_1B);
        split_w2_tf32_kernel<<<256, 256>>>(eW2 + (size_t)i * 65536, w2t + (size_t)i * 65536);
    }

    auto gemm_multi = [&](const float* X, size_t woff, const OutSpec& sp, int M, int nblk) {
        dim3 gr(nblk, ceil_div(M, 128));
        gemm_tc<<<gr, 256, GEMM_SMEM>>>(X, wh + woff, wl + woff, sp, M);
    };

    cudaMemcpyAsync(lx, in_xl, sizeof(float) * (size_t)NL * DIM, cudaMemcpyDeviceToDevice, 0);
    cudaMemcpyAsync(px, in_xp, sizeof(float) * (size_t)NP * DIM, cudaMemcpyDeviceToDevice, 0);

    for (int layer = 0; layer < 2; layer++) {
        const int iA = 2 * layer, iB = 2 * layer + 1;
        const int i_lp = 2 * layer, i_pl = 2 * layer + 1;
        const size_t oA = (size_t)iA * W_INST, oB = (size_t)iB * W_INST;
        const size_t oLP = (size_t)i_lp * W_INST, oPL = (size_t)i_pl * W_INST;

        // ======== conv A ========
        // --- TransConv QKVS fused (lego->lego over ll); GAT-pl bias folded into skip ---
        {
            OutSpec sp{};
            sp.base[0] = q;  sp.bias1[0] = tbq + iA * 128; sp.stride[0] = 128;
            sp.base[1] = k;  sp.bias1[1] = tbk + iA * 128; sp.stride[1] = 128;
            sp.base[2] = v;  sp.bias1[2] = tbv + iA * 128; sp.stride[2] = 128;
            sp.base[3] = la; sp.bias1[3] = tbs + iA * 128; sp.bias2[3] = gb + i_pl * 128;
            sp.stride[3] = 128;
            gemm_multi(lx, oA + OW_Q, sp, NL, 4);
        }
        trans_score_kernel<<<ceil_div(N_E_LL, 8), 256>>>(q, k, ss_ll, sd_ll, N_E_LL, sc);
        attn_agg_kernel<<<ceil_div(NL, 8), 256>>>(rp_ll, ss_ll, sc, v, la, NL);

        // --- GAT (point -> lego over pl) ---
        {
            OutSpec sp{};
            sp.base[0] = hs; sp.stride[0] = 128;
            gemm_multi(px, oPL + OW_G, sp, NP, 1);
        }
        wa_kernel<<<1, 256>>>(gW + (size_t)i_pl * 16384, gAs + i_pl * 128, gAd + i_pl * 128, wa);
        gemv_dot_kernel<<<ceil_div(NP, 8), 256>>>(px, wa, asb, NP);
        gemv_dot_kernel<<<ceil_div(NL, 8), 256>>>(lx, wa + 128, adb, NL);
        gat_score_kernel<<<ceil_div(N_E_PL, 256), 256>>>(asb, adb, ss_pl, sd_pl, N_E_PL, sc);
        attn_agg_kernel<<<ceil_div(NL, 8), 256>>>(rp_pl, ss_pl, sc, hs, la, NL);

        // --- EdgeConv (point->point over pp); GAT-lp bias folded in finalize ---
        {
            OutSpec sp{};
            for (int i = 0; i < 4; i++) {
                sp.base[i] = Cb + i * 128; sp.stride[i] = 512;
                sp.bias1[i] = eb1 + iA * 512 + i * 128;
            }
            for (int i = 4; i < 8; i++) { sp.base[i] = Bb + (i - 4) * 128; sp.stride[i] = 512; }
            gemm_multi(px, oA + OW_1D, sp, NP, 8);
        }
        fill_kernel<<<ceil_div(NP * DIM, 256), 256>>>(ea, -INFINITY, NP * DIM);
        edge_tc<<<ceil_div(N_E_PP, 128), 256, EDGE_SMEM>>>(Cb, Bb, ss_pp, sd_pp, N_E_PP,
                                                           w2t + (size_t)iA * 65536,
                                                           eb2 + iA * 128, ea);
        finalize_max_kernel<<<ceil_div(NP * DIM, 256), 256>>>(ea, gb + i_lp * 128, pa, NP * DIM);

        // --- GAT (lego -> point over lp) ---
        {
            OutSpec sp{};
            sp.base[0] = hs; sp.stride[0] = 128;
            gemm_multi(lx, oLP + OW_G, sp, NL, 1);
        }
        wa_kernel<<<1, 256>>>(gW + (size_t)i_lp * 16384, gAs + i_lp * 128, gAd + i_lp * 128, wa);
        gemv_dot_kernel<<<ceil_div(NL, 8), 256>>>(lx, wa, asb, NL);
        gemv_dot_kernel<<<ceil_div(NP, 8), 256>>>(px, wa + 128, adb, NP);
        gat_score_kernel<<<ceil_div(N_E_LP, 256), 256>>>(asb, adb, ss_lp, sd_lp, N_E_LP, sc);
        attn_agg_kernel<<<ceil_div(NP, 8), 256>>>(rp_lp, ss_lp, sc, hs, pa, NP);

        // ======== conv B ========
        // --- TransConv QKVS fused (lego_a -> x_lego) ---
        {
            OutSpec sp{};
            sp.base[0] = q;  sp.bias1[0] = tbq + iB * 128; sp.stride[0] = 128;
            sp.base[1] = k;  sp.bias1[1] = tbk + iB * 128; sp.stride[1] = 128;
            sp.base[2] = v;  sp.bias1[2] = tbv + iB * 128; sp.stride[2] = 128;
            sp.base[3] = lx; sp.bias1[3] = tbs + iB * 128; sp.stride[3] = 128;
            gemm_multi(la, oB + OW_Q, sp, NL, 4);
        }
        trans_score_kernel<<<ceil_div(N_E_LL, 8), 256>>>(q, k, ss_ll, sd_ll, N_E_LL, sc);
        attn_agg_kernel<<<ceil_div(NL, 8), 256>>>(rp_ll, ss_ll, sc, v, lx, NL);

        // --- EdgeConv (point_a -> x_point) ---
        {
            OutSpec sp{};
            for (int i = 0; i < 4; i++) {
                sp.base[i] = Cb + i * 128; sp.stride[i] = 512;
                sp.bias1[i] = eb1 + iB * 512 + i * 128;
            }
            for (int i = 4; i < 8; i++) { sp.base[i] = Bb + (i - 4) * 128; sp.stride[i] = 512; }
            gemm_multi(pa, oB + OW_1D, sp, NP, 8);
        }
        fill_kernel<<<ceil_div(NP * DIM, 256), 256>>>(ea, -INFINITY, NP * DIM);
        edge_tc<<<ceil_div(N_E_PP, 128), 256, EDGE_SMEM>>>(Cb, Bb, ss_pp, sd_pp, N_E_PP,
                                                           w2t + (size_t)iB * 65536,
                                                           eb2 + iB * 128, ea);
        finalize_max_kernel<<<ceil_div(NP * DIM, 256), 256>>>(ea, nullptr, px, NP * DIM);
    }

    float* out = (float*)d_out;
    cudaMemcpyAsync(out, lx, sizeof(float) * (size_t)NL * DIM, cudaMemcpyDeviceToDevice, 0);
    cudaMemcpyAsync(out + (size_t)NL * DIM, px, sizeof(float) * (size_t)NP * DIM,
                    cudaMemcpyDeviceToDevice, 0);
}

// round 15
// speedup vs baseline: 2.0449x; 1.1034x over previous
#include <cuda_runtime.h>
#include <cuda_bf16.h>
#include <cuda_fp16.h>
#include <math.h>
#include <stdint.h>

#define DIM 128
#define NL 50000
#define NP 100000
#define N_E_LL 500000
#define N_E_PP 400000
#define N_E_LP 500000
#define N_E_PL 500000

// ------------------------- device scratch (no allocs allowed) -------------------------
__device__ float g_lego_x[(size_t)NL * DIM];
__device__ float g_point_x[(size_t)NP * DIM];
__device__ float g_lego_a[(size_t)NL * DIM];
__device__ float g_point_a[(size_t)NP * DIM];
__device__ float g_q[(size_t)NL * DIM];
__device__ float g_k[(size_t)NL * DIM];
__device__ float g_v[(size_t)NL * DIM];
__device__ float g_hs[(size_t)NP * DIM];
__device__ float g_as[NP];
__device__ float g_ad[NP];
__device__ float g_score[N_E_LL];
__device__ float g_C[(size_t)NP * 512];
__device__ float g_B[(size_t)NP * 512];
__device__ float g_eagg[(size_t)NP * DIM];
__device__ float g_wa[256];

// sorted-edge infrastructure
__device__ int g_rp_ll[NL + 1];
__device__ int g_rp_pl[NL + 1];
__device__ int g_rp_pp[NP + 1];
__device__ int g_rp_lp[NP + 1];
__device__ int g_cur[NP + 1];
__device__ int g_part[256];
__device__ int g_ss_ll[N_E_LL], g_sd_ll[N_E_LL];
__device__ int g_ss_pp[N_E_PP], g_sd_pp[N_E_PP];
__device__ int g_ss_lp[N_E_LP], g_sd_lp[N_E_LP];
__device__ int g_ss_pl[N_E_PL], g_sd_pl[N_E_PL];

// pre-split transposed weights (bf16 hi/lo), layout [n][k] k-contiguous
#define OW_Q 0
#define OW_K 16384
#define OW_V 32768
#define OW_S 49152
#define OW_G 65536
#define OW_1D 81920
#define OW_1B 147456
#define W_INST 212992
__device__ __nv_bfloat16 g_wh[(size_t)4 * W_INST];
__device__ __nv_bfloat16 g_wl[(size_t)4 * W_INST];
// W2 transposed fp16, layout [n][512]
__device__ __half g_w2h[(size_t)4 * 65536];

// ------------------------- multi-output GEMM spec -------------------------
struct OutSpec {
    float* base[8];
    const float* bias1[8];
    const float* bias2[8];
    int stride[8];
};

// ------------------------- PTX helpers -------------------------
__device__ __forceinline__ uint32_t smem_u32(const void* p) {
    uint32_t a;
    asm("{ .reg .u64 t; cvta.to.shared.u64 t, %1; cvt.u32.u64 %0, t; }" : "=r"(a) : "l"(p));
    return a;
}
__device__ __forceinline__ void ldsm_x4(uint32_t* r, uint32_t addr) {
    asm volatile("ldmatrix.sync.aligned.m8n8.x4.shared.b16 {%0,%1,%2,%3}, [%4];"
                 : "=r"(r[0]), "=r"(r[1]), "=r"(r[2]), "=r"(r[3]) : "r"(addr));
}
__device__ __forceinline__ void mma_bf16(float* c, const uint32_t* a, const uint32_t* b) {
    asm volatile(
        "mma.sync.aligned.m16n8k16.row.col.f32.bf16.bf16.f32 "
        "{%0,%1,%2,%3}, {%4,%5,%6,%7}, {%8,%9}, {%0,%1,%2,%3};"
        : "+f"(c[0]), "+f"(c[1]), "+f"(c[2]), "+f"(c[3])
        : "r"(a[0]), "r"(a[1]), "r"(a[2]), "r"(a[3]), "r"(b[0]), "r"(b[1]));
}
__device__ __forceinline__ void mma_f16(float* c, const uint32_t* a, const uint32_t* b) {
    asm volatile(
        "mma.sync.aligned.m16n8k16.row.col.f32.f16.f16.f32 "
        "{%0,%1,%2,%3}, {%4,%5,%6,%7}, {%8,%9}, {%0,%1,%2,%3};"
        : "+f"(c[0]), "+f"(c[1]), "+f"(c[2]), "+f"(c[3])
        : "r"(a[0]), "r"(a[1]), "r"(a[2]), "r"(a[3]), "r"(b[0]), "r"(b[1]));
}
__device__ __forceinline__ uint32_t f2h2(float a, float b) {
    __half2 h = __floats2half2_rn(a, b);
    return *reinterpret_cast<uint32_t*>(&h);
}

// split 8 fp32 into hi/lo bf16 16B groups (Markstein split)
__device__ __forceinline__ void split8(const float* f, uint4* hi, uint4* lo) {
    uint32_t hw[4], lw[4];
#pragma unroll
    for (int i = 0; i < 4; i++) {
        float x0 = f[2 * i], x1 = f[2 * i + 1];
        __nv_bfloat16 h0 = __float2bfloat16(x0), h1 = __float2bfloat16(x1);
        __nv_bfloat162 hp = __halves2bfloat162(h0, h1);
        hw[i] = *reinterpret_cast<uint32_t*>(&hp);
        __nv_bfloat16 l0 = __float2bfloat16(x0 - __bfloat162float(h0));
        __nv_bfloat16 l1 = __float2bfloat16(x1 - __bfloat162float(h1));
        __nv_bfloat162 lp = __halves2bfloat162(l0, l1);
        lw[i] = *reinterpret_cast<uint32_t*>(&lp);
    }
    *hi = make_uint4(hw[0], hw[1], hw[2], hw[3]);
    *lo = make_uint4(lw[0], lw[1], lw[2], lw[3]);
}

// ------------------------- small helpers -------------------------
__device__ __forceinline__ void atomicMaxF(float* addr, float val) {
    if (val >= 0.0f) atomicMax((int*)addr, __float_as_int(val));
    else             atomicMin((unsigned int*)addr, (unsigned int)__float_as_int(val));
}

__global__ void fill_kernel(float* __restrict__ p, float v, int n) {
    int i = blockIdx.x * blockDim.x + threadIdx.x;
    if (i < n) p[i] = v;
}
__global__ void fill_int_kernel(int* __restrict__ p, int v, int n) {
    int i = blockIdx.x * blockDim.x + threadIdx.x;
    if (i < n) p[i] = v;
}
__global__ void copy_int_kernel(int* __restrict__ d, const int* __restrict__ s, int n) {
    int i = blockIdx.x * blockDim.x + threadIdx.x;
    if (i < n) d[i] = s[i];
}

// ------------------------- counting sort by dst -------------------------
__global__ void hist_kernel(const int* __restrict__ dst, int E, int* __restrict__ cnt) {
    int e = blockIdx.x * blockDim.x + threadIdx.x;
    if (e < E) atomicAdd(&cnt[dst[e]], 1);
}
__global__ void scan_block_kernel(int* __restrict__ data, int* __restrict__ part, int n) {
    __shared__ int sh[1024];
    int i = blockIdx.x * 1024 + threadIdx.x;
    int x = (i < n) ? data[i] : 0;
    sh[threadIdx.x] = x;
    __syncthreads();
    for (int o = 1; o < 1024; o <<= 1) {
        int t = (threadIdx.x >= o) ? sh[threadIdx.x - o] : 0;
        __syncthreads();
        sh[threadIdx.x] += t;
        __syncthreads();
    }
    if (i < n) data[i] = sh[threadIdx.x] - x;      // exclusive
    if (threadIdx.x == 1023) part[blockIdx.x] = sh[1023];
}
__global__ void scan_part_kernel(int* __restrict__ part, int nb) {
    __shared__ int sh[1024];
    int x = (threadIdx.x < nb) ? part[threadIdx.x] : 0;
    sh[threadIdx.x] = x;
    __syncthreads();
    for (int o = 1; o < 1024; o <<= 1) {
        int t = (threadIdx.x >= o) ? sh[threadIdx.x - o] : 0;
        __syncthreads();
        sh[threadIdx.x] += t;
        __syncthreads();
    }
    if (threadIdx.x < nb) part[threadIdx.x] = sh[threadIdx.x] - x;   // exclusive
}
__global__ void scan_add_kernel(int* __restrict__ data, const int* __restrict__ part, int n) {
    int i = blockIdx.x * 1024 + threadIdx.x;
    if (i < n) data[i] += part[blockIdx.x];
}
__global__ void scatter_kernel(const int* __restrict__ src, const int* __restrict__ dst, int E,
                               int* __restrict__ cur, int* __restrict__ ssrc, int* __restrict__ sdst) {
    int e = blockIdx.x * blockDim.x + threadIdx.x;
    if (e >= E) return;
    int d = dst[e];
    int pos = atomicAdd(&cur[d], 1);
    ssrc[pos] = src[e];
    sdst[pos] = d;
}

// ------------------------- weight prep -------------------------
__global__ void split_wT_kernel(const float* __restrict__ W, int K, int N,
                                __nv_bfloat16* __restrict__ hiT, __nv_bfloat16* __restrict__ loT) {
    int idx = blockIdx.x * 256 + threadIdx.x;
    if (idx >= K * N) return;
    int k = idx / N, n = idx - k * N;
    float x = W[idx];
    __nv_bfloat16 h = __float2bfloat16(x);
    __nv_bfloat16 l = __float2bfloat16(x - __bfloat162float(h));
    hiT[(size_t)n * K + k] = h;
    loT[(size_t)n * K + k] = l;
}
// W1diff = W1[0:128,:] - W1[128:256,:]  (K=128, N=512), split+transpose
__global__ void split_w1d_kernel(const float* __restrict__ W1,
                                 __nv_bfloat16* __restrict__ hiT, __nv_bfloat16* __restrict__ loT) {
    int idx = blockIdx.x * 256 + threadIdx.x;
    if (idx >= 128 * 512) return;
    int k = idx >> 9, n = idx & 511;
    float x = W1[idx] - W1[idx + 128 * 512];
    __nv_bfloat16 h = __float2bfloat16(x);
    __nv_bfloat16 l = __float2bfloat16(x - __bfloat162float(h));
    hiT[(size_t)n * 128 + k] = h;
    loT[(size_t)n * 128 + k] = l;
}
// W2 [512][128] -> transposed fp16 [128][512]
__global__ void split_w2_h_kernel(const float* __restrict__ W2, __half* __restrict__ outT) {
    int idx = blockIdx.x * 256 + threadIdx.x;
    if (idx >= 512 * 128) return;
    int k = idx >> 7, n = idx & 127;
    outT[(size_t)n * 512 + k] = __float2half_rn(W2[idx]);
}

__global__ void wa_kernel(const float* __restrict__ W, const float* __restrict__ a_s,
                          const float* __restrict__ a_d, float* __restrict__ wa) {
    int r = threadIdx.x;
    const float* av = (r < 128) ? a_s : a_d;
    int rr = r & 127;
    float s = 0.0f;
    for (int c = 0; c < 128; c++) s = fmaf(W[rr * 128 + c], av[c], s);
    wa[r] = s;
}

__global__ void gemv_dot_kernel(const float* __restrict__ X, const float* __restrict__ w,
                                float* __restrict__ out, int N) {
    int i = (blockIdx.x * blockDim.x + threadIdx.x) >> 5;
    if (i >= N) return;
    int lane = threadIdx.x & 31;
    float4 xa = ((const float4*)(X + (size_t)i * DIM))[lane];
    float4 wv = ((const float4*)w)[lane];
    float p = xa.x * wv.x + xa.y * wv.y + xa.z * wv.z + xa.w * wv.w;
#pragma unroll
    for (int o = 16; o; o >>= 1) p += __shfl_down_sync(0xffffffffu, p, o);
    if (lane == 0) out[i] = p;
}

// ------------------------- mma.sync node GEMM (bf16 3-pass, multi-output) -------------------------
#define SA_G 272
#define OAH 0
#define OAL 34816
#define OBH 69632
#define OBL 104448
#define GEMM_SMEM 139264

__global__ __launch_bounds__(256, 1)
void gemm_tc(const float* __restrict__ X,
             const __nv_bfloat16* __restrict__ WhiT, const __nv_bfloat16* __restrict__ WloT,
             OutSpec spec, int M) {
    extern __shared__ __align__(16) char smem[];
    const uint32_t sbase = smem_u32(smem);
    const int tid = threadIdx.x, lane = tid & 31, wid = tid >> 5;
    const int bm = blockIdx.y * 128, bn = blockIdx.x * 128;

    // ---- A tile: X rows [bm, bm+128) x K=128, hi/lo split on the fly ----
#pragma unroll
    for (int it = 0; it < 8; it++) {
        int task = tid + it * 256;           // 2048 tasks: 128 m x 16 k8
        int m = task >> 4, k8 = task & 15;
        int gm = bm + m;
        float f[8];
        if (gm < M) {
            const float4* p = (const float4*)(X + (size_t)gm * 128 + k8 * 8);
            float4 a = p[0], b = p[1];
            f[0] = a.x; f[1] = a.y; f[2] = a.z; f[3] = a.w;
            f[4] = b.x; f[5] = b.y; f[6] = b.z; f[7] = b.w;
        } else {
#pragma unroll
            for (int i = 0; i < 8; i++) f[i] = 0.0f;
        }
        uint4 hi, lo; split8(f, &hi, &lo);
        uint32_t off = (uint32_t)m * SA_G + (uint32_t)k8 * 16;
        *(uint4*)(smem + OAH + off) = hi;
        *(uint4*)(smem + OAL + off) = lo;
    }
    // ---- B tile: straight copies from pre-split transposed weights ----
#pragma unroll
    for (int it = 0; it < 8; it++) {
        int task = tid + it * 256;           // 2048 tasks: 128 n x 16 chunks
        int n = task >> 4, c = task & 15;
        uint32_t off = (uint32_t)n * SA_G + (uint32_t)c * 16;
        *(uint4*)(smem + OBH + off) = *(const uint4*)(WhiT + (size_t)(bn + n) * 128 + c * 8);
        *(uint4*)(smem + OBL + off) = *(const uint4*)(WloT + (size_t)(bn + n) * 128 + c * 8);
    }
    __syncthreads();

    const int wm = (wid & 3) * 32, wn = (wid >> 2) * 64;
    const int g = lane >> 3, lr = lane & 7;
    const uint32_t aoff = (uint32_t)((g & 1) * 8 + lr) * SA_G + (uint32_t)(g >> 1) * 16;
    const uint32_t boff = (uint32_t)((g >> 1) * 8 + lr) * SA_G + (uint32_t)(g & 1) * 16;

    float acc[2][8][4];
#pragma unroll
    for (int i = 0; i < 2; i++)
#pragma unroll
        for (int j = 0; j < 8; j++)
#pragma unroll
            for (int r = 0; r < 4; r++) acc[i][j][r] = 0.0f;

#pragma unroll
    for (int pass = 0; pass < 3; pass++) {
        uint32_t Ab = sbase + (pass == 2 ? OAL : OAH) + (uint32_t)wm * SA_G + aoff;
        uint32_t Bb = sbase + (pass == 1 ? OBL : OBH) + (uint32_t)wn * SA_G + boff;
#pragma unroll
        for (int s = 0; s < 8; s++) {
            uint32_t a[2][4], b[4][4];
#pragma unroll
            for (int i = 0; i < 2; i++) ldsm_x4(a[i], Ab + i * (16 * SA_G) + s * 32);
#pragma unroll
            for (int j = 0; j < 4; j++) ldsm_x4(b[j], Bb + j * (16 * SA_G) + s * 32);
#pragma unroll
            for (int i = 0; i < 2; i++)
#pragma unroll
                for (int j = 0; j < 8; j++)
                    mma_bf16(acc[i][j], a[i], &b[j >> 1][(j & 1) * 2]);
        }
    }

    // ---- epilogue via OutSpec ----
    float* base = spec.base[blockIdx.x];
    const float* bb1 = spec.bias1[blockIdx.x];
    const float* bb2 = spec.bias2[blockIdx.x];
    const int stride = spec.stride[blockIdx.x];
    const int qq = lane >> 2, idx = lane & 3;
#pragma unroll
    for (int i = 0; i < 2; i++) {
        int gr0 = bm + wm + i * 16 + qq;
#pragma unroll
        for (int j = 0; j < 8; j++) {
            int gcl = wn + j * 8 + idx * 2;
            float bb0 = 0.0f, bv1 = 0.0f;
            if (bb1) { bb0 += bb1[gcl]; bv1 += bb1[gcl + 1]; }
            if (bb2) { bb0 += bb2[gcl]; bv1 += bb2[gcl + 1]; }
            if (gr0 < M)
                *(float2*)(base + (size_t)gr0 * stride + gcl) =
                    make_float2(acc[i][j][0] + bb0, acc[i][j][1] + bv1);
            int gr1 = gr0 + 8;
            if (gr1 < M)
                *(float2*)(base + (size_t)gr1 * stride + gcl) =
                    make_float2(acc[i][j][2] + bb0, acc[i][j][3] + bv1);
        }
    }
}

// ------------------------- fp16 single-pass EdgeConv MLP + segment max -------------------------
// 128 edges/CTA; H = relu(Cn[dst]+Bn[src]) (K=512 in 64-chunks, double-buffered fp16);
// D = H @ W2 via m16n8k16 fp16 (fp32 accum); epilogue atomicMax into agg[dst].
#define SE_G 144
#define EH0 1024
#define EH1 19456
#define EW0 37888
#define EW1 56320
#define EDGE_SMEM 74752

__global__ __launch_bounds__(256, 1)
void edge_tc(const float* __restrict__ Cn, const float* __restrict__ Bn,
             const int* __restrict__ src, const int* __restrict__ dst, int E,
             const __half* __restrict__ W2T, const float* __restrict__ b2,
             float* __restrict__ agg) {
    extern __shared__ __align__(16) char smem[];
    const uint32_t sbase = smem_u32(smem);
    const int tid = threadIdx.x, lane = tid & 31, wid = tid >> 5;
    const int e0 = blockIdx.x * 128;
    int* sS = (int*)(smem);
    int* sD = (int*)(smem + 512);

    if (tid < 128) {
        int e = e0 + tid;
        sS[tid] = (e < E) ? src[e] : 0;
        sD[tid] = (e < E) ? dst[e] : 0;
    }
    __syncthreads();

    const int wm = (wid & 3) * 32, wn = (wid >> 2) * 64;
    const int g = lane >> 3, lr = lane & 7;
    const uint32_t aoff = (uint32_t)((g & 1) * 8 + lr) * SE_G + (uint32_t)(g >> 1) * 16;
    const uint32_t boff = (uint32_t)((g >> 1) * 8 + lr) * SE_G + (uint32_t)(g & 1) * 16;

    float acc[2][8][4];
#pragma unroll
    for (int i = 0; i < 2; i++)
#pragma unroll
        for (int j = 0; j < 8; j++)
#pragma unroll
            for (int r = 0; r < 4; r++) acc[i][j][r] = 0.0f;

    const int HB[2] = {EH0, EH1};
    const int WB[2] = {EW0, EW1};

    auto load_chunk = [&](int kc, int pb) {
        char* wdst = smem + WB[pb];
        const __half* wsrc = W2T + kc * 64;
#pragma unroll
        for (int it = 0; it < 4; it++) {
            int task = tid + it * 256;       // 1024: 128 n x 8 chunks of 8 fp16
            int n = task >> 3, c = task & 7;
            *(uint4*)(wdst + n * SE_G + c * 16) = *(const uint4*)(wsrc + (size_t)n * 512 + c * 8);
        }
        char* hdst = smem + HB[pb];
#pragma unroll
        for (int it = 0; it < 4; it++) {
            int task = tid + it * 256;       // 1024: 128 e x 8 k8
            int e = task >> 3, k8 = task & 7;
            const float4* pc = (const float4*)(Cn + (size_t)sD[e] * 512 + kc * 64 + k8 * 8);
            const float4* pb4 = (const float4*)(Bn + (size_t)sS[e] * 512 + kc * 64 + k8 * 8);
            float4 c0v = pc[0], c1v = pc[1], b0v = pb4[0], b1v = pb4[1];
            uint4 u;
            u.x = f2h2(fmaxf(c0v.x + b0v.x, 0.f), fmaxf(c0v.y + b0v.y, 0.f));
            u.y = f2h2(fmaxf(c0v.z + b0v.z, 0.f), fmaxf(c0v.w + b0v.w, 0.f));
            u.z = f2h2(fmaxf(c1v.x + b1v.x, 0.f), fmaxf(c1v.y + b1v.y, 0.f));
            u.w = f2h2(fmaxf(c1v.z + b1v.z, 0.f), fmaxf(c1v.w + b1v.w, 0.f));
            *(uint4*)(hdst + e * SE_G + k8 * 16) = u;
        }
    };

    load_chunk(0, 0);
    __syncthreads();

    for (int kc = 0; kc < 8; kc++) {
        int pb = kc & 1;
        if (kc < 7) load_chunk(kc + 1, pb ^ 1);
        uint32_t Ab = sbase + HB[pb] + (uint32_t)wm * SE_G + aoff;
        uint32_t Bb = sbase + WB[pb] + (uint32_t)wn * SE_G + boff;
#pragma unroll
        for (int s = 0; s < 4; s++) {
            uint32_t a[2][4], b[4][4];
#pragma unroll
            for (int i = 0; i < 2; i++) ldsm_x4(a[i], Ab + i * (16 * SE_G) + s * 32);
#pragma unroll
            for (int j = 0; j < 4; j++) ldsm_x4(b[j], Bb + j * (16 * SE_G) + s * 32);
#pragma unroll
            for (int i = 0; i < 2; i++)
#pragma unroll
                for (int j = 0; j < 8; j++)
                    mma_f16(acc[i][j], a[i], &b[j >> 1][(j & 1) * 2]);
        }
        __syncthreads();
    }

    // ---- epilogue: segment-max atomics (dst-sorted -> L2-local) ----
    const int qq = lane >> 2, idx = lane & 3;
#pragma unroll
    for (int i = 0; i < 2; i++) {
#pragma unroll
        for (int half = 0; half < 2; half++) {
            int el = wm + i * 16 + half * 8 + qq;
            if (e0 + el >= E) continue;
            float* ag = agg + (size_t)sD[el] * 128;
#pragma unroll
            for (int j = 0; j < 8; j++) {
                int c = wn + j * 8 + idx * 2;
                atomicMaxF(&ag[c],     acc[i][j][half * 2 + 0] + b2[c]);
                atomicMaxF(&ag[c + 1], acc[i][j][half * 2 + 1] + b2[c + 1]);
            }
        }
    }
}

// ------------------------- score kernels (sorted edges, no atomics) -------------------------
__global__ void trans_score_kernel(const float* __restrict__ q, const float* __restrict__ k,
                                   const int* __restrict__ ssrc, const int* __restrict__ sdst,
                                   int E, float* __restrict__ score) {
    int e = (blockIdx.x * blockDim.x + threadIdx.x) >> 5;
    if (e >= E) return;
    int lane = threadIdx.x & 31;
    int s = ssrc[e], d = sdst[e];
    float4 qa = ((const float4*)(q + (size_t)d * DIM))[lane];
    float4 ka = ((const float4*)(k + (size_t)s * DIM))[lane];
    float p = qa.x * ka.x + qa.y * ka.y + qa.z * ka.z + qa.w * ka.w;
#pragma unroll
    for (int o = 16; o; o >>= 1) p += __shfl_down_sync(0xffffffffu, p, o);
    if (lane == 0) score[e] = p * 0.08838834764831845f;
}

__global__ void gat_score_kernel(const float* __restrict__ as_, const float* __restrict__ ad_,
                                 const int* __restrict__ ssrc, const int* __restrict__ sdst,
                                 int E, float* __restrict__ score) {
    int e = blockIdx.x * blockDim.x + threadIdx.x;
    if (e >= E) return;
    float s = as_[ssrc[e]] + ad_[sdst[e]];
    score[e] = (s > 0.0f) ? s : 0.2f * s;
}

// ------------------------- CSR softmax-aggregation: warp per dst node, 2x unrolled -------------------------
__global__ void attn_agg_kernel(const int* __restrict__ rp, const int* __restrict__ ssrc,
                                const float* __restrict__ score, const float* __restrict__ v,
                                float* __restrict__ out, int N) {
    int node = (blockIdx.x * blockDim.x + threadIdx.x) >> 5;
    if (node >= N) return;
    int lane = threadIdx.x & 31;
    int beg = rp[node], end = rp[node + 1];
    if (beg == end) return;
    float m = -INFINITY;
    for (int i = beg + lane; i < end; i += 32) m = fmaxf(m, score[i]);
#pragma unroll
    for (int o = 16; o; o >>= 1) m = fmaxf(m, __shfl_xor_sync(0xffffffffu, m, o));
    float ax = 0.f, ay = 0.f, az = 0.f, aw = 0.f, asum = 0.f;
    int e = beg;
    for (; e + 2 <= end; e += 2) {
        float s0 = score[e], s1 = score[e + 1];
        int i0 = ssrc[e], i1 = ssrc[e + 1];
        float a0 = expf(s0 - m), a1 = expf(s1 - m);
        float4 v0 = ((const float4*)(v + (size_t)i0 * DIM))[lane];
        float4 v1 = ((const float4*)(v + (size_t)i1 * DIM))[lane];
        asum += a0 + a1;
        ax = fmaf(a0, v0.x, fmaf(a1, v1.x, ax));
        ay = fmaf(a0, v0.y, fmaf(a1, v1.y, ay));
        az = fmaf(a0, v0.z, fmaf(a1, v1.z, az));
        aw = fmaf(a0, v0.w, fmaf(a1, v1.w, aw));
    }
    if (e < end) {
        float a = expf(score[e] - m);
        asum += a;
        float4 val = ((const float4*)(v + (size_t)ssrc[e] * DIM))[lane];
        ax = fmaf(a, val.x, ax); ay = fmaf(a, val.y, ay);
        az = fmaf(a, val.z, az); aw = fmaf(a, val.w, aw);
    }
    float inv = 1.0f / (asum + 1e-16f);
    float4* op = (float4*)(out + (size_t)node * DIM) + lane;
    float4 cur = *op;
    cur.x += ax * inv; cur.y += ay * inv; cur.z += az * inv; cur.w += aw * inv;
    *op = cur;
}

__global__ void finalize_max_kernel(const float* __restrict__ agg, const float* __restrict__ gbias,
                                    float* __restrict__ out, int n) {
    int i = blockIdx.x * blockDim.x + threadIdx.x;
    if (i >= n) return;
    float v = agg[i];
    if (!isfinite(v)) v = 0.0f;
    if (gbias) v += gbias[i & (DIM - 1)];
    out[i] = v;
}

// ------------------------- host orchestration -------------------------
static inline int ceil_div(int a, int b) { return (a + b - 1) / b; }

extern "C" void kernel_launch(void* const* d_in, const int* in_sizes, int n_in,
                              void* d_out, int out_size) {
    const float* in_xl = (const float*)d_in[0];
    const float* in_xp = (const float*)d_in[1];
    const float* tWq = (const float*)d_in[2];
    const float* tbq = (const float*)d_in[3];
    const float* tWk = (const float*)d_in[4];
    const float* tbk = (const float*)d_in[5];
    const float* tWv = (const float*)d_in[6];
    const float* tbv = (const float*)d_in[7];
    const float* tWs = (const float*)d_in[8];
    const float* tbs = (const float*)d_in[9];
    const float* eW1 = (const float*)d_in[10];
    const float* eb1 = (const float*)d_in[11];
    const float* eW2 = (const float*)d_in[12];
    const float* eb2 = (const float*)d_in[13];
    const float* gW  = (const float*)d_in[14];
    const float* gAs = (const float*)d_in[15];
    const float* gAd = (const float*)d_in[16];
    const float* gb  = (const float*)d_in[17];
    const int* ll_src = (const int*)d_in[18];
    const int* ll_dst = (const int*)d_in[19];
    const int* pp_src = (const int*)d_in[20];
    const int* pp_dst = (const int*)d_in[21];
    const int* lp_src = (const int*)d_in[22];
    const int* lp_dst = (const int*)d_in[23];
    const int* pl_src = (const int*)d_in[24];
    const int* pl_dst = (const int*)d_in[25];

    cudaFuncSetAttribute(gemm_tc, cudaFuncAttributeMaxDynamicSharedMemorySize, GEMM_SMEM);
    cudaFuncSetAttribute(edge_tc, cudaFuncAttributeMaxDynamicSharedMemorySize, EDGE_SMEM);

    float *lx, *px, *la, *pa, *q, *k, *v, *hs, *asb, *adb, *sc, *Cb, *Bb, *ea, *wa;
    cudaGetSymbolAddress((void**)&lx, g_lego_x);
    cudaGetSymbolAddress((void**)&px, g_point_x);
    cudaGetSymbolAddress((void**)&la, g_lego_a);
    cudaGetSymbolAddress((void**)&pa, g_point_a);
    cudaGetSymbolAddress((void**)&q, g_q);
    cudaGetSymbolAddress((void**)&k, g_k);
    cudaGetSymbolAddress((void**)&v, g_v);
    cudaGetSymbolAddress((void**)&hs, g_hs);
    cudaGetSymbolAddress((void**)&asb, g_as);
    cudaGetSymbolAddress((void**)&adb, g_ad);
    cudaGetSymbolAddress((void**)&sc, g_score);
    cudaGetSymbolAddress((void**)&Cb, g_C);
    cudaGetSymbolAddress((void**)&Bb, g_B);
    cudaGetSymbolAddress((void**)&ea, g_eagg);
    cudaGetSymbolAddress((void**)&wa, g_wa);

    __half* w2h;
    cudaGetSymbolAddress((void**)&w2h, g_w2h);

    int *rp_ll, *rp_pl, *rp_pp, *rp_lp, *cur, *part;
    int *ss_ll, *sd_ll, *ss_pp, *sd_pp, *ss_lp, *sd_lp, *ss_pl, *sd_pl;
    cudaGetSymbolAddress((void**)&rp_ll, g_rp_ll);
    cudaGetSymbolAddress((void**)&rp_pl, g_rp_pl);
    cudaGetSymbolAddress((void**)&rp_pp, g_rp_pp);
    cudaGetSymbolAddress((void**)&rp_lp, g_rp_lp);
    cudaGetSymbolAddress((void**)&cur, g_cur);
    cudaGetSymbolAddress((void**)&part, g_part);
    cudaGetSymbolAddress((void**)&ss_ll, g_ss_ll);
    cudaGetSymbolAddress((void**)&sd_ll, g_sd_ll);
    cudaGetSymbolAddress((void**)&ss_pp, g_ss_pp);
    cudaGetSymbolAddress((void**)&sd_pp, g_sd_pp);
    cudaGetSymbolAddress((void**)&ss_lp, g_ss_lp);
    cudaGetSymbolAddress((void**)&sd_lp, g_sd_lp);
    cudaGetSymbolAddress((void**)&ss_pl, g_ss_pl);
    cudaGetSymbolAddress((void**)&sd_pl, g_sd_pl);

    __nv_bfloat16 *wh, *wl;
    cudaGetSymbolAddress((void**)&wh, g_wh);
    cudaGetSymbolAddress((void**)&wl, g_wl);

    // ---- counting sort of each relation by dst ----
    auto sort_rel = [&](const int* src, const int* dst, int E, int Nn,
                        int* rp, int* ssrc, int* sdst) {
        int n1 = Nn + 1;
        fill_int_kernel<<<ceil_div(n1, 256), 256>>>(rp, 0, n1);
        hist_kernel<<<ceil_div(E, 256), 256>>>(dst, E, rp);
        int nb = ceil_div(n1, 1024);
        scan_block_kernel<<<nb, 1024>>>(rp, part, n1);
        scan_part_kernel<<<1, 1024>>>(part, nb);
        scan_add_kernel<<<nb, 1024>>>(rp, part, n1);
        copy_int_kernel<<<ceil_div(n1, 256), 256>>>(cur, rp, n1);
        scatter_kernel<<<ceil_div(E, 256), 256>>>(src, dst, E, cur, ssrc, sdst);
    };
    sort_rel(ll_src, ll_dst, N_E_LL, NL, rp_ll, ss_ll, sd_ll);
    sort_rel(pp_src, pp_dst, N_E_PP, NP, rp_pp, ss_pp, sd_pp);
    sort_rel(lp_src, lp_dst, N_E_LP, NP, rp_lp, ss_lp, sd_lp);
    sort_rel(pl_src, pl_dst, N_E_PL, NL, rp_pl, ss_pl, sd_pl);

    // ---- pre-split / pre-convert all weights ----
    for (int i = 0; i < 4; i++) {
        size_t o = (size_t)i * W_INST;
        split_wT_kernel<<<64, 256>>>(tWq + (size_t)i * 16384, 128, 128, wh + o + OW_Q, wl + o + OW_Q);
        split_wT_kernel<<<64, 256>>>(tWk + (size_t)i * 16384, 128, 128, wh + o + OW_K, wl + o + OW_K);
        split_wT_kernel<<<64, 256>>>(tWv + (size_t)i * 16384, 128, 128, wh + o + OW_V, wl + o + OW_V);
        split_wT_kernel<<<64, 256>>>(tWs + (size_t)i * 16384, 128, 128, wh + o + OW_S, wl + o + OW_S);
        split_wT_kernel<<<64, 256>>>(gW  + (size_t)i * 16384, 128, 128, wh + o + OW_G, wl + o + OW_G);
        split_w1d_kernel<<<256, 256>>>(eW1 + (size_t)i * 131072, wh + o + OW_1D, wl + o + OW_1D);
        split_wT_kernel<<<256, 256>>>(eW1 + (size_t)i * 131072 + 65536, 128, 512,
                                      wh + o + OW_1B, wl + o + OW_1B);
        split_w2_h_kernel<<<256, 256>>>(eW2 + (size_t)i * 65536, w2h + (size_t)i * 65536);
    }

    auto gemm_multi = [&](const float* X, size_t woff, const OutSpec& sp, int M, int nblk) {
        dim3 gr(nblk, ceil_div(M, 128));
        gemm_tc<<<gr, 256, GEMM_SMEM>>>(X, wh + woff, wl + woff, sp, M);
    };

    cudaMemcpyAsync(lx, in_xl, sizeof(float) * (size_t)NL * DIM, cudaMemcpyDeviceToDevice, 0);
    cudaMemcpyAsync(px, in_xp, sizeof(float) * (size_t)NP * DIM, cudaMemcpyDeviceToDevice, 0);

    for (int layer = 0; layer < 2; layer++) {
        const int iA = 2 * layer, iB = 2 * layer + 1;
        const int i_lp = 2 * layer, i_pl = 2 * layer + 1;
        const size_t oA = (size_t)iA * W_INST, oB = (size_t)iB * W_INST;
        const size_t oLP = (size_t)i_lp * W_INST, oPL = (size_t)i_pl * W_INST;

        // ======== conv A ========
        // --- TransConv QKVS fused (lego->lego over ll); GAT-pl bias folded into skip ---
        {
            OutSpec sp{};
            sp.base[0] = q;  sp.bias1[0] = tbq + iA * 128; sp.stride[0] = 128;
            sp.base[1] = k;  sp.bias1[1] = tbk + iA * 128; sp.stride[1] = 128;
            sp.base[2] = v;  sp.bias1[2] = tbv + iA * 128; sp.stride[2] = 128;
            sp.base[3] = la; sp.bias1[3] = tbs + iA * 128; sp.bias2[3] = gb + i_pl * 128;
            sp.stride[3] = 128;
            gemm_multi(lx, oA + OW_Q, sp, NL, 4);
        }
        trans_score_kernel<<<ceil_div(N_E_LL, 8), 256>>>(q, k, ss_ll, sd_ll, N_E_LL, sc);
        attn_agg_kernel<<<ceil_div(NL, 8), 256>>>(rp_ll, ss_ll, sc, v, la, NL);

        // --- GAT (point -> lego over pl) ---
        {
            OutSpec sp{};
            sp.base[0] = hs; sp.stride[0] = 128;
            gemm_multi(px, oPL + OW_G, sp, NP, 1);
        }
        wa_kernel<<<1, 256>>>(gW + (size_t)i_pl * 16384, gAs + i_pl * 128, gAd + i_pl * 128, wa);
        gemv_dot_kernel<<<ceil_div(NP, 8), 256>>>(px, wa, asb, NP);
        gemv_dot_kernel<<<ceil_div(NL, 8), 256>>>(lx, wa + 128, adb, NL);
        gat_score_kernel<<<ceil_div(N_E_PL, 256), 256>>>(asb, adb, ss_pl, sd_pl, N_E_PL, sc);
        attn_agg_kernel<<<ceil_div(NL, 8), 256>>>(rp_pl, ss_pl, sc, hs, la, NL);

        // --- EdgeConv (point->point over pp); GAT-lp bias folded in finalize ---
        {
            OutSpec sp{};
            for (int i = 0; i < 4; i++) {
                sp.base[i] = Cb + i * 128; sp.stride[i] = 512;
                sp.bias1[i] = eb1 + iA * 512 + i * 128;
            }
            for (int i = 4; i < 8; i++) { sp.base[i] = Bb + (i - 4) * 128; sp.stride[i] = 512; }
            gemm_multi(px, oA + OW_1D, sp, NP, 8);
        }
        fill_kernel<<<ceil_div(NP * DIM, 256), 256>>>(ea, -INFINITY, NP * DIM);
        edge_tc<<<ceil_div(N_E_PP, 128), 256, EDGE_SMEM>>>(Cb, Bb, ss_pp, sd_pp, N_E_PP,
                                                           w2h + (size_t)iA * 65536,
                                                           eb2 + iA * 128, ea);
        finalize_max_kernel<<<ceil_div(NP * DIM, 256), 256>>>(ea, gb + i_lp * 128, pa, NP * DIM);

        // --- GAT (lego -> point over lp) ---
        {
            OutSpec sp{};
            sp.base[0] = hs; sp.stride[0] = 128;
            gemm_multi(lx, oLP + OW_G, sp, NL, 1);
        }
        wa_kernel<<<1, 256>>>(gW + (size_t)i_lp * 16384, gAs + i_lp * 128, gAd + i_lp * 128, wa);
        gemv_dot_kernel<<<ceil_div(NL, 8), 256>>>(lx, wa, asb, NL);
        gemv_dot_kernel<<<ceil_div(NP, 8), 256>>>(px, wa + 128, adb, NP);
        gat_score_kernel<<<ceil_div(N_E_LP, 256), 256>>>(asb, adb, ss_lp, sd_lp, N_E_LP, sc);
        attn_agg_kernel<<<ceil_div(NP, 8), 256>>>(rp_lp, ss_lp, sc, hs, pa, NP);

        // ======== conv B ========
        // --- TransConv QKVS fused (lego_a -> x_lego) ---
        {
            OutSpec sp{};
            sp.base[0] = q;  sp.bias1[0] = tbq + iB * 128; sp.stride[0] = 128;
            sp.base[1] = k;  sp.bias1[1] = tbk + iB * 128; sp.stride[1] = 128;
            sp.base[2] = v;  sp.bias1[2] = tbv + iB * 128; sp.stride[2] = 128;
            sp.base[3] = lx; sp.bias1[3] = tbs + iB * 128; sp.stride[3] = 128;
            gemm_multi(la, oB + OW_Q, sp, NL, 4);
        }
        trans_score_kernel<<<ceil_div(N_E_LL, 8), 256>>>(q, k, ss_ll, sd_ll, N_E_LL, sc);
        attn_agg_kernel<<<ceil_div(NL, 8), 256>>>(rp_ll, ss_ll, sc, v, lx, NL);

        // --- EdgeConv (point_a -> x_point) ---
        {
            OutSpec sp{};
            for (int i = 0; i < 4; i++) {
                sp.base[i] = Cb + i * 128; sp.stride[i] = 512;
                sp.bias1[i] = eb1 + iB * 512 + i * 128;
            }
            for (int i = 4; i < 8; i++) { sp.base[i] = Bb + (i - 4) * 128; sp.stride[i] = 512; }
            gemm_multi(pa, oB + OW_1D, sp, NP, 8);
        }
        fill_kernel<<<ceil_div(NP * DIM, 256), 256>>>(ea, -INFINITY, NP * DIM);
        edge_tc<<<ceil_div(N_E_PP, 128), 256, EDGE_SMEM>>>(Cb, Bb, ss_pp, sd_pp, N_E_PP,
                                                           w2h + (size_t)iB * 65536,
                                                           eb2 + iB * 128, ea);
        finalize_max_kernel<<<ceil_div(NP * DIM, 256), 256>>>(ea, nullptr, px, NP * DIM);
    }

    float* out = (float*)d_out;
    cudaMemcpyAsync(out, lx, sizeof(float) * (size_t)NL * DIM, cudaMemcpyDeviceToDevice, 0);
    cudaMemcpyAsync(out + (size_t)NL * DIM, px, sizeof(float) * (size_t)NP * DIM,
                    cudaMemcpyDeviceToDevice, 0);
}

// round 16
// speedup vs baseline: 2.2079x; 1.0797x over previous
#include <cuda_runtime.h>
#include <cuda_bf16.h>
#include <cuda_fp16.h>
#include <math.h>
#include <stdint.h>

#define DIM 128
#define NL 50000
#define NP 100000
#define N_E_LL 500000
#define N_E_PP 400000
#define N_E_LP 500000
#define N_E_PL 500000

// ------------------------- device scratch (no allocs allowed) -------------------------
__device__ float g_lego0[(size_t)NL * DIM];
__device__ float g_lego1[(size_t)NL * DIM];
__device__ float g_point0[(size_t)NP * DIM];
__device__ float g_point1[(size_t)NP * DIM];
__device__ float g_lego_a[(size_t)NL * DIM];
__device__ float g_point_a[(size_t)NP * DIM];
__device__ float g_q[(size_t)NL * DIM];
__device__ float g_k[(size_t)NL * DIM];
__device__ float g_v[(size_t)NL * DIM];
__device__ float g_hs_pl[(size_t)NP * DIM];   // chain-L GAT (point->lego)
__device__ float g_hs_lp[(size_t)NL * DIM];   // chain-P GAT (lego->point)
__device__ float g_as_l[NP];
__device__ float g_ad_l[NL];
__device__ float g_as_p[NL];
__device__ float g_ad_p[NP];
__device__ float g_C[(size_t)NP * 512];
__device__ float g_B[(size_t)NP * 512];
__device__ float g_eagg[(size_t)NP * DIM];
__device__ float g_wa_l[256];
__device__ float g_wa_p[256];

// sorted-edge infrastructure (per-relation cur/part so sorts can run concurrently)
__device__ int g_rp_ll[NL + 1];
__device__ int g_rp_pl[NL + 1];
__device__ int g_rp_pp[NP + 1];
__device__ int g_rp_lp[NP + 1];
__device__ int g_cur0[NP + 1], g_cur1[NP + 1], g_cur2[NP + 1], g_cur3[NP + 1];
__device__ int g_part0[256], g_part1[256], g_part2[256], g_part3[256];
__device__ int g_ss_ll[N_E_LL], g_sd_ll[N_E_LL];
__device__ int g_ss_pp[N_E_PP], g_sd_pp[N_E_PP];
__device__ int g_ss_lp[N_E_LP], g_sd_lp[N_E_LP];
__device__ int g_ss_pl[N_E_PL], g_sd_pl[N_E_PL];

// pre-split transposed weights (bf16 hi/lo), layout [n][k] k-contiguous
#define OW_Q 0
#define OW_K 16384
#define OW_V 32768
#define OW_S 49152
#define OW_G 65536
#define OW_1D 81920
#define OW_1B 147456
#define W_INST 212992
__device__ __nv_bfloat16 g_wh[(size_t)4 * W_INST];
__device__ __nv_bfloat16 g_wl[(size_t)4 * W_INST];
// W2 transposed fp16, layout [n][512]
__device__ __half g_w2h[(size_t)4 * 65536];

// ------------------------- multi-output GEMM spec -------------------------
struct OutSpec {
    float* base[8];
    const float* bias1[8];
    const float* bias2[8];
    int stride[8];
};

// ------------------------- PTX helpers -------------------------
__device__ __forceinline__ uint32_t smem_u32(const void* p) {
    uint32_t a;
    asm("{ .reg .u64 t; cvta.to.shared.u64 t, %1; cvt.u32.u64 %0, t; }" : "=r"(a) : "l"(p));
    return a;
}
__device__ __forceinline__ void ldsm_x4(uint32_t* r, uint32_t addr) {
    asm volatile("ldmatrix.sync.aligned.m8n8.x4.shared.b16 {%0,%1,%2,%3}, [%4];"
                 : "=r"(r[0]), "=r"(r[1]), "=r"(r[2]), "=r"(r[3]) : "r"(addr));
}
__device__ __forceinline__ void mma_bf16(float* c, const uint32_t* a, const uint32_t* b) {
    asm volatile(
        "mma.sync.aligned.m16n8k16.row.col.f32.bf16.bf16.f32 "
        "{%0,%1,%2,%3}, {%4,%5,%6,%7}, {%8,%9}, {%0,%1,%2,%3};"
        : "+f"(c[0]), "+f"(c[1]), "+f"(c[2]), "+f"(c[3])
        : "r"(a[0]), "r"(a[1]), "r"(a[2]), "r"(a[3]), "r"(b[0]), "r"(b[1]));
}
__device__ __forceinline__ void mma_f16(float* c, const uint32_t* a, const uint32_t* b) {
    asm volatile(
        "mma.sync.aligned.m16n8k16.row.col.f32.f16.f16.f32 "
        "{%0,%1,%2,%3}, {%4,%5,%6,%7}, {%8,%9}, {%0,%1,%2,%3};"
        : "+f"(c[0]), "+f"(c[1]), "+f"(c[2]), "+f"(c[3])
        : "r"(a[0]), "r"(a[1]), "r"(a[2]), "r"(a[3]), "r"(b[0]), "r"(b[1]));
}
__device__ __forceinline__ uint32_t f2h2(float a, float b) {
    __half2 h = __floats2half2_rn(a, b);
    return *reinterpret_cast<uint32_t*>(&h);
}

// split 8 fp32 into hi/lo bf16 16B groups (Markstein split)
__device__ __forceinline__ void split8(const float* f, uint4* hi, uint4* lo) {
    uint32_t hw[4], lw[4];
#pragma unroll
    for (int i = 0; i < 4; i++) {
        float x0 = f[2 * i], x1 = f[2 * i + 1];
        __nv_bfloat16 h0 = __float2bfloat16(x0), h1 = __float2bfloat16(x1);
        __nv_bfloat162 hp = __halves2bfloat162(h0, h1);
        hw[i] = *reinterpret_cast<uint32_t*>(&hp);
        __nv_bfloat16 l0 = __float2bfloat16(x0 - __bfloat162float(h0));
        __nv_bfloat16 l1 = __float2bfloat16(x1 - __bfloat162float(h1));
        __nv_bfloat162 lp = __halves2bfloat162(l0, l1);
        lw[i] = *reinterpret_cast<uint32_t*>(&lp);
    }
    *hi = make_uint4(hw[0], hw[1], hw[2], hw[3]);
    *lo = make_uint4(lw[0], lw[1], lw[2], lw[3]);
}

// ------------------------- small helpers -------------------------
__device__ __forceinline__ void atomicMaxF(float* addr, float val) {
    if (val >= 0.0f) atomicMax((int*)addr, __float_as_int(val));
    else             atomicMin((unsigned int*)addr, (unsigned int)__float_as_int(val));
}

__global__ void fill_kernel(float* __restrict__ p, float v, int n) {
    int i = blockIdx.x * blockDim.x + threadIdx.x;
    if (i < n) p[i] = v;
}
__global__ void fill_int_kernel(int* __restrict__ p, int v, int n) {
    int i = blockIdx.x * blockDim.x + threadIdx.x;
    if (i < n) p[i] = v;
}
__global__ void copy_int_kernel(int* __restrict__ d, const int* __restrict__ s, int n) {
    int i = blockIdx.x * blockDim.x + threadIdx.x;
    if (i < n) d[i] = s[i];
}

// ------------------------- counting sort by dst -------------------------
__global__ void hist_kernel(const int* __restrict__ dst, int E, int* __restrict__ cnt) {
    int e = blockIdx.x * blockDim.x + threadIdx.x;
    if (e < E) atomicAdd(&cnt[dst[e]], 1);
}
__global__ void scan_block_kernel(int* __restrict__ data, int* __restrict__ part, int n) {
    __shared__ int sh[1024];
    int i = blockIdx.x * 1024 + threadIdx.x;
    int x = (i < n) ? data[i] : 0;
    sh[threadIdx.x] = x;
    __syncthreads();
    for (int o = 1; o < 1024; o <<= 1) {
        int t = (threadIdx.x >= o) ? sh[threadIdx.x - o] : 0;
        __syncthreads();
        sh[threadIdx.x] += t;
        __syncthreads();
    }
    if (i < n) data[i] = sh[threadIdx.x] - x;      // exclusive
    if (threadIdx.x == 1023) part[blockIdx.x] = sh[1023];
}
__global__ void scan_part_kernel(int* __restrict__ part, int nb) {
    __shared__ int sh[1024];
    int x = (threadIdx.x < nb) ? part[threadIdx.x] : 0;
    sh[threadIdx.x] = x;
    __syncthreads();
    for (int o = 1; o < 1024; o <<= 1) {
        int t = (threadIdx.x >= o) ? sh[threadIdx.x - o] : 0;
        __syncthreads();
        sh[threadIdx.x] += t;
        __syncthreads();
    }
    if (threadIdx.x < nb) part[threadIdx.x] = sh[threadIdx.x] - x;   // exclusive
}
__global__ void scan_add_kernel(int* __restrict__ data, const int* __restrict__ part, int n) {
    int i = blockIdx.x * 1024 + threadIdx.x;
    if (i < n) data[i] += part[blockIdx.x];
}
__global__ void scatter_kernel(const int* __restrict__ src, const int* __restrict__ dst, int E,
                               int* __restrict__ cur, int* __restrict__ ssrc, int* __restrict__ sdst) {
    int e = blockIdx.x * blockDim.x + threadIdx.x;
    if (e >= E) return;
    int d = dst[e];
    int pos = atomicAdd(&cur[d], 1);
    ssrc[pos] = src[e];
    sdst[pos] = d;
}

// ------------------------- weight prep -------------------------
__global__ void split_wT_kernel(const float* __restrict__ W, int K, int N,
                                __nv_bfloat16* __restrict__ hiT, __nv_bfloat16* __restrict__ loT) {
    int idx = blockIdx.x * 256 + threadIdx.x;
    if (idx >= K * N) return;
    int k = idx / N, n = idx - k * N;
    float x = W[idx];
    __nv_bfloat16 h = __float2bfloat16(x);
    __nv_bfloat16 l = __float2bfloat16(x - __bfloat162float(h));
    hiT[(size_t)n * K + k] = h;
    loT[(size_t)n * K + k] = l;
}
// W1diff = W1[0:128,:] - W1[128:256,:]  (K=128, N=512), split+transpose
__global__ void split_w1d_kernel(const float* __restrict__ W1,
                                 __nv_bfloat16* __restrict__ hiT, __nv_bfloat16* __restrict__ loT) {
    int idx = blockIdx.x * 256 + threadIdx.x;
    if (idx >= 128 * 512) return;
    int k = idx >> 9, n = idx & 511;
    float x = W1[idx] - W1[idx + 128 * 512];
    __nv_bfloat16 h = __float2bfloat16(x);
    __nv_bfloat16 l = __float2bfloat16(x - __bfloat162float(h));
    hiT[(size_t)n * 128 + k] = h;
    loT[(size_t)n * 128 + k] = l;
}
// W2 [512][128] -> transposed fp16 [128][512]
__global__ void split_w2_h_kernel(const float* __restrict__ W2, __half* __restrict__ outT) {
    int idx = blockIdx.x * 256 + threadIdx.x;
    if (idx >= 512 * 128) return;
    int k = idx >> 7, n = idx & 127;
    outT[(size_t)n * 512 + k] = __float2half_rn(W2[idx]);
}

__global__ void wa_kernel(const float* __restrict__ W, const float* __restrict__ a_s,
                          const float* __restrict__ a_d, float* __restrict__ wa) {
    int r = threadIdx.x;
    const float* av = (r < 128) ? a_s : a_d;
    int rr = r & 127;
    float s = 0.0f;
    for (int c = 0; c < 128; c++) s = fmaf(W[rr * 128 + c], av[c], s);
    wa[r] = s;
}

__global__ void gemv_dot_kernel(const float* __restrict__ X, const float* __restrict__ w,
                                float* __restrict__ out, int N) {
    int i = (blockIdx.x * blockDim.x + threadIdx.x) >> 5;
    if (i >= N) return;
    int lane = threadIdx.x & 31;
    float4 xa = ((const float4*)(X + (size_t)i * DIM))[lane];
    float4 wv = ((const float4*)w)[lane];
    float p = xa.x * wv.x + xa.y * wv.y + xa.z * wv.z + xa.w * wv.w;
#pragma unroll
    for (int o = 16; o; o >>= 1) p += __shfl_down_sync(0xffffffffu, p, o);
    if (lane == 0) out[i] = p;
}

// ------------------------- mma.sync node GEMM (bf16 3-pass, multi-output) -------------------------
#define SA_G 272
#define OAH 0
#define OAL 34816
#define OBH 69632
#define OBL 104448
#define GEMM_SMEM 139264

__global__ __launch_bounds__(256, 1)
void gemm_tc(const float* __restrict__ X,
             const __nv_bfloat16* __restrict__ WhiT, const __nv_bfloat16* __restrict__ WloT,
             OutSpec spec, int M) {
    extern __shared__ __align__(16) char smem[];
    const uint32_t sbase = smem_u32(smem);
    const int tid = threadIdx.x, lane = tid & 31, wid = tid >> 5;
    const int bm = blockIdx.y * 128, bn = blockIdx.x * 128;

#pragma unroll
    for (int it = 0; it < 8; it++) {
        int task = tid + it * 256;
        int m = task >> 4, k8 = task & 15;
        int gm = bm + m;
        float f[8];
        if (gm < M) {
            const float4* p = (const float4*)(X + (size_t)gm * 128 + k8 * 8);
            float4 a = p[0], b = p[1];
            f[0] = a.x; f[1] = a.y; f[2] = a.z; f[3] = a.w;
            f[4] = b.x; f[5] = b.y; f[6] = b.z; f[7] = b.w;
        } else {
#pragma unroll
            for (int i = 0; i < 8; i++) f[i] = 0.0f;
        }
        uint4 hi, lo; split8(f, &hi, &lo);
        uint32_t off = (uint32_t)m * SA_G + (uint32_t)k8 * 16;
        *(uint4*)(smem + OAH + off) = hi;
        *(uint4*)(smem + OAL + off) = lo;
    }
#pragma unroll
    for (int it = 0; it < 8; it++) {
        int task = tid + it * 256;
        int n = task >> 4, c = task & 15;
        uint32_t off = (uint32_t)n * SA_G + (uint32_t)c * 16;
        *(uint4*)(smem + OBH + off) = *(const uint4*)(WhiT + (size_t)(bn + n) * 128 + c * 8);
        *(uint4*)(smem + OBL + off) = *(const uint4*)(WloT + (size_t)(bn + n) * 128 + c * 8);
    }
    __syncthreads();

    const int wm = (wid & 3) * 32, wn = (wid >> 2) * 64;
    const int g = lane >> 3, lr = lane & 7;
    const uint32_t aoff = (uint32_t)((g & 1) * 8 + lr) * SA_G + (uint32_t)(g >> 1) * 16;
    const uint32_t boff = (uint32_t)((g >> 1) * 8 + lr) * SA_G + (uint32_t)(g & 1) * 16;

    float acc[2][8][4];
#pragma unroll
    for (int i = 0; i < 2; i++)
#pragma unroll
        for (int j = 0; j < 8; j++)
#pragma unroll
            for (int r = 0; r < 4; r++) acc[i][j][r] = 0.0f;

#pragma unroll
    for (int pass = 0; pass < 3; pass++) {
        uint32_t Ab = sbase + (pass == 2 ? OAL : OAH) + (uint32_t)wm * SA_G + aoff;
        uint32_t Bb = sbase + (pass == 1 ? OBL : OBH) + (uint32_t)wn * SA_G + boff;
#pragma unroll
        for (int s = 0; s < 8; s++) {
            uint32_t a[2][4], b[4][4];
#pragma unroll
            for (int i = 0; i < 2; i++) ldsm_x4(a[i], Ab + i * (16 * SA_G) + s * 32);
#pragma unroll
            for (int j = 0; j < 4; j++) ldsm_x4(b[j], Bb + j * (16 * SA_G) + s * 32);
#pragma unroll
            for (int i = 0; i < 2; i++)
#pragma unroll
                for (int j = 0; j < 8; j++)
                    mma_bf16(acc[i][j], a[i], &b[j >> 1][(j & 1) * 2]);
        }
    }

    float* base = spec.base[blockIdx.x];
    const float* bb1 = spec.bias1[blockIdx.x];
    const float* bb2 = spec.bias2[blockIdx.x];
    const int stride = spec.stride[blockIdx.x];
    const int qq = lane >> 2, idx = lane & 3;
#pragma unroll
    for (int i = 0; i < 2; i++) {
        int gr0 = bm + wm + i * 16 + qq;
#pragma unroll
        for (int j = 0; j < 8; j++) {
            int gcl = wn + j * 8 + idx * 2;
            float bb0 = 0.0f, bv1 = 0.0f;
            if (bb1) { bb0 += bb1[gcl]; bv1 += bb1[gcl + 1]; }
            if (bb2) { bb0 += bb2[gcl]; bv1 += bb2[gcl + 1]; }
            if (gr0 < M)
                *(float2*)(base + (size_t)gr0 * stride + gcl) =
                    make_float2(acc[i][j][0] + bb0, acc[i][j][1] + bv1);
            int gr1 = gr0 + 8;
            if (gr1 < M)
                *(float2*)(base + (size_t)gr1 * stride + gcl) =
                    make_float2(acc[i][j][2] + bb0, acc[i][j][3] + bv1);
        }
    }
}

// ------------------------- fp16 single-pass EdgeConv MLP + segment max -------------------------
#define SE_G 144
#define EH0 1024
#define EH1 19456
#define EW0 37888
#define EW1 56320
#define EDGE_SMEM 74752

__global__ __launch_bounds__(256, 1)
void edge_tc(const float* __restrict__ Cn, const float* __restrict__ Bn,
             const int* __restrict__ src, const int* __restrict__ dst, int E,
             const __half* __restrict__ W2T, const float* __restrict__ b2,
             float* __restrict__ agg) {
    extern __shared__ __align__(16) char smem[];
    const uint32_t sbase = smem_u32(smem);
    const int tid = threadIdx.x, lane = tid & 31, wid = tid >> 5;
    const int e0 = blockIdx.x * 128;
    int* sS = (int*)(smem);
    int* sD = (int*)(smem + 512);

    if (tid < 128) {
        int e = e0 + tid;
        sS[tid] = (e < E) ? src[e] : 0;
        sD[tid] = (e < E) ? dst[e] : 0;
    }
    __syncthreads();

    const int wm = (wid & 3) * 32, wn = (wid >> 2) * 64;
    const int g = lane >> 3, lr = lane & 7;
    const uint32_t aoff = (uint32_t)((g & 1) * 8 + lr) * SE_G + (uint32_t)(g >> 1) * 16;
    const uint32_t boff = (uint32_t)((g >> 1) * 8 + lr) * SE_G + (uint32_t)(g & 1) * 16;

    float acc[2][8][4];
#pragma unroll
    for (int i = 0; i < 2; i++)
#pragma unroll
        for (int j = 0; j < 8; j++)
#pragma unroll
            for (int r = 0; r < 4; r++) acc[i][j][r] = 0.0f;

    const int HB[2] = {EH0, EH1};
    const int WB[2] = {EW0, EW1};

    auto load_chunk = [&](int kc, int pb) {
        char* wdst = smem + WB[pb];
        const __half* wsrc = W2T + kc * 64;
#pragma unroll
        for (int it = 0; it < 4; it++) {
            int task = tid + it * 256;
            int n = task >> 3, c = task & 7;
            *(uint4*)(wdst + n * SE_G + c * 16) = *(const uint4*)(wsrc + (size_t)n * 512 + c * 8);
        }
        char* hdst = smem + HB[pb];
#pragma unroll
        for (int it = 0; it < 4; it++) {
            int task = tid + it * 256;
            int e = task >> 3, k8 = task & 7;
            const float4* pc = (const float4*)(Cn + (size_t)sD[e] * 512 + kc * 64 + k8 * 8);
            const float4* pb4 = (const float4*)(Bn + (size_t)sS[e] * 512 + kc * 64 + k8 * 8);
            float4 c0v = pc[0], c1v = pc[1], b0v = pb4[0], b1v = pb4[1];
            uint4 u;
            u.x = f2h2(fmaxf(c0v.x + b0v.x, 0.f), fmaxf(c0v.y + b0v.y, 0.f));
            u.y = f2h2(fmaxf(c0v.z + b0v.z, 0.f), fmaxf(c0v.w + b0v.w, 0.f));
            u.z = f2h2(fmaxf(c1v.x + b1v.x, 0.f), fmaxf(c1v.y + b1v.y, 0.f));
            u.w = f2h2(fmaxf(c1v.z + b1v.z, 0.f), fmaxf(c1v.w + b1v.w, 0.f));
            *(uint4*)(hdst + e * SE_G + k8 * 16) = u;
        }
    };

    load_chunk(0, 0);
    __syncthreads();

    for (int kc = 0; kc < 8; kc++) {
        int pb = kc & 1;
        if (kc < 7) load_chunk(kc + 1, pb ^ 1);
        uint32_t Ab = sbase + HB[pb] + (uint32_t)wm * SE_G + aoff;
        uint32_t Bb = sbase + WB[pb] + (uint32_t)wn * SE_G + boff;
#pragma unroll
        for (int s = 0; s < 4; s++) {
            uint32_t a[2][4], b[4][4];
#pragma unroll
            for (int i = 0; i < 2; i++) ldsm_x4(a[i], Ab + i * (16 * SE_G) + s * 32);
#pragma unroll
            for (int j = 0; j < 4; j++) ldsm_x4(b[j], Bb + j * (16 * SE_G) + s * 32);
#pragma unroll
            for (int i = 0; i < 2; i++)
#pragma unroll
                for (int j = 0; j < 8; j++)
                    mma_f16(acc[i][j], a[i], &b[j >> 1][(j & 1) * 2]);
        }
        __syncthreads();
    }

    const int qq = lane >> 2, idx = lane & 3;
#pragma unroll
    for (int i = 0; i < 2; i++) {
#pragma unroll
        for (int half = 0; half < 2; half++) {
            int el = wm + i * 16 + half * 8 + qq;
            if (e0 + el >= E) continue;
            float* ag = agg + (size_t)sD[el] * 128;
#pragma unroll
            for (int j = 0; j < 8; j++) {
                int c = wn + j * 8 + idx * 2;
                atomicMaxF(&ag[c],     acc[i][j][half * 2 + 0] + b2[c]);
                atomicMaxF(&ag[c + 1], acc[i][j][half * 2 + 1] + b2[c + 1]);
            }
        }
    }
}

// ------------------------- fused online-softmax attention (warp per dst node) -------------------------
__global__ void trans_fused_kernel(const int* __restrict__ rp, const int* __restrict__ ssrc,
                                   const float* __restrict__ q, const float* __restrict__ k,
                                   const float* __restrict__ v, float* __restrict__ out, int N) {
    int node = (blockIdx.x * blockDim.x + threadIdx.x) >> 5;
    if (node >= N) return;
    int lane = threadIdx.x & 31;
    int beg = rp[node], end = rp[node + 1];
    if (beg == end) return;
    float4 qv = ((const float4*)(q + (size_t)node * DIM))[lane];
    float m = -INFINITY, s = 0.f, ax = 0.f, ay = 0.f, az = 0.f, aw = 0.f;
    int e = beg;
    for (; e + 2 <= end; e += 2) {
        int s0 = ssrc[e], s1 = ssrc[e + 1];
        float4 k0 = ((const float4*)(k + (size_t)s0 * DIM))[lane];
        float4 k1 = ((const float4*)(k + (size_t)s1 * DIM))[lane];
        float4 v0 = ((const float4*)(v + (size_t)s0 * DIM))[lane];
        float4 v1 = ((const float4*)(v + (size_t)s1 * DIM))[lane];
        float p0 = k0.x * qv.x + k0.y * qv.y + k0.z * qv.z + k0.w * qv.w;
        float p1 = k1.x * qv.x + k1.y * qv.y + k1.z * qv.z + k1.w * qv.w;
#pragma unroll
        for (int o = 16; o; o >>= 1) {
            p0 += __shfl_xor_sync(0xffffffffu, p0, o);
            p1 += __shfl_xor_sync(0xffffffffu, p1, o);
        }
        p0 *= 0.08838834764831845f;
        p1 *= 0.08838834764831845f;
        float nm = fmaxf(m, fmaxf(p0, p1));
        float scl = expf(m - nm), a0 = expf(p0 - nm), a1 = expf(p1 - nm);
        s = s * scl + a0 + a1;
        ax = ax * scl + a0 * v0.x + a1 * v1.x;
        ay = ay * scl + a0 * v0.y + a1 * v1.y;
        az = az * scl + a0 * v0.z + a1 * v1.z;
        aw = aw * scl + a0 * v0.w + a1 * v1.w;
        m = nm;
    }
    if (e < end) {
        int s0 = ssrc[e];
        float4 k0 = ((const float4*)(k + (size_t)s0 * DIM))[lane];
        float4 v0 = ((const float4*)(v + (size_t)s0 * DIM))[lane];
        float p0 = k0.x * qv.x + k0.y * qv.y + k0.z * qv.z + k0.w * qv.w;
#pragma unroll
        for (int o = 16; o; o >>= 1) p0 += __shfl_xor_sync(0xffffffffu, p0, o);
        p0 *= 0.08838834764831845f;
        float nm = fmaxf(m, p0);
        float scl = expf(m - nm), a0 = expf(p0 - nm);
        s = s * scl + a0;
        ax = ax * scl + a0 * v0.x;
        ay = ay * scl + a0 * v0.y;
        az = az * scl + a0 * v0.z;
        aw = aw * scl + a0 * v0.w;
    }
    float inv = 1.0f / (s + 1e-16f);
    float4* op = (float4*)(out + (size_t)node * DIM) + lane;
    float4 c = *op;
    c.x += ax * inv; c.y += ay * inv; c.z += az * inv; c.w += aw * inv;
    *op = c;
}

__global__ void gat_fused_kernel(const int* __restrict__ rp, const int* __restrict__ ssrc,
                                 const float* __restrict__ as_, const float* __restrict__ ad_,
                                 const float* __restrict__ hs, float* __restrict__ out, int N) {
    int node = (blockIdx.x * blockDim.x + threadIdx.x) >> 5;
    if (node >= N) return;
    int lane = threadIdx.x & 31;
    int beg = rp[node], end = rp[node + 1];
    if (beg == end) return;
    float adv = ad_[node];
    float m = -INFINITY, s = 0.f, ax = 0.f, ay = 0.f, az = 0.f, aw = 0.f;
    int e = beg;
    for (; e + 2 <= end; e += 2) {
        int s0 = ssrc[e], s1 = ssrc[e + 1];
        float p0 = as_[s0] + adv, p1 = as_[s1] + adv;
        p0 = (p0 > 0.f) ? p0 : 0.2f * p0;
        p1 = (p1 > 0.f) ? p1 : 0.2f * p1;
        float4 v0 = ((const float4*)(hs + (size_t)s0 * DIM))[lane];
        float4 v1 = ((const float4*)(hs + (size_t)s1 * DIM))[lane];
        float nm = fmaxf(m, fmaxf(p0, p1));
        float scl = expf(m - nm), a0 = expf(p0 - nm), a1 = expf(p1 - nm);
        s = s * scl + a0 + a1;
        ax = ax * scl + a0 * v0.x + a1 * v1.x;
        ay = ay * scl + a0 * v0.y + a1 * v1.y;
        az = az * scl + a0 * v0.z + a1 * v1.z;
        aw = aw * scl + a0 * v0.w + a1 * v1.w;
        m = nm;
    }
    if (e < end) {
        int s0 = ssrc[e];
        float p0 = as_[s0] + adv;
        p0 = (p0 > 0.f) ? p0 : 0.2f * p0;
        float4 v0 = ((const float4*)(hs + (size_t)s0 * DIM))[lane];
        float nm = fmaxf(m, p0);
        float scl = expf(m - nm), a0 = expf(p0 - nm);
        s = s * scl + a0;
        ax = ax * scl + a0 * v0.x;
        ay = ay * scl + a0 * v0.y;
        az = az * scl + a0 * v0.z;
        aw = aw * scl + a0 * v0.w;
    }
    float inv = 1.0f / (s + 1e-16f);
    float4* op = (float4*)(out + (size_t)node * DIM) + lane;
    float4 c = *op;
    c.x += ax * inv; c.y += ay * inv; c.z += az * inv; c.w += aw * inv;
    *op = c;
}

__global__ void finalize_max_kernel(const float* __restrict__ agg, const float* __restrict__ gbias,
                                    float* __restrict__ out, int n) {
    int i = blockIdx.x * blockDim.x + threadIdx.x;
    if (i >= n) return;
    float v = agg[i];
    if (!isfinite(v)) v = 0.0f;
    if (gbias) v += gbias[i & (DIM - 1)];
    out[i] = v;
}

// ------------------------- host orchestration -------------------------
static inline int ceil_div(int a, int b) { return (a + b - 1) / b; }

extern "C" void kernel_launch(void* const* d_in, const int* in_sizes, int n_in,
                              void* d_out, int out_size) {
    const float* in_xl = (const float*)d_in[0];
    const float* in_xp = (const float*)d_in[1];
    const float* tWq = (const float*)d_in[2];
    const float* tbq = (const float*)d_in[3];
    const float* tWk = (const float*)d_in[4];
    const float* tbk = (const float*)d_in[5];
    const float* tWv = (const float*)d_in[6];
    const float* tbv = (const float*)d_in[7];
    const float* tWs = (const float*)d_in[8];
    const float* tbs = (const float*)d_in[9];
    const float* eW1 = (const float*)d_in[10];
    const float* eb1 = (const float*)d_in[11];
    const float* eW2 = (const float*)d_in[12];
    const float* eb2 = (const float*)d_in[13];
    const float* gW  = (const float*)d_in[14];
    const float* gAs = (const float*)d_in[15];
    const float* gAd = (const float*)d_in[16];
    const float* gb  = (const float*)d_in[17];
    const int* ll_src = (const int*)d_in[18];
    const int* ll_dst = (const int*)d_in[19];
    const int* pp_src = (const int*)d_in[20];
    const int* pp_dst = (const int*)d_in[21];
    const int* lp_src = (const int*)d_in[22];
    const int* lp_dst = (const int*)d_in[23];
    const int* pl_src = (const int*)d_in[24];
    const int* pl_dst = (const int*)d_in[25];

    cudaFuncSetAttribute(gemm_tc, cudaFuncAttributeMaxDynamicSharedMemorySize, GEMM_SMEM);
    cudaFuncSetAttribute(edge_tc, cudaFuncAttributeMaxDynamicSharedMemorySize, EDGE_SMEM);

    float *lx0, *lx1, *px0, *px1, *la, *pa, *q, *k, *v;
    float *hs_pl, *hs_lp, *as_l, *ad_l, *as_p, *ad_p, *Cb, *Bb, *ea, *wa_l, *wa_p;
    cudaGetSymbolAddress((void**)&lx0, g_lego0);
    cudaGetSymbolAddress((void**)&lx1, g_lego1);
    cudaGetSymbolAddress((void**)&px0, g_point0);
    cudaGetSymbolAddress((void**)&px1, g_point1);
    cudaGetSymbolAddress((void**)&la, g_lego_a);
    cudaGetSymbolAddress((void**)&pa, g_point_a);
    cudaGetSymbolAddress((void**)&q, g_q);
    cudaGetSymbolAddress((void**)&k, g_k);
    cudaGetSymbolAddress((void**)&v, g_v);
    cudaGetSymbolAddress((void**)&hs_pl, g_hs_pl);
    cudaGetSymbolAddress((void**)&hs_lp, g_hs_lp);
    cudaGetSymbolAddress((void**)&as_l, g_as_l);
    cudaGetSymbolAddress((void**)&ad_l, g_ad_l);
    cudaGetSymbolAddress((void**)&as_p, g_as_p);
    cudaGetSymbolAddress((void**)&ad_p, g_ad_p);
    cudaGetSymbolAddress((void**)&Cb, g_C);
    cudaGetSymbolAddress((void**)&Bb, g_B);
    cudaGetSymbolAddress((void**)&ea, g_eagg);
    cudaGetSymbolAddress((void**)&wa_l, g_wa_l);
    cudaGetSymbolAddress((void**)&wa_p, g_wa_p);

    __half* w2h;
    cudaGetSymbolAddress((void**)&w2h, g_w2h);

    int *rp_ll, *rp_pl, *rp_pp, *rp_lp;
    int *cur0, *cur1, *cur2, *cur3, *part0, *part1, *part2, *part3;
    int *ss_ll, *sd_ll, *ss_pp, *sd_pp, *ss_lp, *sd_lp, *ss_pl, *sd_pl;
    cudaGetSymbolAddress((void**)&rp_ll, g_rp_ll);
    cudaGetSymbolAddress((void**)&rp_pl, g_rp_pl);
    cudaGetSymbolAddress((void**)&rp_pp, g_rp_pp);
    cudaGetSymbolAddress((void**)&rp_lp, g_rp_lp);
    cudaGetSymbolAddress((void**)&cur0, g_cur0);
    cudaGetSymbolAddress((void**)&cur1, g_cur1);
    cudaGetSymbolAddress((void**)&cur2, g_cur2);
    cudaGetSymbolAddress((void**)&cur3, g_cur3);
    cudaGetSymbolAddress((void**)&part0, g_part0);
    cudaGetSymbolAddress((void**)&part1, g_part1);
    cudaGetSymbolAddress((void**)&part2, g_part2);
    cudaGetSymbolAddress((void**)&part3, g_part3);
    cudaGetSymbolAddress((void**)&ss_ll, g_ss_ll);
    cudaGetSymbolAddress((void**)&sd_ll, g_sd_ll);
    cudaGetSymbolAddress((void**)&ss_pp, g_ss_pp);
    cudaGetSymbolAddress((void**)&sd_pp, g_sd_pp);
    cudaGetSymbolAddress((void**)&ss_lp, g_ss_lp);
    cudaGetSymbolAddress((void**)&sd_lp, g_sd_lp);
    cudaGetSymbolAddress((void**)&ss_pl, g_ss_pl);
    cudaGetSymbolAddress((void**)&sd_pl, g_sd_pl);

    __nv_bfloat16 *wh, *wl;
    cudaGetSymbolAddress((void**)&wh, g_wh);
    cudaGetSymbolAddress((void**)&wl, g_wl);

    // ---- streams + fork/join events (created per call; host objects, no device mem) ----
    cudaStream_t sL, sP;
    cudaStreamCreateWithFlags(&sL, cudaStreamNonBlocking);
    cudaStreamCreateWithFlags(&sP, cudaStreamNonBlocking);
    cudaEvent_t evF[3], evL[3], evP[3];
    for (int i = 0; i < 3; i++) {
        cudaEventCreateWithFlags(&evF[i], cudaEventDisableTiming);
        cudaEventCreateWithFlags(&evL[i], cudaEventDisableTiming);
        cudaEventCreateWithFlags(&evP[i], cudaEventDisableTiming);
    }
    auto fork = [&](int i) {
        cudaEventRecord(evF[i], 0);
        cudaStreamWaitEvent(sL, evF[i], 0);
        cudaStreamWaitEvent(sP, evF[i], 0);
    };
    auto join = [&](int i) {
        cudaEventRecord(evL[i], sL);
        cudaEventRecord(evP[i], sP);
        cudaStreamWaitEvent(0, evL[i], 0);
        cudaStreamWaitEvent(0, evP[i], 0);
    };

    auto sort_rel = [&](const int* src, const int* dst, int E, int Nn, int* rp,
                        int* ssrc, int* sdst, int* curb, int* partb, cudaStream_t st) {
        int n1 = Nn + 1;
        fill_int_kernel<<<ceil_div(n1, 256), 256, 0, st>>>(rp, 0, n1);
        hist_kernel<<<ceil_div(E, 256), 256, 0, st>>>(dst, E, rp);
        int nb = ceil_div(n1, 1024);
        scan_block_kernel<<<nb, 1024, 0, st>>>(rp, partb, n1);
        scan_part_kernel<<<1, 1024, 0, st>>>(partb, nb);
        scan_add_kernel<<<nb, 1024, 0, st>>>(rp, partb, n1);
        copy_int_kernel<<<ceil_div(n1, 256), 256, 0, st>>>(curb, rp, n1);
        scatter_kernel<<<ceil_div(E, 256), 256, 0, st>>>(src, dst, E, curb, ssrc, sdst);
    };

    auto gemm_multi = [&](const float* X, size_t woff, const OutSpec& sp, int M, int nblk,
                          cudaStream_t st) {
        dim3 gr(nblk, ceil_div(M, 128));
        gemm_tc<<<gr, 256, GEMM_SMEM, st>>>(X, wh + woff, wl + woff, sp, M);
    };

    // ======== prologue: sorts on sL/sP, weight presplit + input copies on origin ========
    fork(0);
    sort_rel(ll_src, ll_dst, N_E_LL, NL, rp_ll, ss_ll, sd_ll, cur0, part0, sL);
    sort_rel(pl_src, pl_dst, N_E_PL, NL, rp_pl, ss_pl, sd_pl, cur1, part1, sL);
    sort_rel(pp_src, pp_dst, N_E_PP, NP, rp_pp, ss_pp, sd_pp, cur2, part2, sP);
    sort_rel(lp_src, lp_dst, N_E_LP, NP, rp_lp, ss_lp, sd_lp, cur3, part3, sP);
    for (int i = 0; i < 4; i++) {
        size_t o = (size_t)i * W_INST;
        split_wT_kernel<<<64, 256>>>(tWq + (size_t)i * 16384, 128, 128, wh + o + OW_Q, wl + o + OW_Q);
        split_wT_kernel<<<64, 256>>>(tWk + (size_t)i * 16384, 128, 128, wh + o + OW_K, wl + o + OW_K);
        split_wT_kernel<<<64, 256>>>(tWv + (size_t)i * 16384, 128, 128, wh + o + OW_V, wl + o + OW_V);
        split_wT_kernel<<<64, 256>>>(tWs + (size_t)i * 16384, 128, 128, wh + o + OW_S, wl + o + OW_S);
        split_wT_kernel<<<64, 256>>>(gW  + (size_t)i * 16384, 128, 128, wh + o + OW_G, wl + o + OW_G);
        split_w1d_kernel<<<256, 256>>>(eW1 + (size_t)i * 131072, wh + o + OW_1D, wl + o + OW_1D);
        split_wT_kernel<<<256, 256>>>(eW1 + (size_t)i * 131072 + 65536, 128, 512,
                                      wh + o + OW_1B, wl + o + OW_1B);
        split_w2_h_kernel<<<256, 256>>>(eW2 + (size_t)i * 65536, w2h + (size_t)i * 65536);
    }
    cudaMemcpyAsync(lx0, in_xl, sizeof(float) * (size_t)NL * DIM, cudaMemcpyDeviceToDevice, 0);
    cudaMemcpyAsync(px0, in_xp, sizeof(float) * (size_t)NP * DIM, cudaMemcpyDeviceToDevice, 0);
    join(0);

    float* lbuf[2] = {lx0, lx1};
    float* pbuf[2] = {px0, px1};

    for (int layer = 0; layer < 2; layer++) {
        const int iA = 2 * layer, iB = 2 * layer + 1;
        const int i_lp = 2 * layer, i_pl = 2 * layer + 1;
        const size_t oA = (size_t)iA * W_INST, oB = (size_t)iB * W_INST;
        const size_t oLP = (size_t)i_lp * W_INST, oPL = (size_t)i_pl * W_INST;
        const float* lin = lbuf[layer & 1];
        const float* pin = pbuf[layer & 1];
        float* lout = lbuf[(layer + 1) & 1];
        float* pout = pbuf[(layer + 1) & 1];

        fork(1 + layer);

        // ======== chain-L (lego) on sL ========
        {
            OutSpec sp{};
            sp.base[0] = q;  sp.bias1[0] = tbq + iA * 128; sp.stride[0] = 128;
            sp.base[1] = k;  sp.bias1[1] = tbk + iA * 128; sp.stride[1] = 128;
            sp.base[2] = v;  sp.bias1[2] = tbv + iA * 128; sp.stride[2] = 128;
            sp.base[3] = la; sp.bias1[3] = tbs + iA * 128; sp.bias2[3] = gb + i_pl * 128;
            sp.stride[3] = 128;
            gemm_multi(lin, oA + OW_Q, sp, NL, 4, sL);
        }
        trans_fused_kernel<<<ceil_div(NL, 8), 256, 0, sL>>>(rp_ll, ss_ll, q, k, v, la, NL);
        {
            OutSpec sp{};
            sp.base[0] = hs_pl; sp.stride[0] = 128;
            gemm_multi(pin, oPL + OW_G, sp, NP, 1, sL);
        }
        wa_kernel<<<1, 256, 0, sL>>>(gW + (size_t)i_pl * 16384, gAs + i_pl * 128,
                                     gAd + i_pl * 128, wa_l);
        gemv_dot_kernel<<<ceil_div(NP, 8), 256, 0, sL>>>(pin, wa_l, as_l, NP);
        gemv_dot_kernel<<<ceil_div(NL, 8), 256, 0, sL>>>(lin, wa_l + 128, ad_l, NL);
        gat_fused_kernel<<<ceil_div(NL, 8), 256, 0, sL>>>(rp_pl, ss_pl, as_l, ad_l, hs_pl, la, NL);
        {
            OutSpec sp{};
            sp.base[0] = q;    sp.bias1[0] = tbq + iB * 128; sp.stride[0] = 128;
            sp.base[1] = k;    sp.bias1[1] = tbk + iB * 128; sp.stride[1] = 128;
            sp.base[2] = v;    sp.bias1[2] = tbv + iB * 128; sp.stride[2] = 128;
            sp.base[3] = lout; sp.bias1[3] = tbs + iB * 128; sp.stride[3] = 128;
            gemm_multi(la, oB + OW_Q, sp, NL, 4, sL);
        }
        trans_fused_kernel<<<ceil_div(NL, 8), 256, 0, sL>>>(rp_ll, ss_ll, q, k, v, lout, NL);

        // ======== chain-P (point) on sP ========
        {
            OutSpec sp{};
            for (int i = 0; i < 4; i++) {
                sp.base[i] = Cb + i * 128; sp.stride[i] = 512;
                sp.bias1[i] = eb1 + iA * 512 + i * 128;
            }
            for (int i = 4; i < 8; i++) { sp.base[i] = Bb + (i - 4) * 128; sp.stride[i] = 512; }
            gemm_multi(pin, oA + OW_1D, sp, NP, 8, sP);
        }
        fill_kernel<<<ceil_div(NP * DIM, 256), 256, 0, sP>>>(ea, -INFINITY, NP * DIM);
        edge_tc<<<ceil_div(N_E_PP, 128), 256, EDGE_SMEM, sP>>>(Cb, Bb, ss_pp, sd_pp, N_E_PP,
                                                               w2h + (size_t)iA * 65536,
                                                               eb2 + iA * 128, ea);
        finalize_max_kernel<<<ceil_div(NP * DIM, 256), 256, 0, sP>>>(ea, gb + i_lp * 128, pa,
                                                                     NP * DIM);
        {
            OutSpec sp{};
            sp.base[0] = hs_lp; sp.stride[0] = 128;
            gemm_multi(lin, oLP + OW_G, sp, NL, 1, sP);
        }
        wa_kernel<<<1, 256, 0, sP>>>(gW + (size_t)i_lp * 16384, gAs + i_lp * 128,
                                     gAd + i_lp * 128, wa_p);
        gemv_dot_kernel<<<ceil_div(NL, 8), 256, 0, sP>>>(lin, wa_p, as_p, NL);
        gemv_dot_kernel<<<ceil_div(NP, 8), 256, 0, sP>>>(pin, wa_p + 128, ad_p, NP);
        gat_fused_kernel<<<ceil_div(NP, 8), 256, 0, sP>>>(rp_lp, ss_lp, as_p, ad_p, hs_lp, pa, NP);
        {
            OutSpec sp{};
            for (int i = 0; i < 4; i++) {
                sp.base[i] = Cb + i * 128; sp.stride[i] = 512;
                sp.bias1[i] = eb1 + iB * 512 + i * 128;
            }
            for (int i = 4; i < 8; i++) { sp.base[i] = Bb + (i - 4) * 128; sp.stride[i] = 512; }
            gemm_multi(pa, oB + OW_1D, sp, NP, 8, sP);
        }
        fill_kernel<<<ceil_div(NP * DIM, 256), 256, 0, sP>>>(ea, -INFINITY, NP * DIM);
        edge_tc<<<ceil_div(N_E_PP, 128), 256, EDGE_SMEM, sP>>>(Cb, Bb, ss_pp, sd_pp, N_E_PP,
                                                               w2h + (size_t)iB * 65536,
                                                               eb2 + iB * 128, ea);
        finalize_max_kernel<<<ceil_div(NP * DIM, 256), 256, 0, sP>>>(ea, nullptr, pout, NP * DIM);

        join(1 + layer);
    }

    float* out = (float*)d_out;
    cudaMemcpyAsync(out, lx0, sizeof(float) * (size_t)NL * DIM, cudaMemcpyDeviceToDevice, 0);
    cudaMemcpyAsync(out + (size_t)NL * DIM, px0, sizeof(float) * (size_t)NP * DIM,
                    cudaMemcpyDeviceToDevice, 0);

    cudaStreamDestroy(sL);
    cudaStreamDestroy(sP);
    for (int i = 0; i < 3; i++) {
        cudaEventDestroy(evF[i]);
        cudaEventDestroy(evL[i]);
        cudaEventDestroy(evP[i]);
    }
}